// round 7
// baseline (speedup 1.0000x reference)
#include <cuda_runtime.h>

#define BB   16
#define NN   512
#define DIN  256
#define DD   64
#define EE   32
#define MAXDIST 50

typedef unsigned long long ull;

__device__ __forceinline__ void fma2(ull& d, ull a, ull b) {
    asm("fma.rn.f32x2 %0, %1, %2, %0;" : "+l"(d) : "l"(a), "l"(b));
}
__device__ __forceinline__ ull dup2(float x) {
    unsigned u = __float_as_uint(x); ull d;
    asm("mov.b64 %0, {%1, %1};" : "=l"(d) : "r"(u));
    return d;
}
__device__ __forceinline__ float2 unpk(ull u) {
    unsigned lo, hi;
    asm("mov.b64 {%0, %1}, %2;" : "=r"(lo), "=r"(hi) : "l"(u));
    return make_float2(__uint_as_float(lo), __uint_as_float(hi));
}
__device__ __forceinline__ float ex2(float x) {
    float r;
    asm("ex2.approx.f32 %0, %1;" : "=f"(r) : "f"(x));
    return r;
}

__device__ float g_qT[BB*DD*NN];   // per batch: [d][n]
__device__ float g_kT[BB*DD*NN];   // per batch: [d][n]
__device__ float g_v [BB*NN*DD];   // row-major [n][d]
__device__ float g_rel[MAXDIST+1]; // 0.125 * log2(e) * sigmoid(...)

// ============================================================
// Kernel 1: xp = x@Wp+bp ; q,k,v = xp@W{q,k,v}+b (FFMA2)
// ============================================================
__global__ __launch_bounds__(256) void qkv_kernel(
    const float* __restrict__ x,
    const float* __restrict__ Wp, const float* __restrict__ bp,
    const float* __restrict__ Wq, const float* __restrict__ bq,
    const float* __restrict__ Wk, const float* __restrict__ bk,
    const float* __restrict__ Wv, const float* __restrict__ bv,
    const float* __restrict__ Eemb, const float* __restrict__ Wr1,
    const float* __restrict__ br1,  const float* __restrict__ Wr2) {
    __shared__ float bufA[64*68];
    __shared__ float bufB[64*68];
    const int tid = threadIdx.x;
    const int ty = tid >> 4, tx = tid & 15;
    const int row0 = blockIdx.x * 64;
    const int b = row0 >> 9;
    const int n0 = row0 & 511;

    if (blockIdx.x == 0 && tid <= MAXDIST) {
        float e[EE];
#pragma unroll
        for (int c = 0; c < EE; c++) e[c] = Eemb[tid*EE + c];
        float w = 0.f;
#pragma unroll
        for (int j = 0; j < 16; j++) {
            float h = br1[j];
#pragma unroll
            for (int c = 0; c < EE; c++) h = fmaf(e[c], Wr1[c*16 + j], h);
            h = fmaxf(h, 0.f);
            w = fmaf(h, Wr2[j], w);
        }
        g_rel[tid] = 0.18033688011112042f / (1.f + __expf(-w));
    }

    const int fi = tid >> 4;
    const int ff = tid & 15;

    float4 ra4[4], rb4[4];
#pragma unroll
    for (int j = 0; j < 4; j++) {
        int i = fi + j*16;
        ra4[j] = *(const float4*)&x[(row0 + i)*DIN + ff*4];
        rb4[j] = *(const float4*)&Wp[i*DD + ff*4];
    }
    ull acc2[2][4];
#pragma unroll
    for (int p = 0; p < 2; p++)
#pragma unroll
        for (int c = 0; c < 4; c++) acc2[p][c] = 0ULL;

    for (int kc = 0; kc < 4; kc++) {
#pragma unroll
        for (int j = 0; j < 4; j++) {
            int i = fi + j*16;
            bufA[(ff*4 + 0)*68 + i] = ra4[j].x;
            bufA[(ff*4 + 1)*68 + i] = ra4[j].y;
            bufA[(ff*4 + 2)*68 + i] = ra4[j].z;
            bufA[(ff*4 + 3)*68 + i] = ra4[j].w;
            *(float4*)&bufB[i*68 + ff*4] = rb4[j];
        }
        __syncthreads();
        if (kc < 3) {
#pragma unroll
            for (int j = 0; j < 4; j++) {
                int i = fi + j*16;
                ra4[j] = *(const float4*)&x[(row0 + i)*DIN + (kc+1)*64 + ff*4];
                rb4[j] = *(const float4*)&Wp[((kc+1)*64 + i)*DD + ff*4];
            }
        }
#pragma unroll 8
        for (int kk = 0; kk < 64; kk++) {
            ulonglong2 a = *(const ulonglong2*)&bufA[kk*68 + ty*4];
            float4 bw = *(const float4*)&bufB[kk*68 + tx*4];
            ull b0 = dup2(bw.x), b1 = dup2(bw.y), b2 = dup2(bw.z), b3 = dup2(bw.w);
            fma2(acc2[0][0], a.x, b0); fma2(acc2[0][1], a.x, b1);
            fma2(acc2[0][2], a.x, b2); fma2(acc2[0][3], a.x, b3);
            fma2(acc2[1][0], a.y, b0); fma2(acc2[1][1], a.y, b1);
            fma2(acc2[1][2], a.y, b2); fma2(acc2[1][3], a.y, b3);
        }
        __syncthreads();
    }
#pragma unroll
    for (int c = 0; c < 4; c++) {
        float2 p0 = unpk(acc2[0][c]), p1 = unpk(acc2[1][c]);
        float bias = bp[tx*4 + c];
        float4 v4 = {p0.x + bias, p0.y + bias, p1.x + bias, p1.y + bias};
        *(float4*)&bufA[(tx*4 + c)*68 + ty*4] = v4;
    }
    __syncthreads();

    const float* Ws[3] = {Wq, Wk, Wv};
    const float* bs[3] = {bq, bk, bv};
    for (int t = 0; t < 3; t++) {
#pragma unroll
        for (int j = 0; j < 4; j++) {
            int i = fi + j*16;
            *(float4*)&bufB[i*68 + ff*4] = *(const float4*)&Ws[t][i*DD + ff*4];
        }
        __syncthreads();
        ull o2[2][4];
#pragma unroll
        for (int p = 0; p < 2; p++)
#pragma unroll
            for (int c = 0; c < 4; c++) o2[p][c] = 0ULL;
#pragma unroll 8
        for (int kk = 0; kk < 64; kk++) {
            ulonglong2 a = *(const ulonglong2*)&bufA[kk*68 + ty*4];
            float4 bw = *(const float4*)&bufB[kk*68 + tx*4];
            ull b0 = dup2(bw.x), b1 = dup2(bw.y), b2 = dup2(bw.z), b3 = dup2(bw.w);
            fma2(o2[0][0], a.x, b0); fma2(o2[0][1], a.x, b1);
            fma2(o2[0][2], a.x, b2); fma2(o2[0][3], a.x, b3);
            fma2(o2[1][0], a.y, b0); fma2(o2[1][1], a.y, b1);
            fma2(o2[1][2], a.y, b2); fma2(o2[1][3], a.y, b3);
        }
        if (t == 2) {
            float2 u[2][4];
#pragma unroll
            for (int p = 0; p < 2; p++)
#pragma unroll
                for (int c = 0; c < 4; c++) u[p][c] = unpk(o2[p][c]);
            float4 bias = *(const float4*)&bs[2][tx*4];
#pragma unroll
            for (int r = 0; r < 4; r++) {
                float4 v4;
                float2* up = u[r >> 1];
                if (r & 1) v4 = make_float4(up[0].y + bias.x, up[1].y + bias.y, up[2].y + bias.z, up[3].y + bias.w);
                else       v4 = make_float4(up[0].x + bias.x, up[1].x + bias.y, up[2].x + bias.z, up[3].x + bias.w);
                *(float4*)&g_v[(row0 + ty*4 + r)*DD + tx*4] = v4;
            }
        } else {
            float* dst = (t == 0) ? g_qT : g_kT;
#pragma unroll
            for (int c = 0; c < 4; c++) {
                float2 p0 = unpk(o2[0][c]), p1 = unpk(o2[1][c]);
                float bias = bs[t][tx*4 + c];
                float4 v4 = {p0.x + bias, p0.y + bias, p1.x + bias, p1.y + bias};
                *(float4*)&dst[b*DD*NN + (tx*4 + c)*NN + n0 + ty*4] = v4;
            }
        }
        __syncthreads();
    }
}

// ============================================================
// Kernel 2: 32-row query tiles, 256 CTAs, 512 thr, 2 CTAs/SM.
// 4 chunks x 128 keys; exp fused in QK epilogue; smem 95.4KB.
// ============================================================
#define S_OFF   0        /* 32x132 = 4224 : scores chunk / aoT / ws1+ws2 */
#define RA_OFF  4224     /* 8448 : kT chunk [64][132] / partials / h1T / head w */
#define RB_OFF  12672    /* 8192 : v chunk [128][64] / w1 / w2 */
#define QT_OFF  20864    /* 64x36 = 2304 : qT / hnT */
#define REL_OFF 23168
#define RK_OFF  23232
#define WS_OFF  23744    /* 64 */
#define INV_OFF 23808    /* 32 */
#define SMEM_FLOATS 23840
#define SMEM_BYTES  (SMEM_FLOATS*4)

__global__ __launch_bounds__(512, 2) void attn_kernel(
    const int* __restrict__ ranks,
    const float* __restrict__ Wf1, const float* __restrict__ bf1,
    const float* __restrict__ Wf2, const float* __restrict__ bf2,
    const float* __restrict__ ln_g, const float* __restrict__ ln_b,
    const float* __restrict__ Ws1, const float* __restrict__ bs1,
    const float* __restrict__ Ws2, const float* __restrict__ bs2,
    float* __restrict__ out) {
    extern __shared__ float sm[];
    float* S    = sm + S_OFF;
    float* RA   = sm + RA_OFF;
    float* RB   = sm + RB_OFF;
    float* qT   = sm + QT_OFF;
    float* rel  = sm + REL_OFF;
    int*   rk   = (int*)(sm + RK_OFF);
    float* wsum = sm + WS_OFF;
    float* invs = sm + INV_OFF;

    const int tid = threadIdx.x;
    const int b = blockIdx.y;
    const int q0 = blockIdx.x * 32;
    const int base = b * NN;
    const int bT = b * DD * NN;
    const int warp = tid >> 5, lane = tid & 31;

    if (tid <= MAXDIST) rel[tid] = g_rel[tid];
    for (int m = tid; m < NN; m += 512) rk[m] = ranks[base + m];
    {
        int d = tid >> 3, f = tid & 7;
        *(float4*)&qT[d*36 + f*4] = *(const float4*)&g_qT[bT + d*NN + q0 + f*4];
    }
    __syncthreads();

    // QK mapping: 8 row-groups x 64 key-slots (2 keys each)
    const int ty = tid >> 6;
    const int tx = tid & 63;
    int ri[4];
#pragma unroll
    for (int r = 0; r < 4; r++) ri[r] = rk[q0 + ty*4 + r];
    // PV mapping: 4 splitK groups x 8 row-groups x 16 col-groups
    const int g3   = tid >> 7;
    const int t3   = tid & 127;
    const int rowg = t3 >> 4;
    const int colg = t3 & 15;

    float rs[4] = {0.f, 0.f, 0.f, 0.f};
    ull accpv[4][2];
#pragma unroll
    for (int r = 0; r < 4; r++) { accpv[r][0] = 0ULL; accpv[r][1] = 0ULL; }

    for (int ch = 0; ch < 4; ch++) {
        const int k0 = ch * 128;
        // ---- stage kT [64][132] and v [128][64] ----
#pragma unroll
        for (int j = 0; j < 4; j++) {
            int idx = tid + j*512;
            *(float4*)&RA[(idx >> 5)*132 + (idx & 31)*4] =
                *(const float4*)&g_kT[bT + (idx >> 5)*NN + k0 + (idx & 31)*4];
            *(float4*)&RB[(idx >> 4)*64 + (idx & 15)*4] =
                *(const float4*)&g_v[(base + k0 + (idx >> 4))*DD + (idx & 15)*4];
        }
        __syncthreads();

        // ---- QK + exp ----
        {
            ull acc2[2][2];
            acc2[0][0] = acc2[0][1] = acc2[1][0] = acc2[1][1] = 0ULL;
#pragma unroll 8
            for (int d = 0; d < 64; d++) {
                ulonglong2 a = *(const ulonglong2*)&qT[d*36 + ty*4];
                float2 kb = *(const float2*)&RA[d*132 + tx*2];
                ull b0 = dup2(kb.x), b1 = dup2(kb.y);
                fma2(acc2[0][0], a.x, b0); fma2(acc2[0][1], a.x, b1);
                fma2(acc2[1][0], a.y, b0); fma2(acc2[1][1], a.y, b1);
            }
            int rk0 = rk[k0 + tx*2], rk1 = rk[k0 + tx*2 + 1];
#pragma unroll
            for (int p = 0; p < 2; p++) {
                float2 u0 = unpk(acc2[p][0]);   // key0, rows (2p, 2p+1)
                float2 u1 = unpk(acc2[p][1]);   // key1
                int ra = ri[2*p], rbq = ri[2*p + 1];
                int d00 = ra - rk0;  if (d00 < 0) d00 = -d00;  if (d00 > MAXDIST) d00 = MAXDIST;
                int d01 = ra - rk1;  if (d01 < 0) d01 = -d01;  if (d01 > MAXDIST) d01 = MAXDIST;
                int d10 = rbq - rk0; if (d10 < 0) d10 = -d10;  if (d10 > MAXDIST) d10 = MAXDIST;
                int d11 = rbq - rk1; if (d11 < 0) d11 = -d11;  if (d11 > MAXDIST) d11 = MAXDIST;
                float e00 = ex2(u0.x * rel[d00]);
                float e01 = ex2(u1.x * rel[d01]);
                float e10 = ex2(u0.y * rel[d10]);
                float e11 = ex2(u1.y * rel[d11]);
                *(float2*)&S[(ty*4 + 2*p    )*132 + tx*2] = make_float2(e00, e01);
                *(float2*)&S[(ty*4 + 2*p + 1)*132 + tx*2] = make_float2(e10, e11);
                rs[2*p]     += e00 + e01;
                rs[2*p + 1] += e10 + e11;
            }
        }
        if (ch == 3) {
#pragma unroll
            for (int r = 0; r < 4; r++) {
                float v = rs[r];
#pragma unroll
                for (int o = 16; o >= 1; o >>= 1) v += __shfl_xor_sync(0xffffffffu, v, o);
                if (lane == 0) wsum[warp*4 + r] = v;
            }
        }
        __syncthreads();

        // ---- PV: 32 keys per splitK group ----
        {
            const int kl0 = g3 * 32;
#pragma unroll 2
            for (int kl = 0; kl < 32; kl += 4) {
                float4 p0 = *(const float4*)&S[(rowg*4 + 0)*132 + kl0 + kl];
                float4 p1 = *(const float4*)&S[(rowg*4 + 1)*132 + kl0 + kl];
                float4 p2 = *(const float4*)&S[(rowg*4 + 2)*132 + kl0 + kl];
                float4 p3 = *(const float4*)&S[(rowg*4 + 3)*132 + kl0 + kl];
                const float* pp0 = (const float*)&p0;
                const float* pp1 = (const float*)&p1;
                const float* pp2 = (const float*)&p2;
                const float* pp3 = (const float*)&p3;
#pragma unroll
                for (int j = 0; j < 4; j++) {
                    ulonglong2 v = *(const ulonglong2*)&RB[(kl0 + kl + j)*64 + colg*4];
                    ull pa0 = dup2(pp0[j]);
                    ull pa1 = dup2(pp1[j]);
                    ull pa2 = dup2(pp2[j]);
                    ull pa3 = dup2(pp3[j]);
                    fma2(accpv[0][0], pa0, v.x); fma2(accpv[0][1], pa0, v.y);
                    fma2(accpv[1][0], pa1, v.x); fma2(accpv[1][1], pa1, v.y);
                    fma2(accpv[2][0], pa2, v.x); fma2(accpv[2][1], pa2, v.y);
                    fma2(accpv[3][0], pa3, v.x); fma2(accpv[3][1], pa3, v.y);
                }
            }
        }
        __syncthreads();
    }

    // ---- splitK partials + w1 staging + invs ----
    float po[4][4];
#pragma unroll
    for (int r = 0; r < 4; r++) {
        float2 u0 = unpk(accpv[r][0]), u1 = unpk(accpv[r][1]);
        po[r][0] = u0.x; po[r][1] = u0.y; po[r][2] = u1.x; po[r][3] = u1.y;
    }
    if (g3 > 0) {
        float* part = RA + (g3 - 1)*2048;
#pragma unroll
        for (int r = 0; r < 4; r++)
            *(float4*)&part[(rowg*4 + r)*64 + colg*4] = *(float4*)&po[r][0];
    }
#pragma unroll
    for (int j = 0; j < 4; j++) {
        int idx = tid + j*512;
        *(float4*)&RB[idx*4] = *(const float4*)&Wf1[idx*4];
    }
    if (tid < 32)
        invs[tid] = 1.f / (wsum[(tid >> 2)*8 + (tid & 3)] + wsum[(tid >> 2)*8 + 4 + (tid & 3)]);
    __syncthreads();

    // ---- group 0: reduce + 1/sum -> aoT (S region) ----
    if (g3 == 0) {
#pragma unroll
        for (int gg = 0; gg < 3; gg++) {
            const float* part = RA + gg*2048;
#pragma unroll
            for (int r = 0; r < 4; r++) {
                float4 q4 = *(const float4*)&part[(rowg*4 + r)*64 + colg*4];
                po[r][0] += q4.x; po[r][1] += q4.y; po[r][2] += q4.z; po[r][3] += q4.w;
            }
        }
        float iv[4];
#pragma unroll
        for (int r = 0; r < 4; r++) iv[r] = invs[rowg*4 + r];
#pragma unroll
        for (int c = 0; c < 4; c++) {
            float4 v4 = {po[0][c]*iv[0], po[1][c]*iv[1], po[2][c]*iv[2], po[3][c]*iv[3]};
            *(float4*)&S[(colg*4 + c)*36 + rowg*4] = v4;
        }
    }
    __syncthreads();

    // ---- FFN1: h1 = relu(ao@Wf1+bf1), 32x128 ----
    {
        const int rw = tid >> 5, cg = tid & 31;    // 2 rows, 4 cols
        ull f1[4] = {0ULL, 0ULL, 0ULL, 0ULL};
#pragma unroll 8
        for (int k = 0; k < 64; k++) {
            ull a = *(const ull*)&S[k*36 + rw*2];
            float4 bw = *(const float4*)&RB[k*128 + cg*4];
            fma2(f1[0], a, dup2(bw.x)); fma2(f1[1], a, dup2(bw.y));
            fma2(f1[2], a, dup2(bw.z)); fma2(f1[3], a, dup2(bw.w));
        }
#pragma unroll
        for (int c = 0; c < 4; c++) {
            float bias = bf1[cg*4 + c];
            float2 u = unpk(f1[c]);
            *(float2*)&RA[(cg*4 + c)*36 + rw*2] =
                make_float2(fmaxf(u.x + bias, 0.f), fmaxf(u.y + bias, 0.f));
        }
    }
    __syncthreads();

    // ---- stage w2 (RB), ws1+ws2 (S) ----
#pragma unroll
    for (int j = 0; j < 4; j++) {
        int idx = tid + j*512;
        *(float4*)&RB[idx*4] = *(const float4*)&Wf2[idx*4];
    }
    *(float4*)&S[tid*4] = *(const float4*)&Ws1[tid*4];
    if (tid < 8) *(float4*)&S[2048 + tid*4] = *(const float4*)&Ws2[tid*4];
    __syncthreads();

    // ---- FFN2 + LayerNorm -> hnT (qT region) ----
    {
        const int rw = tid >> 5, cg = tid & 31;    // 2 rows, 2 cols
        ull f2[2] = {0ULL, 0ULL};
#pragma unroll 8
        for (int k = 0; k < 128; k++) {
            ull a = *(const ull*)&RA[k*36 + rw*2];
            float2 bw = *(const float2*)&RB[k*64 + cg*2];
            fma2(f2[0], a, dup2(bw.x)); fma2(f2[1], a, dup2(bw.y));
        }
        float2 u0 = unpk(f2[0]), u1 = unpk(f2[1]);
        float b0 = bf2[cg*2], b1 = bf2[cg*2 + 1];
        float e00 = u0.x + b0, e01 = u1.x + b1;    // row rw*2
        float e10 = u0.y + b0, e11 = u1.y + b1;    // row rw*2+1
        float s0 = e00 + e01, q0s = e00*e00 + e01*e01;
        float s1v = e10 + e11, q1s = e10*e10 + e11*e11;
#pragma unroll
        for (int o = 16; o >= 1; o >>= 1) {
            s0  += __shfl_xor_sync(0xffffffffu, s0,  o);
            q0s += __shfl_xor_sync(0xffffffffu, q0s, o);
            s1v += __shfl_xor_sync(0xffffffffu, s1v, o);
            q1s += __shfl_xor_sync(0xffffffffu, q1s, o);
        }
        float mu0 = s0 * (1.f/64.f), mu1 = s1v * (1.f/64.f);
        float in0 = rsqrtf(q0s * (1.f/64.f) - mu0*mu0 + 1e-5f);
        float in1 = rsqrtf(q1s * (1.f/64.f) - mu1*mu1 + 1e-5f);
        float g0v = ln_g[cg*2], g1v = ln_g[cg*2 + 1];
        float be0 = ln_b[cg*2], be1 = ln_b[cg*2 + 1];
        *(float2*)&qT[(cg*2 + 0)*36 + rw*2] =
            make_float2((e00 - mu0)*in0*g0v + be0, (e10 - mu1)*in1*g0v + be0);
        *(float2*)&qT[(cg*2 + 1)*36 + rw*2] =
            make_float2((e01 - mu0)*in0*g1v + be1, (e11 - mu1)*in1*g1v + be1);
    }
    __syncthreads();

    // ---- head: 32 rows x 32 cols -> out ----
    {
        const int rw = tid >> 4, cg = tid & 15;
        float s1a = 0.f, s1b = 0.f;
#pragma unroll 8
        for (int k = 0; k < 64; k++) {
            float a = qT[k*36 + rw];
            float2 w = *(const float2*)&S[k*32 + cg*2];
            s1a = fmaf(a, w.x, s1a); s1b = fmaf(a, w.y, s1b);
        }
        float pa = fmaxf(s1a + bs1[cg*2], 0.f);
        float pb = fmaxf(s1b + bs1[cg*2 + 1], 0.f);
        float2 w2v = *(const float2*)&S[2048 + cg*2];
        float p = pa*w2v.x + pb*w2v.y;
#pragma unroll
        for (int o = 8; o >= 1; o >>= 1) p += __shfl_xor_sync(0xffffffffu, p, o, 16);
        if (cg == 0)
            out[base + q0 + rw] = 1.f / (1.f + __expf(-(p + bs2[0])));
    }
}

// ============================================================
extern "C" void kernel_launch(void* const* d_in, const int* in_sizes, int n_in,
                              void* d_out, int out_size) {
    const float* x     = (const float*)d_in[0];
    const int*   ranks = (const int*)  d_in[1];
    const float* Wp    = (const float*)d_in[2];
    const float* bp    = (const float*)d_in[3];
    const float* Wq    = (const float*)d_in[4];
    const float* bq    = (const float*)d_in[5];
    const float* Wk    = (const float*)d_in[6];
    const float* bk    = (const float*)d_in[7];
    const float* Wv    = (const float*)d_in[8];
    const float* bv    = (const float*)d_in[9];
    const float* Eemb  = (const float*)d_in[10];
    const float* Wr1   = (const float*)d_in[11];
    const float* br1   = (const float*)d_in[12];
    const float* Wr2   = (const float*)d_in[13];
    const float* Wf1   = (const float*)d_in[14];
    const float* bf1   = (const float*)d_in[15];
    const float* Wf2   = (const float*)d_in[16];
    const float* bf2   = (const float*)d_in[17];
    const float* ln_g  = (const float*)d_in[18];
    const float* ln_b  = (const float*)d_in[19];
    const float* Ws1   = (const float*)d_in[20];
    const float* bs1   = (const float*)d_in[21];
    const float* Ws2   = (const float*)d_in[22];
    const float* bs2   = (const float*)d_in[23];
    float* out = (float*)d_out;

    cudaFuncSetAttribute(attn_kernel, cudaFuncAttributeMaxDynamicSharedMemorySize, SMEM_BYTES);

    qkv_kernel<<<BB*NN/64, 256>>>(x, Wp, bp, Wq, bq, Wk, bk, Wv, bv,
                                  Eemb, Wr1, br1, Wr2);
    dim3 grid(NN/32, BB);
    attn_kernel<<<grid, 512, SMEM_BYTES>>>(ranks, Wf1, bf1, Wf2, bf2,
                                           ln_g, ln_b, Ws1, bs1, Ws2, bs2, out);
}

// round 8
// speedup vs baseline: 1.1285x; 1.1285x over previous
#include <cuda_runtime.h>

#define BB   16
#define NN   512
#define DIN  256
#define DD   64
#define EE   32
#define MAXDIST 50

typedef unsigned long long ull;

__device__ __forceinline__ void fma2(ull& d, ull a, ull b) {
    asm("fma.rn.f32x2 %0, %1, %2, %0;" : "+l"(d) : "l"(a), "l"(b));
}
__device__ __forceinline__ ull dup2(float x) {
    unsigned u = __float_as_uint(x); ull d;
    asm("mov.b64 %0, {%1, %1};" : "=l"(d) : "r"(u));
    return d;
}
__device__ __forceinline__ float2 unpk(ull u) {
    unsigned lo, hi;
    asm("mov.b64 {%0, %1}, %2;" : "=r"(lo), "=r"(hi) : "l"(u));
    return make_float2(__uint_as_float(lo), __uint_as_float(hi));
}
__device__ __forceinline__ float ex2(float x) {
    float r;
    asm("ex2.approx.f32 %0, %1;" : "=f"(r) : "f"(x));
    return r;
}
__device__ __forceinline__ void cpa16(unsigned dst, const float* src) {
    asm volatile("cp.async.cg.shared.global [%0], [%1], 16;" :: "r"(dst), "l"(src));
}
#define CP_COMMIT() asm volatile("cp.async.commit_group;" ::: "memory")
#define CP_WAIT1()  asm volatile("cp.async.wait_group 1;" ::: "memory")

__device__ float g_qT[BB*DD*NN];   // per batch: [d][n]
__device__ float g_kT[BB*DD*NN];   // per batch: [d][n]
__device__ float g_v [BB*NN*DD];   // row-major [n][d]
__device__ float g_rel[MAXDIST+1]; // 0.125 * log2(e) * sigmoid(...)

// ============================================================
// Kernel 1: xp = x@Wp+bp ; q,k,v = xp@W{q,k,v}+b (FFMA2)
// ============================================================
__global__ __launch_bounds__(256) void qkv_kernel(
    const float* __restrict__ x,
    const float* __restrict__ Wp, const float* __restrict__ bp,
    const float* __restrict__ Wq, const float* __restrict__ bq,
    const float* __restrict__ Wk, const float* __restrict__ bk,
    const float* __restrict__ Wv, const float* __restrict__ bv,
    const float* __restrict__ Eemb, const float* __restrict__ Wr1,
    const float* __restrict__ br1,  const float* __restrict__ Wr2) {
    __shared__ float bufA[64*68];
    __shared__ float bufB[64*68];
    const int tid = threadIdx.x;
    const int ty = tid >> 4, tx = tid & 15;
    const int row0 = blockIdx.x * 64;
    const int b = row0 >> 9;
    const int n0 = row0 & 511;

    if (blockIdx.x == 0 && tid <= MAXDIST) {
        float e[EE];
#pragma unroll
        for (int c = 0; c < EE; c++) e[c] = Eemb[tid*EE + c];
        float w = 0.f;
#pragma unroll
        for (int j = 0; j < 16; j++) {
            float h = br1[j];
#pragma unroll
            for (int c = 0; c < EE; c++) h = fmaf(e[c], Wr1[c*16 + j], h);
            h = fmaxf(h, 0.f);
            w = fmaf(h, Wr2[j], w);
        }
        g_rel[tid] = 0.18033688011112042f / (1.f + __expf(-w));
    }

    const int fi = tid >> 4;
    const int ff = tid & 15;

    float4 ra4[4], rb4[4];
#pragma unroll
    for (int j = 0; j < 4; j++) {
        int i = fi + j*16;
        ra4[j] = *(const float4*)&x[(row0 + i)*DIN + ff*4];
        rb4[j] = *(const float4*)&Wp[i*DD + ff*4];
    }
    ull acc2[2][4];
#pragma unroll
    for (int p = 0; p < 2; p++)
#pragma unroll
        for (int c = 0; c < 4; c++) acc2[p][c] = 0ULL;

    for (int kc = 0; kc < 4; kc++) {
#pragma unroll
        for (int j = 0; j < 4; j++) {
            int i = fi + j*16;
            bufA[(ff*4 + 0)*68 + i] = ra4[j].x;
            bufA[(ff*4 + 1)*68 + i] = ra4[j].y;
            bufA[(ff*4 + 2)*68 + i] = ra4[j].z;
            bufA[(ff*4 + 3)*68 + i] = ra4[j].w;
            *(float4*)&bufB[i*68 + ff*4] = rb4[j];
        }
        __syncthreads();
        if (kc < 3) {
#pragma unroll
            for (int j = 0; j < 4; j++) {
                int i = fi + j*16;
                ra4[j] = *(const float4*)&x[(row0 + i)*DIN + (kc+1)*64 + ff*4];
                rb4[j] = *(const float4*)&Wp[((kc+1)*64 + i)*DD + ff*4];
            }
        }
#pragma unroll 8
        for (int kk = 0; kk < 64; kk++) {
            ulonglong2 a = *(const ulonglong2*)&bufA[kk*68 + ty*4];
            float4 bw = *(const float4*)&bufB[kk*68 + tx*4];
            ull b0 = dup2(bw.x), b1 = dup2(bw.y), b2 = dup2(bw.z), b3 = dup2(bw.w);
            fma2(acc2[0][0], a.x, b0); fma2(acc2[0][1], a.x, b1);
            fma2(acc2[0][2], a.x, b2); fma2(acc2[0][3], a.x, b3);
            fma2(acc2[1][0], a.y, b0); fma2(acc2[1][1], a.y, b1);
            fma2(acc2[1][2], a.y, b2); fma2(acc2[1][3], a.y, b3);
        }
        __syncthreads();
    }
#pragma unroll
    for (int c = 0; c < 4; c++) {
        float2 p0 = unpk(acc2[0][c]), p1 = unpk(acc2[1][c]);
        float bias = bp[tx*4 + c];
        float4 v4 = {p0.x + bias, p0.y + bias, p1.x + bias, p1.y + bias};
        *(float4*)&bufA[(tx*4 + c)*68 + ty*4] = v4;
    }
    __syncthreads();

    const float* Ws[3] = {Wq, Wk, Wv};
    const float* bs[3] = {bq, bk, bv};
    for (int t = 0; t < 3; t++) {
#pragma unroll
        for (int j = 0; j < 4; j++) {
            int i = fi + j*16;
            *(float4*)&bufB[i*68 + ff*4] = *(const float4*)&Ws[t][i*DD + ff*4];
        }
        __syncthreads();
        ull o2[2][4];
#pragma unroll
        for (int p = 0; p < 2; p++)
#pragma unroll
            for (int c = 0; c < 4; c++) o2[p][c] = 0ULL;
#pragma unroll 8
        for (int kk = 0; kk < 64; kk++) {
            ulonglong2 a = *(const ulonglong2*)&bufA[kk*68 + ty*4];
            float4 bw = *(const float4*)&bufB[kk*68 + tx*4];
            ull b0 = dup2(bw.x), b1 = dup2(bw.y), b2 = dup2(bw.z), b3 = dup2(bw.w);
            fma2(o2[0][0], a.x, b0); fma2(o2[0][1], a.x, b1);
            fma2(o2[0][2], a.x, b2); fma2(o2[0][3], a.x, b3);
            fma2(o2[1][0], a.y, b0); fma2(o2[1][1], a.y, b1);
            fma2(o2[1][2], a.y, b2); fma2(o2[1][3], a.y, b3);
        }
        if (t == 2) {
            float2 u[2][4];
#pragma unroll
            for (int p = 0; p < 2; p++)
#pragma unroll
                for (int c = 0; c < 4; c++) u[p][c] = unpk(o2[p][c]);
            float4 bias = *(const float4*)&bs[2][tx*4];
#pragma unroll
            for (int r = 0; r < 4; r++) {
                float4 v4;
                float2* up = u[r >> 1];
                if (r & 1) v4 = make_float4(up[0].y + bias.x, up[1].y + bias.y, up[2].y + bias.z, up[3].y + bias.w);
                else       v4 = make_float4(up[0].x + bias.x, up[1].x + bias.y, up[2].x + bias.z, up[3].x + bias.w);
                *(float4*)&g_v[(row0 + ty*4 + r)*DD + tx*4] = v4;
            }
        } else {
            float* dst = (t == 0) ? g_qT : g_kT;
#pragma unroll
            for (int c = 0; c < 4; c++) {
                float2 p0 = unpk(o2[0][c]), p1 = unpk(o2[1][c]);
                float bias = bs[t][tx*4 + c];
                float4 v4 = {p0.x + bias, p0.y + bias, p1.x + bias, p1.y + bias};
                *(float4*)&dst[b*DD*NN + (tx*4 + c)*NN + n0 + ty*4] = v4;
            }
        }
        __syncthreads();
    }
}

// ============================================================
// Kernel 2: R6 compute (64-row tiles, 128 CTAs, 512 thr) with
// cp.async K/V staging overlapped by buffer liveness.
// ============================================================
#define SCH 260
#define KB_OFF  16640
#define VB_OFF  33280
#define QT_OFF  49664
#define REL_OFF 54016
#define RK_OFF  54080
#define WS_OFF  54592
#define INV_OFF 54720
#define SMEM_FLOATS 54784
#define SMEM_BYTES  (SMEM_FLOATS*4)

__global__ __launch_bounds__(512) void attn_kernel(
    const int* __restrict__ ranks,
    const float* __restrict__ Wf1, const float* __restrict__ bf1,
    const float* __restrict__ Wf2, const float* __restrict__ bf2,
    const float* __restrict__ ln_g, const float* __restrict__ ln_b,
    const float* __restrict__ Ws1, const float* __restrict__ bs1,
    const float* __restrict__ Ws2, const float* __restrict__ bs2,
    float* __restrict__ out) {
    extern __shared__ float sm[];
    float* S    = sm;                    // 64x260 scores chunk / partials / h1T / ws
    float* KB   = sm + KB_OFF;           // kT chunk 64x260 / aoT+w1 / w2
    float* VB   = sm + VB_OFF;           // v chunk 256x64
    float* qT   = sm + QT_OFF;           // 64x68 / hnT
    float* rel  = sm + REL_OFF;
    int*   rk   = (int*)(sm + RK_OFF);
    float* wsum = sm + WS_OFF;
    float* invs = sm + INV_OFF;

    const int tid = threadIdx.x;
    const int b = blockIdx.y;
    const int q0 = blockIdx.x * 64;
    const int base = b * NN;
    const int bT = b * DD * NN;
    const int warp = tid >> 5, lane = tid & 31;

    const unsigned sb = (unsigned)__cvta_generic_to_shared(sm);
    const unsigned kbA = sb + KB_OFF*4;
    const unsigned vbA = sb + VB_OFF*4;

    // issue K0 (group), then V0 (group)
#pragma unroll
    for (int j = 0; j < 8; j++) {
        int idx = tid + j*512;
        int d = idx >> 6, f = idx & 63;
        cpa16(kbA + (d*SCH + f*4)*4, &g_kT[bT + d*NN + f*4]);
    }
    CP_COMMIT();
#pragma unroll
    for (int j = 0; j < 8; j++) {
        int idx = tid + j*512;
        int key = idx >> 4, f = idx & 15;
        cpa16(vbA + (key*64 + f*4)*4, &g_v[(base + key)*DD + f*4]);
    }
    CP_COMMIT();

    // regular staging of rel, ranks, qT
    if (tid <= MAXDIST) rel[tid] = g_rel[tid];
    for (int m = tid; m < NN; m += 512) rk[m] = ranks[base + m];
#pragma unroll
    for (int j = 0; j < 2; j++) {
        int idx = tid + j*512;
        int d = idx >> 4, f = idx & 15;
        *(float4*)&qT[d*68 + f*4] = *(const float4*)&g_qT[bT + d*NN + q0 + f*4];
    }

    const int ty = tid >> 6;        // 8 row-groups of 8 rows
    const int tx = tid & 63;        // 4 keys each
    int ri[8];
    const int g3   = tid >> 7;
    const int t3   = tid & 127;
    const int rowg = t3 >> 3;
    const int colg = t3 & 7;

    float rs[8];
#pragma unroll
    for (int r = 0; r < 8; r++) rs[r] = 0.f;
    ull accpv[4][4];
#pragma unroll
    for (int r = 0; r < 4; r++)
#pragma unroll
        for (int c = 0; c < 4; c++) accpv[r][c] = 0ULL;

    CP_WAIT1(); __syncthreads();     // K0 ready (qT/rk also synced)
#pragma unroll
    for (int rr = 0; rr < 8; rr++) ri[rr] = rk[q0 + ty*8 + rr];

    for (int ch = 0; ch < 2; ch++) {
        const int k0 = ch * 256;

        // ---- QK + exp into S ----
        {
            ull acc2[4][4];
#pragma unroll
            for (int p = 0; p < 4; p++)
#pragma unroll
                for (int c = 0; c < 4; c++) acc2[p][c] = 0ULL;
#pragma unroll 4
            for (int d = 0; d < 64; d++) {
                ulonglong2 a01 = *(const ulonglong2*)&qT[d*68 + ty*8];
                ulonglong2 a23 = *(const ulonglong2*)&qT[d*68 + ty*8 + 4];
                float4 kb = *(const float4*)&KB[d*SCH + tx*4];
                ull b0 = dup2(kb.x), b1 = dup2(kb.y), b2 = dup2(kb.z), b3 = dup2(kb.w);
                fma2(acc2[0][0], a01.x, b0); fma2(acc2[0][1], a01.x, b1);
                fma2(acc2[0][2], a01.x, b2); fma2(acc2[0][3], a01.x, b3);
                fma2(acc2[1][0], a01.y, b0); fma2(acc2[1][1], a01.y, b1);
                fma2(acc2[1][2], a01.y, b2); fma2(acc2[1][3], a01.y, b3);
                fma2(acc2[2][0], a23.x, b0); fma2(acc2[2][1], a23.x, b1);
                fma2(acc2[2][2], a23.x, b2); fma2(acc2[2][3], a23.x, b3);
                fma2(acc2[3][0], a23.y, b0); fma2(acc2[3][1], a23.y, b1);
                fma2(acc2[3][2], a23.y, b2); fma2(acc2[3][3], a23.y, b3);
            }
            int rkc[4];
#pragma unroll
            for (int c = 0; c < 4; c++) rkc[c] = rk[k0 + tx*4 + c];
#pragma unroll
            for (int p = 0; p < 4; p++) {
                float4 olo, ohi;
                float* plo = (float*)&olo;
                float* phi = (float*)&ohi;
                int rlo = ri[2*p], rhi = ri[2*p + 1];
#pragma unroll
                for (int c = 0; c < 4; c++) {
                    float2 u = unpk(acc2[p][c]);
                    int d0 = rlo - rkc[c]; if (d0 < 0) d0 = -d0; if (d0 > MAXDIST) d0 = MAXDIST;
                    int d1 = rhi - rkc[c]; if (d1 < 0) d1 = -d1; if (d1 > MAXDIST) d1 = MAXDIST;
                    float e0 = ex2(u.x * rel[d0]);
                    float e1 = ex2(u.y * rel[d1]);
                    plo[c] = e0; phi[c] = e1;
                    rs[2*p]     += e0;
                    rs[2*p + 1] += e1;
                }
                *(float4*)&S[(ty*8 + 2*p    )*SCH + tx*4] = olo;
                *(float4*)&S[(ty*8 + 2*p + 1)*SCH + tx*4] = ohi;
            }
        }
        if (ch == 1) {
#pragma unroll
            for (int r = 0; r < 8; r++) {
                float v = rs[r];
#pragma unroll
                for (int o = 16; o >= 1; o >>= 1) v += __shfl_xor_sync(0xffffffffu, v, o);
                if (lane == 0) wsum[warp*8 + r] = v;
            }
        }
        __syncthreads();              // S ready; KB free

        // prefetch K(ch+1) into KB (overlaps PV)
        if (ch == 0) {
#pragma unroll
            for (int j = 0; j < 8; j++) {
                int idx = tid + j*512;
                int d = idx >> 6, f = idx & 63;
                cpa16(kbA + (d*SCH + f*4)*4, &g_kT[bT + d*NN + 256 + f*4]);
            }
        }
        CP_COMMIT();
        if (ch == 1 && tid < 64) {
            int tty = tid >> 3, r = tid & 7;
            invs[tid] = 1.f / (wsum[tty*16 + r] + wsum[tty*16 + 8 + r]);
        }
        CP_WAIT1(); __syncthreads();  // V(ch) ready

        // ---- PV: splitK 4 groups x 64 keys ----
        {
            const int kl0 = g3 * 64;
#pragma unroll 2
            for (int kl = 0; kl < 64; kl += 4) {
                float4 p0 = *(const float4*)&S[(rowg*4 + 0)*SCH + kl0 + kl];
                float4 p1 = *(const float4*)&S[(rowg*4 + 1)*SCH + kl0 + kl];
                float4 p2 = *(const float4*)&S[(rowg*4 + 2)*SCH + kl0 + kl];
                float4 p3 = *(const float4*)&S[(rowg*4 + 3)*SCH + kl0 + kl];
                const float* pp0 = (const float*)&p0;
                const float* pp1 = (const float*)&p1;
                const float* pp2 = (const float*)&p2;
                const float* pp3 = (const float*)&p3;
#pragma unroll
                for (int j = 0; j < 4; j++) {
                    ulonglong2 v0 = *(const ulonglong2*)&VB[(kl0 + kl + j)*64 + colg*8];
                    ulonglong2 v1 = *(const ulonglong2*)&VB[(kl0 + kl + j)*64 + colg*8 + 4];
                    ull pa0 = dup2(pp0[j]);
                    ull pa1 = dup2(pp1[j]);
                    ull pa2 = dup2(pp2[j]);
                    ull pa3 = dup2(pp3[j]);
                    fma2(accpv[0][0], pa0, v0.x); fma2(accpv[0][1], pa0, v0.y);
                    fma2(accpv[0][2], pa0, v1.x); fma2(accpv[0][3], pa0, v1.y);
                    fma2(accpv[1][0], pa1, v0.x); fma2(accpv[1][1], pa1, v0.y);
                    fma2(accpv[1][2], pa1, v1.x); fma2(accpv[1][3], pa1, v1.y);
                    fma2(accpv[2][0], pa2, v0.x); fma2(accpv[2][1], pa2, v0.y);
                    fma2(accpv[2][2], pa2, v1.x); fma2(accpv[2][3], pa2, v1.y);
                    fma2(accpv[3][0], pa3, v0.x); fma2(accpv[3][1], pa3, v0.y);
                    fma2(accpv[3][2], pa3, v1.x); fma2(accpv[3][3], pa3, v1.y);
                }
            }
        }
        __syncthreads();              // VB free

        // prefetch V(ch+1) into VB (overlaps next QK)
        if (ch == 0) {
#pragma unroll
            for (int j = 0; j < 8; j++) {
                int idx = tid + j*512;
                int key = idx >> 4, f = idx & 15;
                cpa16(vbA + (key*64 + f*4)*4, &g_v[(base + 256 + key)*DD + f*4]);
            }
        }
        CP_COMMIT();
        if (ch == 0) { CP_WAIT1(); __syncthreads(); }   // K1 ready for next QK
    }

    // ---- splitK reduce + 1/sum + aoT ----
    {
        float po[4][8];
#pragma unroll
        for (int r = 0; r < 4; r++)
#pragma unroll
            for (int c = 0; c < 4; c++) {
                float2 u = unpk(accpv[r][c]);
                po[r][2*c] = u.x; po[r][2*c + 1] = u.y;
            }
        if (g3 > 0) {
            float* part = S + (g3 - 1)*4096;
#pragma unroll
            for (int r = 0; r < 4; r++) {
                *(float4*)&part[(rowg*4 + r)*64 + colg*8]     = *(float4*)&po[r][0];
                *(float4*)&part[(rowg*4 + r)*64 + colg*8 + 4] = *(float4*)&po[r][4];
            }
        }
        __syncthreads();
        if (g3 == 0) {
#pragma unroll
            for (int gg = 0; gg < 3; gg++) {
                float* part = S + gg*4096;
#pragma unroll
                for (int r = 0; r < 4; r++) {
                    float4 q0v = *(const float4*)&part[(rowg*4 + r)*64 + colg*8];
                    float4 q1v = *(const float4*)&part[(rowg*4 + r)*64 + colg*8 + 4];
                    po[r][0] += q0v.x; po[r][1] += q0v.y; po[r][2] += q0v.z; po[r][3] += q0v.w;
                    po[r][4] += q1v.x; po[r][5] += q1v.y; po[r][6] += q1v.z; po[r][7] += q1v.w;
                }
            }
            float iv[4];
#pragma unroll
            for (int r = 0; r < 4; r++) iv[r] = invs[rowg*4 + r];
#pragma unroll
            for (int c = 0; c < 8; c++) {
                float4 v4 = {po[0][c]*iv[0], po[1][c]*iv[1], po[2][c]*iv[2], po[3][c]*iv[3]};
                *(float4*)&KB[(colg*8 + c)*68 + rowg*4] = v4;   // aoT
            }
        } else {
            float* w1 = KB + 4352;
            for (int j = (g3 - 1)*128 + t3; j < 2048; j += 384)
                *(float4*)&w1[j*4] = *(const float4*)&Wf1[j*4];
        }
    }
    __syncthreads();

    // ---- FFN1: h1 = relu(ao@Wf1+bf1) (64x128) ----
    {
        const float* w1 = KB + 4352;
        const int ty4 = tid >> 5, tx4 = tid & 31;
        ull acc2[2][4];
#pragma unroll
        for (int p = 0; p < 2; p++)
#pragma unroll
            for (int c = 0; c < 4; c++) acc2[p][c] = 0ULL;
#pragma unroll 4
        for (int kk = 0; kk < 64; kk++) {
            ulonglong2 a = *(const ulonglong2*)&KB[kk*68 + ty4*4];
            float4 bw = *(const float4*)&w1[kk*128 + tx4*4];
            ull b0 = dup2(bw.x), b1 = dup2(bw.y), b2 = dup2(bw.z), b3 = dup2(bw.w);
            fma2(acc2[0][0], a.x, b0); fma2(acc2[0][1], a.x, b1);
            fma2(acc2[0][2], a.x, b2); fma2(acc2[0][3], a.x, b3);
            fma2(acc2[1][0], a.y, b0); fma2(acc2[1][1], a.y, b1);
            fma2(acc2[1][2], a.y, b2); fma2(acc2[1][3], a.y, b3);
        }
        __syncthreads();    // KB (aoT+w1) reads done
#pragma unroll
        for (int c = 0; c < 4; c++) {
            float bias = bf1[tx4*4 + c];
            float2 u0 = unpk(acc2[0][c]), u1 = unpk(acc2[1][c]);
            float4 v4 = {fmaxf(u0.x + bias, 0.f), fmaxf(u0.y + bias, 0.f),
                         fmaxf(u1.x + bias, 0.f), fmaxf(u1.y + bias, 0.f)};
            *(float4*)&S[(tx4*4 + c)*68 + ty4*4] = v4;   // h1T
        }
#pragma unroll
        for (int j = 0; j < 4; j++) {
            int f = tid + j*512;
            *(float4*)&KB[f*4] = *(const float4*)&Wf2[f*4];   // w2
        }
        *(float4*)&S[8960 + tid*4] = *(const float4*)&Ws1[tid*4];   // ws1
        if (tid < 8) *(float4*)&S[11008 + tid*4] = *(const float4*)&Ws2[tid*4];
    }
    __syncthreads();

    // ---- FFN2 + LayerNorm -> hnT (qT region) ----
    {
        const int ty4 = tid >> 5, tx4 = tid & 31;
        ull acc2[2][2];
        acc2[0][0] = acc2[0][1] = acc2[1][0] = acc2[1][1] = 0ULL;
#pragma unroll 4
        for (int kk = 0; kk < 128; kk++) {
            ulonglong2 a = *(const ulonglong2*)&S[kk*68 + ty4*4];
            float2 bw = *(const float2*)&KB[kk*64 + tx4*2];
            ull b0 = dup2(bw.x), b1 = dup2(bw.y);
            fma2(acc2[0][0], a.x, b0); fma2(acc2[0][1], a.x, b1);
            fma2(acc2[1][0], a.y, b0); fma2(acc2[1][1], a.y, b1);
        }
        float h2[4][2];
        {
            float2 u00 = unpk(acc2[0][0]), u01 = unpk(acc2[0][1]);
            float2 u10 = unpk(acc2[1][0]), u11 = unpk(acc2[1][1]);
            h2[0][0] = u00.x; h2[0][1] = u01.x;
            h2[1][0] = u00.y; h2[1][1] = u01.y;
            h2[2][0] = u10.x; h2[2][1] = u11.x;
            h2[3][0] = u10.y; h2[3][1] = u11.y;
        }
        float b0 = bf2[tx4*2], b1 = bf2[tx4*2 + 1];
        float g0v = ln_g[tx4*2], g1v = ln_g[tx4*2 + 1];
        float be0 = ln_b[tx4*2], be1 = ln_b[tx4*2 + 1];
#pragma unroll
        for (int r = 0; r < 4; r++) {
            float e0 = h2[r][0] + b0, e1 = h2[r][1] + b1;
            float s  = e0 + e1;
            float s2 = e0*e0 + e1*e1;
#pragma unroll
            for (int o = 16; o >= 1; o >>= 1) {
                s  += __shfl_xor_sync(0xffffffffu, s,  o);
                s2 += __shfl_xor_sync(0xffffffffu, s2, o);
            }
            float mu = s * (1.f/64.f);
            float var = s2 * (1.f/64.f) - mu*mu;
            float inv = rsqrtf(var + 1e-5f);
            qT[(tx4*2 + 0)*68 + ty4*4 + r] = (e0 - mu)*inv*g0v + be0;   // hnT
            qT[(tx4*2 + 1)*68 + ty4*4 + r] = (e1 - mu)*inv*g1v + be1;
        }
    }
    __syncthreads();

    // ---- head (threads 0..255) ----
    if (tid < 256) {
        const int ty4 = tid >> 4, tx4 = tid & 15;
        float s1[4][2];
#pragma unroll
        for (int r = 0; r < 4; r++) { s1[r][0] = 0.f; s1[r][1] = 0.f; }
#pragma unroll 4
        for (int kk = 0; kk < 64; kk++) {
            float4 a = *(const float4*)&qT[kk*68 + ty4*4];
            float w0 = S[8960 + kk*32 + tx4*2], w1b = S[8960 + kk*32 + tx4*2 + 1];
            s1[0][0] = fmaf(a.x, w0, s1[0][0]); s1[0][1] = fmaf(a.x, w1b, s1[0][1]);
            s1[1][0] = fmaf(a.y, w0, s1[1][0]); s1[1][1] = fmaf(a.y, w1b, s1[1][1]);
            s1[2][0] = fmaf(a.z, w0, s1[2][0]); s1[2][1] = fmaf(a.z, w1b, s1[2][1]);
            s1[3][0] = fmaf(a.w, w0, s1[3][0]); s1[3][1] = fmaf(a.w, w1b, s1[3][1]);
        }
        float w2a = S[11008 + tx4*2], w2b = S[11008 + tx4*2 + 1];
        float ba = bs1[tx4*2], bb = bs1[tx4*2 + 1];
        float bs2v = bs2[0];
#pragma unroll
        for (int r = 0; r < 4; r++) {
            float pa = fmaxf(s1[r][0] + ba, 0.f);
            float pb = fmaxf(s1[r][1] + bb, 0.f);
            float p = pa*w2a + pb*w2b;
#pragma unroll
            for (int o = 8; o >= 1; o >>= 1) p += __shfl_xor_sync(0xffffffffu, p, o, 16);
            if (tx4 == 0) {
                float z = p + bs2v;
                out[base + q0 + ty4*4 + r] = 1.f / (1.f + __expf(-z));
            }
        }
    }
}

// ============================================================
extern "C" void kernel_launch(void* const* d_in, const int* in_sizes, int n_in,
                              void* d_out, int out_size) {
    const float* x     = (const float*)d_in[0];
    const int*   ranks = (const int*)  d_in[1];
    const float* Wp    = (const float*)d_in[2];
    const float* bp    = (const float*)d_in[3];
    const float* Wq    = (const float*)d_in[4];
    const float* bq    = (const float*)d_in[5];
    const float* Wk    = (const float*)d_in[6];
    const float* bk    = (const float*)d_in[7];
    const float* Wv    = (const float*)d_in[8];
    const float* bv    = (const float*)d_in[9];
    const float* Eemb  = (const float*)d_in[10];
    const float* Wr1   = (const float*)d_in[11];
    const float* br1   = (const float*)d_in[12];
    const float* Wr2   = (const float*)d_in[13];
    const float* Wf1   = (const float*)d_in[14];
    const float* bf1   = (const float*)d_in[15];
    const float* Wf2   = (const float*)d_in[16];
    const float* bf2   = (const float*)d_in[17];
    const float* ln_g  = (const float*)d_in[18];
    const float* ln_b  = (const float*)d_in[19];
    const float* Ws1   = (const float*)d_in[20];
    const float* bs1   = (const float*)d_in[21];
    const float* Ws2   = (const float*)d_in[22];
    const float* bs2   = (const float*)d_in[23];
    float* out = (float*)d_out;

    cudaFuncSetAttribute(attn_kernel, cudaFuncAttributeMaxDynamicSharedMemorySize, SMEM_BYTES);

    qkv_kernel<<<BB*NN/64, 256>>>(x, Wp, bp, Wq, bq, Wk, bk, Wv, bv,
                                  Eemb, Wr1, br1, Wr2);
    dim3 grid(NN/64, BB);
    attn_kernel<<<grid, 512, SMEM_BYTES>>>(ranks, Wf1, bf1, Wf2, bf2,
                                           ln_g, ln_b, Ws1, bs1, Ws2, bs2, out);
}

// round 10
// speedup vs baseline: 1.5631x; 1.3851x over previous
#include <cuda_runtime.h>

#define BB   16
#define NN   512
#define DIN  256
#define DD   64
#define EE   32
#define MAXDIST 50

typedef unsigned long long ull;

__device__ __forceinline__ void fma2(ull& d, ull a, ull b) {
    asm("fma.rn.f32x2 %0, %1, %2, %0;" : "+l"(d) : "l"(a), "l"(b));
}
__device__ __forceinline__ ull dup2(float x) {
    unsigned u = __float_as_uint(x); ull d;
    asm("mov.b64 %0, {%1, %1};" : "=l"(d) : "r"(u));
    return d;
}
__device__ __forceinline__ float2 unpk(ull u) {
    unsigned lo, hi;
    asm("mov.b64 {%0, %1}, %2;" : "=r"(lo), "=r"(hi) : "l"(u));
    return make_float2(__uint_as_float(lo), __uint_as_float(hi));
}
__device__ __forceinline__ float ex2(float x) {
    float r;
    asm("ex2.approx.f32 %0, %1;" : "=f"(r) : "f"(x));
    return r;
}
__device__ __forceinline__ unsigned cvt_tf32(float x) {
    unsigned r;
    asm("cvt.rna.tf32.f32 %0, %1;" : "=r"(r) : "f"(x));
    return r;
}
__device__ __forceinline__ void mma_tf32(float& c0, float& c1, float& c2, float& c3,
                                         unsigned a0, unsigned a1, unsigned a2, unsigned a3,
                                         unsigned b0, unsigned b1) {
    asm("mma.sync.aligned.m16n8k8.row.col.f32.tf32.tf32.f32 "
        "{%0,%1,%2,%3}, {%4,%5,%6,%7}, {%8,%9}, {%0,%1,%2,%3};"
        : "+f"(c0), "+f"(c1), "+f"(c2), "+f"(c3)
        : "r"(a0), "r"(a1), "r"(a2), "r"(a3), "r"(b0), "r"(b1));
}
__device__ __forceinline__ void cpa16(unsigned dst, const float* src) {
    asm volatile("cp.async.cg.shared.global [%0], [%1], 16;" :: "r"(dst), "l"(src));
}
#define CP_COMMIT() asm volatile("cp.async.commit_group;" ::: "memory")
#define CP_WAIT2()  asm volatile("cp.async.wait_group 2;" ::: "memory")
#define CP_WAIT1()  asm volatile("cp.async.wait_group 1;" ::: "memory")
#define CP_WAIT0()  asm volatile("cp.async.wait_group 0;" ::: "memory")

__device__ float g_qT[BB*DD*NN];   // per batch: [d][n]
__device__ float g_kT[BB*DD*NN];   // per batch: [d][n]
__device__ float g_v [BB*NN*DD];   // row-major [n][d]
__device__ float g_rel[MAXDIST+1]; // 0.125 * log2(e) * sigmoid(...)

// ============================================================
// Kernel 1: xp = x@Wp+bp ; q,k,v = xp@W{q,k,v}+b (FFMA2)
// ============================================================
__global__ __launch_bounds__(256) void qkv_kernel(
    const float* __restrict__ x,
    const float* __restrict__ Wp, const float* __restrict__ bp,
    const float* __restrict__ Wq, const float* __restrict__ bq,
    const float* __restrict__ Wk, const float* __restrict__ bk,
    const float* __restrict__ Wv, const float* __restrict__ bv,
    const float* __restrict__ Eemb, const float* __restrict__ Wr1,
    const float* __restrict__ br1,  const float* __restrict__ Wr2) {
    __shared__ float bufA[64*68];
    __shared__ float bufB[64*68];
    const int tid = threadIdx.x;
    const int ty = tid >> 4, tx = tid & 15;
    const int row0 = blockIdx.x * 64;
    const int b = row0 >> 9;
    const int n0 = row0 & 511;

    if (blockIdx.x == 0 && tid <= MAXDIST) {
        float e[EE];
#pragma unroll
        for (int c = 0; c < EE; c++) e[c] = Eemb[tid*EE + c];
        float w = 0.f;
#pragma unroll
        for (int j = 0; j < 16; j++) {
            float h = br1[j];
#pragma unroll
            for (int c = 0; c < EE; c++) h = fmaf(e[c], Wr1[c*16 + j], h);
            h = fmaxf(h, 0.f);
            w = fmaf(h, Wr2[j], w);
        }
        g_rel[tid] = 0.18033688011112042f / (1.f + __expf(-w));
    }

    const int fi = tid >> 4;
    const int ff = tid & 15;

    float4 ra4[4], rb4[4];
#pragma unroll
    for (int j = 0; j < 4; j++) {
        int i = fi + j*16;
        ra4[j] = *(const float4*)&x[(row0 + i)*DIN + ff*4];
        rb4[j] = *(const float4*)&Wp[i*DD + ff*4];
    }
    ull acc2[2][4];
#pragma unroll
    for (int p = 0; p < 2; p++)
#pragma unroll
        for (int c = 0; c < 4; c++) acc2[p][c] = 0ULL;

    for (int kc = 0; kc < 4; kc++) {
#pragma unroll
        for (int j = 0; j < 4; j++) {
            int i = fi + j*16;
            bufA[(ff*4 + 0)*68 + i] = ra4[j].x;
            bufA[(ff*4 + 1)*68 + i] = ra4[j].y;
            bufA[(ff*4 + 2)*68 + i] = ra4[j].z;
            bufA[(ff*4 + 3)*68 + i] = ra4[j].w;
            *(float4*)&bufB[i*68 + ff*4] = rb4[j];
        }
        __syncthreads();
        if (kc < 3) {
#pragma unroll
            for (int j = 0; j < 4; j++) {
                int i = fi + j*16;
                ra4[j] = *(const float4*)&x[(row0 + i)*DIN + (kc+1)*64 + ff*4];
                rb4[j] = *(const float4*)&Wp[((kc+1)*64 + i)*DD + ff*4];
            }
        }
#pragma unroll 8
        for (int kk = 0; kk < 64; kk++) {
            ulonglong2 a = *(const ulonglong2*)&bufA[kk*68 + ty*4];
            float4 bw = *(const float4*)&bufB[kk*68 + tx*4];
            ull b0 = dup2(bw.x), b1 = dup2(bw.y), b2 = dup2(bw.z), b3 = dup2(bw.w);
            fma2(acc2[0][0], a.x, b0); fma2(acc2[0][1], a.x, b1);
            fma2(acc2[0][2], a.x, b2); fma2(acc2[0][3], a.x, b3);
            fma2(acc2[1][0], a.y, b0); fma2(acc2[1][1], a.y, b1);
            fma2(acc2[1][2], a.y, b2); fma2(acc2[1][3], a.y, b3);
        }
        __syncthreads();
    }
#pragma unroll
    for (int c = 0; c < 4; c++) {
        float2 p0 = unpk(acc2[0][c]), p1 = unpk(acc2[1][c]);
        float bias = bp[tx*4 + c];
        float4 v4 = {p0.x + bias, p0.y + bias, p1.x + bias, p1.y + bias};
        *(float4*)&bufA[(tx*4 + c)*68 + ty*4] = v4;
    }
    __syncthreads();

    const float* Ws[3] = {Wq, Wk, Wv};
    const float* bs[3] = {bq, bk, bv};
    for (int t = 0; t < 3; t++) {
#pragma unroll
        for (int j = 0; j < 4; j++) {
            int i = fi + j*16;
            *(float4*)&bufB[i*68 + ff*4] = *(const float4*)&Ws[t][i*DD + ff*4];
        }
        __syncthreads();
        ull o2[2][4];
#pragma unroll
        for (int p = 0; p < 2; p++)
#pragma unroll
            for (int c = 0; c < 4; c++) o2[p][c] = 0ULL;
#pragma unroll 8
        for (int kk = 0; kk < 64; kk++) {
            ulonglong2 a = *(const ulonglong2*)&bufA[kk*68 + ty*4];
            float4 bw = *(const float4*)&bufB[kk*68 + tx*4];
            ull b0 = dup2(bw.x), b1 = dup2(bw.y), b2 = dup2(bw.z), b3 = dup2(bw.w);
            fma2(o2[0][0], a.x, b0); fma2(o2[0][1], a.x, b1);
            fma2(o2[0][2], a.x, b2); fma2(o2[0][3], a.x, b3);
            fma2(o2[1][0], a.y, b0); fma2(o2[1][1], a.y, b1);
            fma2(o2[1][2], a.y, b2); fma2(o2[1][3], a.y, b3);
        }
        if (t == 2) {
            float2 u[2][4];
#pragma unroll
            for (int p = 0; p < 2; p++)
#pragma unroll
                for (int c = 0; c < 4; c++) u[p][c] = unpk(o2[p][c]);
            float4 bias = *(const float4*)&bs[2][tx*4];
#pragma unroll
            for (int r = 0; r < 4; r++) {
                float4 v4;
                float2* up = u[r >> 1];
                if (r & 1) v4 = make_float4(up[0].y + bias.x, up[1].y + bias.y, up[2].y + bias.z, up[3].y + bias.w);
                else       v4 = make_float4(up[0].x + bias.x, up[1].x + bias.y, up[2].x + bias.z, up[3].x + bias.w);
                *(float4*)&g_v[(row0 + ty*4 + r)*DD + tx*4] = v4;
            }
        } else {
            float* dst = (t == 0) ? g_qT : g_kT;
#pragma unroll
            for (int c = 0; c < 4; c++) {
                float2 p0 = unpk(o2[0][c]), p1 = unpk(o2[1][c]);
                float bias = bs[t][tx*4 + c];
                float4 v4 = {p0.x + bias, p0.y + bias, p1.x + bias, p1.y + bias};
                *(float4*)&dst[b*DD*NN + (tx*4 + c)*NN + n0 + ty*4] = v4;
            }
        }
        __syncthreads();
    }
}

// ============================================================
// Kernel 2: tf32 mma.sync QK + PV, cp.async pipeline, FFMA2 FFN.
// 64-row query tiles, 128 CTAs, 512 threads.
// ============================================================
#define S_OFF    0       /* 64x260 = 16640 : exp scores / h1T+ws */
#define KB_OFF   16640   /* 64x264 = 16896 : kT chunk / aoT+w1 / w2 */
#define VA_OFF   33536   /* 128x72 = 9216 */
#define VB2_OFF  42752   /* 128x72 = 9216 */
#define QT_OFF   51968   /* 64x72  = 4608 : qT(tf32) / hnT */
#define REL_OFF  56576
#define RK_OFF   56640
#define WS_OFF   57152   /* 256 */
#define INV_OFF  57408   /* 64 */
#define SMEM_FLOATS 57472
#define SMEM_BYTES  (SMEM_FLOATS*4)

// QK chunk: mma over 64 d, epilogue exp+rel into S, rowsums.
__device__ __forceinline__ void qk_chunk(
    float* S, const unsigned* qTb, const float* KB, const float* rel, const int* rk,
    int k0, int wc, int q, int g, int r0, int r1, int ri0, int ri1,
    float& rs0, float& rs1) {
    float acc[8][4];
#pragma unroll
    for (int cb = 0; cb < 8; cb++) {
        acc[cb][0] = 0.f; acc[cb][1] = 0.f; acc[cb][2] = 0.f; acc[cb][3] = 0.f;
    }
#pragma unroll
    for (int ks = 0; ks < 8; ks++) {
        unsigned a0 = qTb[(ks*8 + q)*72 + r0];
        unsigned a1 = qTb[(ks*8 + q)*72 + r1];
        unsigned a2 = qTb[(ks*8 + q + 4)*72 + r0];
        unsigned a3 = qTb[(ks*8 + q + 4)*72 + r1];
#pragma unroll
        for (int cb = 0; cb < 8; cb++) {
            int key0 = wc*64 + cb*8;
            unsigned b0 = cvt_tf32(KB[(ks*8 + q)*264 + key0 + g]);
            unsigned b1 = cvt_tf32(KB[(ks*8 + q + 4)*264 + key0 + g]);
            mma_tf32(acc[cb][0], acc[cb][1], acc[cb][2], acc[cb][3],
                     a0, a1, a2, a3, b0, b1);
        }
    }
#pragma unroll
    for (int cb = 0; cb < 8; cb++) {
        int kloc = wc*64 + cb*8 + 2*q;
        int ka = rk[k0 + kloc], kb = rk[k0 + kloc + 1];
        int d00 = ri0 - ka; d00 = d00 < 0 ? -d00 : d00; if (d00 > MAXDIST) d00 = MAXDIST;
        int d01 = ri0 - kb; d01 = d01 < 0 ? -d01 : d01; if (d01 > MAXDIST) d01 = MAXDIST;
        int d10 = ri1 - ka; d10 = d10 < 0 ? -d10 : d10; if (d10 > MAXDIST) d10 = MAXDIST;
        int d11 = ri1 - kb; d11 = d11 < 0 ? -d11 : d11; if (d11 > MAXDIST) d11 = MAXDIST;
        float f00 = __uint_as_float(cvt_tf32(ex2(acc[cb][0] * rel[d00])));
        float f01 = __uint_as_float(cvt_tf32(ex2(acc[cb][1] * rel[d01])));
        float f10 = __uint_as_float(cvt_tf32(ex2(acc[cb][2] * rel[d10])));
        float f11 = __uint_as_float(cvt_tf32(ex2(acc[cb][3] * rel[d11])));
        *(float2*)&S[r0*260 + kloc] = make_float2(f00, f01);
        *(float2*)&S[r1*260 + kloc] = make_float2(f10, f11);
        rs0 += f00 + f01;
        rs1 += f10 + f11;
    }
}

// PV half: 128 keys of one chunk, accumulate into accpv.
__device__ __forceinline__ void pv_half(
    const unsigned* Sb, const float* VB,
    int h, int wc, int q, int g, int r0, int r1, float (&accpv)[2][4]) {
#pragma unroll
    for (int ks = 0; ks < 16; ks++) {
        int kk = h*128 + ks*8;
        unsigned a0 = Sb[r0*260 + kk + q];
        unsigned a1 = Sb[r1*260 + kk + q];
        unsigned a2 = Sb[r0*260 + kk + q + 4];
        unsigned a3 = Sb[r1*260 + kk + q + 4];
#pragma unroll
        for (int cb = 0; cb < 2; cb++) {
            int d0 = wc*16 + cb*8;
            unsigned b0 = cvt_tf32(VB[(ks*8 + q)*72 + d0 + g]);
            unsigned b1 = cvt_tf32(VB[(ks*8 + q + 4)*72 + d0 + g]);
            mma_tf32(accpv[cb][0], accpv[cb][1], accpv[cb][2], accpv[cb][3],
                     a0, a1, a2, a3, b0, b1);
        }
    }
}

__global__ __launch_bounds__(512) void attn_kernel(
    const int* __restrict__ ranks,
    const float* __restrict__ Wf1, const float* __restrict__ bf1,
    const float* __restrict__ Wf2, const float* __restrict__ bf2,
    const float* __restrict__ ln_g, const float* __restrict__ ln_b,
    const float* __restrict__ Ws1, const float* __restrict__ bs1,
    const float* __restrict__ Ws2, const float* __restrict__ bs2,
    float* __restrict__ out) {
    extern __shared__ float sm[];
    float* S    = sm + S_OFF;
    float* KB   = sm + KB_OFF;
    float* VAf  = sm + VA_OFF;
    float* VBf  = sm + VB2_OFF;
    float* qTf  = sm + QT_OFF;
    float* rel  = sm + REL_OFF;
    int*   rk   = (int*)(sm + RK_OFF);
    float* wsum = sm + WS_OFF;
    float* invs = sm + INV_OFF;
    const unsigned* qTb = (const unsigned*)qTf;
    const unsigned* Sb  = (const unsigned*)S;

    const int tid = threadIdx.x;
    const int b = blockIdx.y;
    const int q0 = blockIdx.x * 64;
    const int base = b * NN;
    const int bT = b * DD * NN;
    const int wp = tid >> 5, lane = tid & 31;
    const int g = lane >> 2, q = lane & 3;
    const int rb = wp >> 2, wc = wp & 3;
    const int r0 = rb*16 + g, r1 = r0 + 8;

    const unsigned sb = (unsigned)__cvta_generic_to_shared(sm);
    const unsigned kbA = sb + KB_OFF*4;
    const unsigned vaA = sb + VA_OFF*4;
    const unsigned vbA = sb + VB2_OFF*4;

    // ---- issue K0, Va(0-127), Vb(128-255) ----
#pragma unroll
    for (int j = 0; j < 8; j++) {
        int idx = tid + j*512;
        int d = idx >> 6, f = idx & 63;
        cpa16(kbA + (unsigned)((d*264 + f*4)*4), &g_kT[bT + d*NN + f*4]);
    }
    CP_COMMIT();                                          // grp1: K0
#pragma unroll
    for (int j = 0; j < 4; j++) {
        int idx = tid + j*512;
        int key = idx >> 4, f = idx & 15;
        cpa16(vaA + (unsigned)((key*72 + f*4)*4), &g_v[(base + key)*DD + f*4]);
    }
    CP_COMMIT();                                          // grp2: Va
#pragma unroll
    for (int j = 0; j < 4; j++) {
        int idx = tid + j*512;
        int key = idx >> 4, f = idx & 15;
        cpa16(vbA + (unsigned)((key*72 + f*4)*4), &g_v[(base + 128 + key)*DD + f*4]);
    }
    CP_COMMIT();                                          // grp3: Vb

    // ---- stage rel, rk, qT (pre-converted to tf32) ----
    if (tid <= MAXDIST) rel[tid] = g_rel[tid];
    for (int m = tid; m < NN; m += 512) rk[m] = ranks[base + m];
#pragma unroll
    for (int j = 0; j < 2; j++) {
        int idx = tid + j*512;
        int d = idx >> 4, f = idx & 15;
        float4 v = *(const float4*)&g_qT[bT + d*NN + q0 + f*4];
        unsigned* dst = (unsigned*)&qTf[d*72 + f*4];
        dst[0] = cvt_tf32(v.x); dst[1] = cvt_tf32(v.y);
        dst[2] = cvt_tf32(v.z); dst[3] = cvt_tf32(v.w);
    }

    float rs0 = 0.f, rs1 = 0.f;
    float accpv[2][4];
#pragma unroll
    for (int c = 0; c < 2; c++) {
        accpv[c][0] = 0.f; accpv[c][1] = 0.f; accpv[c][2] = 0.f; accpv[c][3] = 0.f;
    }

    CP_WAIT2(); __syncthreads();                           // K0 ready
    const int ri0 = rk[q0 + r0], ri1 = rk[q0 + r1];

    // ---- QK chunk 0 ----
    qk_chunk(S, qTb, KB, rel, rk, 0, wc, q, g, r0, r1, ri0, ri1, rs0, rs1);
    __syncthreads();                                       // S0 ready, KB free

    // issue K1
#pragma unroll
    for (int j = 0; j < 8; j++) {
        int idx = tid + j*512;
        int d = idx >> 6, f = idx & 63;
        cpa16(kbA + (unsigned)((d*264 + f*4)*4), &g_kT[bT + d*NN + 256 + f*4]);
    }
    CP_COMMIT();                                          // grp4: K1

    CP_WAIT2(); __syncthreads();                           // Va ready
    pv_half(Sb, VAf, 0, wc, q, g, r0, r1, accpv);          // keys 0-127
    CP_WAIT1(); __syncthreads();                           // Vb ready, VAf free
    // issue Va2 (keys 256-383)
#pragma unroll
    for (int j = 0; j < 4; j++) {
        int idx = tid + j*512;
        int key = idx >> 4, f = idx & 15;
        cpa16(vaA + (unsigned)((key*72 + f*4)*4), &g_v[(base + 256 + key)*DD + f*4]);
    }
    CP_COMMIT();                                          // grp5: Va2
    pv_half(Sb, VBf, 1, wc, q, g, r0, r1, accpv);          // keys 128-255
    __syncthreads();                                       // VBf free, S free
    // issue Vb2 (keys 384-511)
#pragma unroll
    for (int j = 0; j < 4; j++) {
        int idx = tid + j*512;
        int key = idx >> 4, f = idx & 15;
        cpa16(vbA + (unsigned)((key*72 + f*4)*4), &g_v[(base + 384 + key)*DD + f*4]);
    }
    CP_COMMIT();                                          // grp6: Vb2
    CP_WAIT2(); __syncthreads();                           // K1 ready

    // ---- QK chunk 1 + rowsum finalize ----
    qk_chunk(S, qTb, KB, rel, rk, 256, wc, q, g, r0, r1, ri0, ri1, rs0, rs1);
    {
        rs0 += __shfl_xor_sync(0xffffffffu, rs0, 1);
        rs0 += __shfl_xor_sync(0xffffffffu, rs0, 2);
        rs1 += __shfl_xor_sync(0xffffffffu, rs1, 1);
        rs1 += __shfl_xor_sync(0xffffffffu, rs1, 2);
        if (q == 0) {
            wsum[wc*64 + r0] = rs0;
            wsum[wc*64 + r1] = rs1;
        }
    }
    __syncthreads();                                       // S1 + wsum ready
    if (tid < 64)
        invs[tid] = 1.f / (wsum[tid] + wsum[64 + tid] + wsum[128 + tid] + wsum[192 + tid]);
    // issue w1 -> KB+4352 (full 8192 floats, overlaps PV1)
#pragma unroll
    for (int j = 0; j < 4; j++) {
        int f = tid + j*512;
        cpa16(kbA + (unsigned)((4352 + f*4)*4), &Wf1[f*4]);
    }
    CP_COMMIT();                                          // grp7: w1

    CP_WAIT2(); __syncthreads();                           // Va2 ready (+invs visible)
    pv_half(Sb, VAf, 0, wc, q, g, r0, r1, accpv);          // keys 256-383
    CP_WAIT1(); __syncthreads();                           // Vb2 ready
    pv_half(Sb, VBf, 1, wc, q, g, r0, r1, accpv);          // keys 384-511
    CP_WAIT0();
    __syncthreads();                                       // w1 ready, all PV done

    // ---- PV epilogue: scale 1/sum, write aoT [d][row] (KB, stride 68) ----
    {
        float iv0 = invs[r0], iv1 = invs[r1];
#pragma unroll
        for (int cb = 0; cb < 2; cb++) {
            int dc = wc*16 + cb*8 + 2*q;
            KB[dc*68 + r0]       = accpv[cb][0] * iv0;
            KB[(dc + 1)*68 + r0] = accpv[cb][1] * iv0;
            KB[dc*68 + r1]       = accpv[cb][2] * iv1;
            KB[(dc + 1)*68 + r1] = accpv[cb][3] * iv1;
        }
    }
    __syncthreads();

    // ---- FFN1: h1 = relu(ao@Wf1+bf1) (64x128), FFMA2 ----
    {
        const float* w1 = KB + 4352;
        const int ty4 = tid >> 5, tx4 = tid & 31;
        ull acc2[2][4];
#pragma unroll
        for (int p = 0; p < 2; p++)
#pragma unroll
            for (int c = 0; c < 4; c++) acc2[p][c] = 0ULL;
#pragma unroll 4
        for (int kk = 0; kk < 64; kk++) {
            ulonglong2 a = *(const ulonglong2*)&KB[kk*68 + ty4*4];
            float4 bw = *(const float4*)&w1[kk*128 + tx4*4];
            ull b0 = dup2(bw.x), b1 = dup2(bw.y), b2 = dup2(bw.z), b3 = dup2(bw.w);
            fma2(acc2[0][0], a.x, b0); fma2(acc2[0][1], a.x, b1);
            fma2(acc2[0][2], a.x, b2); fma2(acc2[0][3], a.x, b3);
            fma2(acc2[1][0], a.y, b0); fma2(acc2[1][1], a.y, b1);
            fma2(acc2[1][2], a.y, b2); fma2(acc2[1][3], a.y, b3);
        }
        __syncthreads();
#pragma unroll
        for (int c = 0; c < 4; c++) {
            float bias = bf1[tx4*4 + c];
            float2 u0 = unpk(acc2[0][c]), u1 = unpk(acc2[1][c]);
            float4 v4 = {fmaxf(u0.x + bias, 0.f), fmaxf(u0.y + bias, 0.f),
                         fmaxf(u1.x + bias, 0.f), fmaxf(u1.y + bias, 0.f)};
            *(float4*)&S[(tx4*4 + c)*68 + ty4*4] = v4;   // h1T
        }
#pragma unroll
        for (int j = 0; j < 4; j++) {
            int f = tid + j*512;
            *(float4*)&KB[f*4] = *(const float4*)&Wf2[f*4];   // w2
        }
        *(float4*)&S[8960 + tid*4] = *(const float4*)&Ws1[tid*4];   // ws1
        if (tid < 8) *(float4*)&S[11008 + tid*4] = *(const float4*)&Ws2[tid*4];
    }
    __syncthreads();

    // ---- FFN2 + LayerNorm -> hnT (qT region, stride 68) ----
    {
        const int ty4 = tid >> 5, tx4 = tid & 31;
        ull acc2[2][2];
        acc2[0][0] = acc2[0][1] = acc2[1][0] = acc2[1][1] = 0ULL;
#pragma unroll 4
        for (int kk = 0; kk < 128; kk++) {
            ulonglong2 a = *(const ulonglong2*)&S[kk*68 + ty4*4];
            float2 bw = *(const float2*)&KB[kk*64 + tx4*2];
            ull b0 = dup2(bw.x), b1 = dup2(bw.y);
            fma2(acc2[0][0], a.x, b0); fma2(acc2[0][1], a.x, b1);
            fma2(acc2[1][0], a.y, b0); fma2(acc2[1][1], a.y, b1);
        }
        float h2[4][2];
        {
            float2 u00 = unpk(acc2[0][0]), u01 = unpk(acc2[0][1]);
            float2 u10 = unpk(acc2[1][0]), u11 = unpk(acc2[1][1]);
            h2[0][0] = u00.x; h2[0][1] = u01.x;
            h2[1][0] = u00.y; h2[1][1] = u01.y;
            h2[2][0] = u10.x; h2[2][1] = u11.x;
            h2[3][0] = u10.y; h2[3][1] = u11.y;
        }
        float b0 = bf2[tx4*2], b1 = bf2[tx4*2 + 1];
        float g0v = ln_g[tx4*2], g1v = ln_g[tx4*2 + 1];
        float be0 = ln_b[tx4*2], be1 = ln_b[tx4*2 + 1];
#pragma unroll
        for (int r = 0; r < 4; r++) {
            float e0 = h2[r][0] + b0, e1 = h2[r][1] + b1;
            float s  = e0 + e1;
            float s2 = e0*e0 + e1*e1;
#pragma unroll
            for (int o = 16; o >= 1; o >>= 1) {
                s  += __shfl_xor_sync(0xffffffffu, s,  o);
                s2 += __shfl_xor_sync(0xffffffffu, s2, o);
            }
            float mu = s * (1.f/64.f);
            float var = s2 * (1.f/64.f) - mu*mu;
            float inv = rsqrtf(var + 1e-5f);
            qTf[(tx4*2 + 0)*68 + ty4*4 + r] = (e0 - mu)*inv*g0v + be0;   // hnT
            qTf[(tx4*2 + 1)*68 + ty4*4 + r] = (e1 - mu)*inv*g1v + be1;
        }
    }
    __syncthreads();

    // ---- head (threads 0..255) ----
    if (tid < 256) {
        const int ty4 = tid >> 4, tx4 = tid & 15;
        float s1[4][2];
#pragma unroll
        for (int r = 0; r < 4; r++) { s1[r][0] = 0.f; s1[r][1] = 0.f; }
#pragma unroll 4
        for (int kk = 0; kk < 64; kk++) {
            float4 a = *(const float4*)&qTf[kk*68 + ty4*4];
            float w0 = S[8960 + kk*32 + tx4*2], w1b = S[8960 + kk*32 + tx4*2 + 1];
            s1[0][0] = fmaf(a.x, w0, s1[0][0]); s1[0][1] = fmaf(a.x, w1b, s1[0][1]);
            s1[1][0] = fmaf(a.y, w0, s1[1][0]); s1[1][1] = fmaf(a.y, w1b, s1[1][1]);
            s1[2][0] = fmaf(a.z, w0, s1[2][0]); s1[2][1] = fmaf(a.z, w1b, s1[2][1]);
            s1[3][0] = fmaf(a.w, w0, s1[3][0]); s1[3][1] = fmaf(a.w, w1b, s1[3][1]);
        }
        float w2a = S[11008 + tx4*2], w2b = S[11008 + tx4*2 + 1];
        float ba = bs1[tx4*2], bb = bs1[tx4*2 + 1];
        float bs2v = bs2[0];
#pragma unroll
        for (int r = 0; r < 4; r++) {
            float pa = fmaxf(s1[r][0] + ba, 0.f);
            float pb = fmaxf(s1[r][1] + bb, 0.f);
            float p = pa*w2a + pb*w2b;
#pragma unroll
            for (int o = 8; o >= 1; o >>= 1) p += __shfl_xor_sync(0xffffffffu, p, o, 16);
            if (tx4 == 0) {
                float z = p + bs2v;
                out[base + q0 + ty4*4 + r] = 1.f / (1.f + __expf(-z));
            }
        }
    }
}

// ============================================================
extern "C" void kernel_launch(void* const* d_in, const int* in_sizes, int n_in,
                              void* d_out, int out_size) {
    const float* x     = (const float*)d_in[0];
    const int*   ranks = (const int*)  d_in[1];
    const float* Wp    = (const float*)d_in[2];
    const float* bp    = (const float*)d_in[3];
    const float* Wq    = (const float*)d_in[4];
    const float* bq    = (const float*)d_in[5];
    const float* Wk    = (const float*)d_in[6];
    const float* bk    = (const float*)d_in[7];
    const float* Wv    = (const float*)d_in[8];
    const float* bv    = (const float*)d_in[9];
    const float* Eemb  = (const float*)d_in[10];
    const float* Wr1   = (const float*)d_in[11];
    const float* br1   = (const float*)d_in[12];
    const float* Wr2   = (const float*)d_in[13];
    const float* Wf1   = (const float*)d_in[14];
    const float* bf1   = (const float*)d_in[15];
    const float* Wf2   = (const float*)d_in[16];
    const float* bf2   = (const float*)d_in[17];
    const float* ln_g  = (const float*)d_in[18];
    const float* ln_b  = (const float*)d_in[19];
    const float* Ws1   = (const float*)d_in[20];
    const float* bs1   = (const float*)d_in[21];
    const float* Ws2   = (const float*)d_in[22];
    const float* bs2   = (const float*)d_in[23];
    float* out = (float*)d_out;

    cudaFuncSetAttribute(attn_kernel, cudaFuncAttributeMaxDynamicSharedMemorySize, SMEM_BYTES);

    qkv_kernel<<<BB*NN/64, 256>>>(x, Wp, bp, Wq, bq, Wk, bk, Wv, bv,
                                  Eemb, Wr1, br1, Wr2);
    dim3 grid(NN/64, BB);
    attn_kernel<<<grid, 512, SMEM_BYTES>>>(ranks, Wf1, bf1, Wf2, bf2,
                                           ln_g, ln_b, Ws1, bs1, Ws2, bs2, out);
}

// round 11
// speedup vs baseline: 1.9309x; 1.2353x over previous
#include <cuda_runtime.h>

#define BB   16
#define NN   512
#define DIN  256
#define DD   64
#define EE   32
#define MAXDIST 50

typedef unsigned long long ull;

__device__ __forceinline__ void fma2(ull& d, ull a, ull b) {
    asm("fma.rn.f32x2 %0, %1, %2, %0;" : "+l"(d) : "l"(a), "l"(b));
}
__device__ __forceinline__ ull dup2(float x) {
    unsigned u = __float_as_uint(x); ull d;
    asm("mov.b64 %0, {%1, %1};" : "=l"(d) : "r"(u));
    return d;
}
__device__ __forceinline__ float2 unpk(ull u) {
    unsigned lo, hi;
    asm("mov.b64 {%0, %1}, %2;" : "=r"(lo), "=r"(hi) : "l"(u));
    return make_float2(__uint_as_float(lo), __uint_as_float(hi));
}
__device__ __forceinline__ float ex2(float x) {
    float r;
    asm("ex2.approx.f32 %0, %1;" : "=f"(r) : "f"(x));
    return r;
}
__device__ __forceinline__ unsigned cvt_tf32(float x) {
    unsigned r;
    asm("cvt.rna.tf32.f32 %0, %1;" : "=r"(r) : "f"(x));
    return r;
}
__device__ __forceinline__ void mma_tf32(float& c0, float& c1, float& c2, float& c3,
                                         unsigned a0, unsigned a1, unsigned a2, unsigned a3,
                                         unsigned b0, unsigned b1) {
    asm("mma.sync.aligned.m16n8k8.row.col.f32.tf32.tf32.f32 "
        "{%0,%1,%2,%3}, {%4,%5,%6,%7}, {%8,%9}, {%0,%1,%2,%3};"
        : "+f"(c0), "+f"(c1), "+f"(c2), "+f"(c3)
        : "r"(a0), "r"(a1), "r"(a2), "r"(a3), "r"(b0), "r"(b1));
}
__device__ __forceinline__ void cpa16(unsigned dst, const float* src) {
    asm volatile("cp.async.cg.shared.global [%0], [%1], 16;" :: "r"(dst), "l"(src));
}
#define CP_COMMIT() asm volatile("cp.async.commit_group;" ::: "memory")
#define CP_WAIT2()  asm volatile("cp.async.wait_group 2;" ::: "memory")
#define CP_WAIT1()  asm volatile("cp.async.wait_group 1;" ::: "memory")
#define CP_WAIT0()  asm volatile("cp.async.wait_group 0;" ::: "memory")

__device__ float g_qT[BB*DD*NN];   // per batch: [d][n]
__device__ float g_kT[BB*DD*NN];   // per batch: [d][n]
__device__ float g_v [BB*NN*DD];   // row-major [n][d]
__device__ float g_rel[MAXDIST+1]; // 0.125 * log2(e) * sigmoid(...)

// ============================================================
// Kernel 1: xp = x@Wp+bp ; q,k,v = xp@W{q,k,v}+b  (tf32 mma)
// 64-row tiles, 128 CTAs, 512 threads (4 rb x 4 wc warps).
// ============================================================
#define XS_OFF  0        /* 64x260  = 16640 */
#define WP_OFF  16640    /* 256x72  = 18432 */
#define WT_OFF  35072    /* 3x64x72 = 13824 */
#define XP_OFF  48896    /* 64x68   = 4352  */
#define K1_FLOATS 53248
#define K1_BYTES  (K1_FLOATS*4)

__global__ __launch_bounds__(512) void qkv_kernel(
    const float* __restrict__ x,
    const float* __restrict__ Wp, const float* __restrict__ bp,
    const float* __restrict__ Wq, const float* __restrict__ bq,
    const float* __restrict__ Wk, const float* __restrict__ bk,
    const float* __restrict__ Wv, const float* __restrict__ bv,
    const float* __restrict__ Eemb, const float* __restrict__ Wr1,
    const float* __restrict__ br1,  const float* __restrict__ Wr2) {
    extern __shared__ float sk[];
    float* XS = sk + XS_OFF;
    float* WP = sk + WP_OFF;
    float* WT = sk + WT_OFF;
    float* XP = sk + XP_OFF;

    const int tid = threadIdx.x;
    const int wp = tid >> 5, lane = tid & 31;
    const int g = lane >> 2, q = lane & 3;
    const int rb = wp >> 2, wc = wp & 3;
    const int r0 = rb*16 + g, r1 = r0 + 8;
    const int row0 = blockIdx.x * 64;
    const int b = row0 >> 9;
    const int n0 = row0 & 511;

    const unsigned sb = (unsigned)__cvta_generic_to_shared(sk);

    // ---- issue x tile (grp1), Wp (grp2), Wq/Wk/Wv (grp3) ----
#pragma unroll
    for (int j = 0; j < 8; j++) {
        int idx = tid + j*512;
        int row = idx >> 6, f = idx & 63;
        cpa16(sb + (unsigned)((XS_OFF + row*260 + f*4)*4), &x[(row0 + row)*DIN + f*4]);
    }
    CP_COMMIT();
#pragma unroll
    for (int j = 0; j < 8; j++) {
        int idx = tid + j*512;
        int row = idx >> 4, f = idx & 15;
        cpa16(sb + (unsigned)((WP_OFF + row*72 + f*4)*4), &Wp[row*DD + f*4]);
    }
    CP_COMMIT();
#pragma unroll
    for (int j = 0; j < 6; j++) {
        int idx = tid + j*512;
        int t = idx >> 10, rem = idx & 1023;
        int row = rem >> 4, f = rem & 15;
        const float* src = (t == 0) ? Wq : (t == 1) ? Wk : Wv;
        cpa16(sb + (unsigned)((WT_OFF + t*4608 + row*72 + f*4)*4), &src[row*DD + f*4]);
    }
    CP_COMMIT();

    // ---- rel table (block 0, overlapped with loads) ----
    if (blockIdx.x == 0 && tid <= MAXDIST) {
        float e[EE];
#pragma unroll
        for (int c = 0; c < EE; c++) e[c] = Eemb[tid*EE + c];
        float w = 0.f;
#pragma unroll
        for (int j = 0; j < 16; j++) {
            float h = br1[j];
#pragma unroll
            for (int c = 0; c < EE; c++) h = fmaf(e[c], Wr1[c*16 + j], h);
            h = fmaxf(h, 0.f);
            w = fmaf(h, Wr2[j], w);
        }
        g_rel[tid] = 0.18033688011112042f / (1.f + __expf(-w));
    }

    CP_WAIT1(); __syncthreads();          // x + Wp ready

    // ---- Phase A: xp = x @ Wp  (M=64, N=64, K=256) ----
    float acc[2][4];
#pragma unroll
    for (int cb = 0; cb < 2; cb++) {
        acc[cb][0] = 0.f; acc[cb][1] = 0.f; acc[cb][2] = 0.f; acc[cb][3] = 0.f;
    }
#pragma unroll 4
    for (int ks = 0; ks < 32; ks++) {
        unsigned a0 = cvt_tf32(XS[r0*260 + ks*8 + q]);
        unsigned a1 = cvt_tf32(XS[r1*260 + ks*8 + q]);
        unsigned a2 = cvt_tf32(XS[r0*260 + ks*8 + q + 4]);
        unsigned a3 = cvt_tf32(XS[r1*260 + ks*8 + q + 4]);
#pragma unroll
        for (int cb = 0; cb < 2; cb++) {
            int nc = wc*16 + cb*8;
            unsigned b0 = cvt_tf32(WP[(ks*8 + q)*72 + nc + g]);
            unsigned b1 = cvt_tf32(WP[(ks*8 + q + 4)*72 + nc + g]);
            mma_tf32(acc[cb][0], acc[cb][1], acc[cb][2], acc[cb][3],
                     a0, a1, a2, a3, b0, b1);
        }
    }
    CP_WAIT0();                            // Wqkv arrived (sync below)
    // epilogue: xp + bias -> XP [row][col] stride 68
#pragma unroll
    for (int cb = 0; cb < 2; cb++) {
        int c = wc*16 + cb*8 + 2*q;
        float bp0 = bp[c], bp1 = bp[c + 1];
        XP[r0*68 + c]     = acc[cb][0] + bp0;
        XP[r0*68 + c + 1] = acc[cb][1] + bp1;
        XP[r1*68 + c]     = acc[cb][2] + bp0;
        XP[r1*68 + c + 1] = acc[cb][3] + bp1;
    }
    __syncthreads();                       // XP + Wqkv visible

    // ---- Phase B: q,k,v = xp @ W{q,k,v} + b  (K=64) ----
    const float* bias_t[3] = {bq, bk, bv};
#pragma unroll
    for (int t = 0; t < 3; t++) {
        const float* W = WT + t*4608;
        float o[2][4];
#pragma unroll
        for (int cb = 0; cb < 2; cb++) {
            o[cb][0] = 0.f; o[cb][1] = 0.f; o[cb][2] = 0.f; o[cb][3] = 0.f;
        }
#pragma unroll
        for (int ks = 0; ks < 8; ks++) {
            unsigned a0 = cvt_tf32(XP[r0*68 + ks*8 + q]);
            unsigned a1 = cvt_tf32(XP[r1*68 + ks*8 + q]);
            unsigned a2 = cvt_tf32(XP[r0*68 + ks*8 + q + 4]);
            unsigned a3 = cvt_tf32(XP[r1*68 + ks*8 + q + 4]);
#pragma unroll
            for (int cb = 0; cb < 2; cb++) {
                int nc = wc*16 + cb*8;
                unsigned b0 = cvt_tf32(W[(ks*8 + q)*72 + nc + g]);
                unsigned b1 = cvt_tf32(W[(ks*8 + q + 4)*72 + nc + g]);
                mma_tf32(o[cb][0], o[cb][1], o[cb][2], o[cb][3],
                         a0, a1, a2, a3, b0, b1);
            }
        }
        const float* bs = bias_t[t];
        if (t == 2) {
#pragma unroll
            for (int cb = 0; cb < 2; cb++) {
                int c = wc*16 + cb*8 + 2*q;
                float b0v = bs[c], b1v = bs[c + 1];
                *(float2*)&g_v[(row0 + r0)*DD + c] = make_float2(o[cb][0] + b0v, o[cb][1] + b1v);
                *(float2*)&g_v[(row0 + r1)*DD + c] = make_float2(o[cb][2] + b0v, o[cb][3] + b1v);
            }
        } else {
            float* dst = (t == 0) ? g_qT : g_kT;
#pragma unroll
            for (int cb = 0; cb < 2; cb++) {
                int c = wc*16 + cb*8 + 2*q;
                float b0v = bs[c], b1v = bs[c + 1];
                dst[b*DD*NN + c*NN + n0 + r0]       = o[cb][0] + b0v;
                dst[b*DD*NN + (c + 1)*NN + n0 + r0] = o[cb][1] + b1v;
                dst[b*DD*NN + c*NN + n0 + r1]       = o[cb][2] + b0v;
                dst[b*DD*NN + (c + 1)*NN + n0 + r1] = o[cb][3] + b1v;
            }
        }
    }
}

// ============================================================
// Kernel 2: tf32 mma.sync QK + PV, cp.async pipeline, FFMA2 FFN.
// 64-row query tiles, 128 CTAs, 512 threads.  (unchanged R10)
// ============================================================
#define S_OFF    0       /* 64x260 = 16640 : exp scores / h1T+ws */
#define KB_OFF   16640   /* 64x264 = 16896 : kT chunk / aoT+w1 / w2 */
#define VA_OFF   33536   /* 128x72 = 9216 */
#define VB2_OFF  42752   /* 128x72 = 9216 */
#define QT_OFF   51968   /* 64x72  = 4608 : qT(tf32) / hnT */
#define REL_OFF  56576
#define RK_OFF   56640
#define WS_OFF   57152   /* 256 */
#define INV_OFF  57408   /* 64 */
#define SMEM_FLOATS 57472
#define SMEM_BYTES  (SMEM_FLOATS*4)

__device__ __forceinline__ void qk_chunk(
    float* S, const unsigned* qTb, const float* KB, const float* rel, const int* rk,
    int k0, int wc, int q, int g, int r0, int r1, int ri0, int ri1,
    float& rs0, float& rs1) {
    float acc[8][4];
#pragma unroll
    for (int cb = 0; cb < 8; cb++) {
        acc[cb][0] = 0.f; acc[cb][1] = 0.f; acc[cb][2] = 0.f; acc[cb][3] = 0.f;
    }
#pragma unroll
    for (int ks = 0; ks < 8; ks++) {
        unsigned a0 = qTb[(ks*8 + q)*72 + r0];
        unsigned a1 = qTb[(ks*8 + q)*72 + r1];
        unsigned a2 = qTb[(ks*8 + q + 4)*72 + r0];
        unsigned a3 = qTb[(ks*8 + q + 4)*72 + r1];
#pragma unroll
        for (int cb = 0; cb < 8; cb++) {
            int key0 = wc*64 + cb*8;
            unsigned b0 = cvt_tf32(KB[(ks*8 + q)*264 + key0 + g]);
            unsigned b1 = cvt_tf32(KB[(ks*8 + q + 4)*264 + key0 + g]);
            mma_tf32(acc[cb][0], acc[cb][1], acc[cb][2], acc[cb][3],
                     a0, a1, a2, a3, b0, b1);
        }
    }
#pragma unroll
    for (int cb = 0; cb < 8; cb++) {
        int kloc = wc*64 + cb*8 + 2*q;
        int ka = rk[k0 + kloc], kb = rk[k0 + kloc + 1];
        int d00 = ri0 - ka; d00 = d00 < 0 ? -d00 : d00; if (d00 > MAXDIST) d00 = MAXDIST;
        int d01 = ri0 - kb; d01 = d01 < 0 ? -d01 : d01; if (d01 > MAXDIST) d01 = MAXDIST;
        int d10 = ri1 - ka; d10 = d10 < 0 ? -d10 : d10; if (d10 > MAXDIST) d10 = MAXDIST;
        int d11 = ri1 - kb; d11 = d11 < 0 ? -d11 : d11; if (d11 > MAXDIST) d11 = MAXDIST;
        float f00 = __uint_as_float(cvt_tf32(ex2(acc[cb][0] * rel[d00])));
        float f01 = __uint_as_float(cvt_tf32(ex2(acc[cb][1] * rel[d01])));
        float f10 = __uint_as_float(cvt_tf32(ex2(acc[cb][2] * rel[d10])));
        float f11 = __uint_as_float(cvt_tf32(ex2(acc[cb][3] * rel[d11])));
        *(float2*)&S[r0*260 + kloc] = make_float2(f00, f01);
        *(float2*)&S[r1*260 + kloc] = make_float2(f10, f11);
        rs0 += f00 + f01;
        rs1 += f10 + f11;
    }
}

__device__ __forceinline__ void pv_half(
    const unsigned* Sb, const float* VB,
    int h, int wc, int q, int g, int r0, int r1, float (&accpv)[2][4]) {
#pragma unroll
    for (int ks = 0; ks < 16; ks++) {
        int kk = h*128 + ks*8;
        unsigned a0 = Sb[r0*260 + kk + q];
        unsigned a1 = Sb[r1*260 + kk + q];
        unsigned a2 = Sb[r0*260 + kk + q + 4];
        unsigned a3 = Sb[r1*260 + kk + q + 4];
#pragma unroll
        for (int cb = 0; cb < 2; cb++) {
            int d0 = wc*16 + cb*8;
            unsigned b0 = cvt_tf32(VB[(ks*8 + q)*72 + d0 + g]);
            unsigned b1 = cvt_tf32(VB[(ks*8 + q + 4)*72 + d0 + g]);
            mma_tf32(accpv[cb][0], accpv[cb][1], accpv[cb][2], accpv[cb][3],
                     a0, a1, a2, a3, b0, b1);
        }
    }
}

__global__ __launch_bounds__(512) void attn_kernel(
    const int* __restrict__ ranks,
    const float* __restrict__ Wf1, const float* __restrict__ bf1,
    const float* __restrict__ Wf2, const float* __restrict__ bf2,
    const float* __restrict__ ln_g, const float* __restrict__ ln_b,
    const float* __restrict__ Ws1, const float* __restrict__ bs1,
    const float* __restrict__ Ws2, const float* __restrict__ bs2,
    float* __restrict__ out) {
    extern __shared__ float sm[];
    float* S    = sm + S_OFF;
    float* KB   = sm + KB_OFF;
    float* VAf  = sm + VA_OFF;
    float* VBf  = sm + VB2_OFF;
    float* qTf  = sm + QT_OFF;
    float* rel  = sm + REL_OFF;
    int*   rk   = (int*)(sm + RK_OFF);
    float* wsum = sm + WS_OFF;
    float* invs = sm + INV_OFF;
    const unsigned* qTb = (const unsigned*)qTf;
    const unsigned* Sb  = (const unsigned*)S;

    const int tid = threadIdx.x;
    const int b = blockIdx.y;
    const int q0 = blockIdx.x * 64;
    const int base = b * NN;
    const int bT = b * DD * NN;
    const int wp = tid >> 5, lane = tid & 31;
    const int g = lane >> 2, q = lane & 3;
    const int rb = wp >> 2, wc = wp & 3;
    const int r0 = rb*16 + g, r1 = r0 + 8;

    const unsigned sb = (unsigned)__cvta_generic_to_shared(sm);
    const unsigned kbA = sb + KB_OFF*4;
    const unsigned vaA = sb + VA_OFF*4;
    const unsigned vbA = sb + VB2_OFF*4;

#pragma unroll
    for (int j = 0; j < 8; j++) {
        int idx = tid + j*512;
        int d = idx >> 6, f = idx & 63;
        cpa16(kbA + (unsigned)((d*264 + f*4)*4), &g_kT[bT + d*NN + f*4]);
    }
    CP_COMMIT();                                          // grp1: K0
#pragma unroll
    for (int j = 0; j < 4; j++) {
        int idx = tid + j*512;
        int key = idx >> 4, f = idx & 15;
        cpa16(vaA + (unsigned)((key*72 + f*4)*4), &g_v[(base + key)*DD + f*4]);
    }
    CP_COMMIT();                                          // grp2: Va
#pragma unroll
    for (int j = 0; j < 4; j++) {
        int idx = tid + j*512;
        int key = idx >> 4, f = idx & 15;
        cpa16(vbA + (unsigned)((key*72 + f*4)*4), &g_v[(base + 128 + key)*DD + f*4]);
    }
    CP_COMMIT();                                          // grp3: Vb

    if (tid <= MAXDIST) rel[tid] = g_rel[tid];
    for (int m = tid; m < NN; m += 512) rk[m] = ranks[base + m];
#pragma unroll
    for (int j = 0; j < 2; j++) {
        int idx = tid + j*512;
        int d = idx >> 4, f = idx & 15;
        float4 v = *(const float4*)&g_qT[bT + d*NN + q0 + f*4];
        unsigned* dst = (unsigned*)&qTf[d*72 + f*4];
        dst[0] = cvt_tf32(v.x); dst[1] = cvt_tf32(v.y);
        dst[2] = cvt_tf32(v.z); dst[3] = cvt_tf32(v.w);
    }

    float rs0 = 0.f, rs1 = 0.f;
    float accpv[2][4];
#pragma unroll
    for (int c = 0; c < 2; c++) {
        accpv[c][0] = 0.f; accpv[c][1] = 0.f; accpv[c][2] = 0.f; accpv[c][3] = 0.f;
    }

    CP_WAIT2(); __syncthreads();                           // K0 ready
    const int ri0 = rk[q0 + r0], ri1 = rk[q0 + r1];

    qk_chunk(S, qTb, KB, rel, rk, 0, wc, q, g, r0, r1, ri0, ri1, rs0, rs1);
    __syncthreads();                                       // S0 ready, KB free

#pragma unroll
    for (int j = 0; j < 8; j++) {
        int idx = tid + j*512;
        int d = idx >> 6, f = idx & 63;
        cpa16(kbA + (unsigned)((d*264 + f*4)*4), &g_kT[bT + d*NN + 256 + f*4]);
    }
    CP_COMMIT();                                          // grp4: K1

    CP_WAIT2(); __syncthreads();                           // Va ready
    pv_half(Sb, VAf, 0, wc, q, g, r0, r1, accpv);          // keys 0-127
    CP_WAIT1(); __syncthreads();                           // Vb ready, VAf free
#pragma unroll
    for (int j = 0; j < 4; j++) {
        int idx = tid + j*512;
        int key = idx >> 4, f = idx & 15;
        cpa16(vaA + (unsigned)((key*72 + f*4)*4), &g_v[(base + 256 + key)*DD + f*4]);
    }
    CP_COMMIT();                                          // grp5: Va2
    pv_half(Sb, VBf, 1, wc, q, g, r0, r1, accpv);          // keys 128-255
    __syncthreads();                                       // VBf free, S free
#pragma unroll
    for (int j = 0; j < 4; j++) {
        int idx = tid + j*512;
        int key = idx >> 4, f = idx & 15;
        cpa16(vbA + (unsigned)((key*72 + f*4)*4), &g_v[(base + 384 + key)*DD + f*4]);
    }
    CP_COMMIT();                                          // grp6: Vb2
    CP_WAIT2(); __syncthreads();                           // K1 ready

    qk_chunk(S, qTb, KB, rel, rk, 256, wc, q, g, r0, r1, ri0, ri1, rs0, rs1);
    {
        rs0 += __shfl_xor_sync(0xffffffffu, rs0, 1);
        rs0 += __shfl_xor_sync(0xffffffffu, rs0, 2);
        rs1 += __shfl_xor_sync(0xffffffffu, rs1, 1);
        rs1 += __shfl_xor_sync(0xffffffffu, rs1, 2);
        if (q == 0) {
            wsum[wc*64 + r0] = rs0;
            wsum[wc*64 + r1] = rs1;
        }
    }
    __syncthreads();                                       // S1 + wsum ready
    if (tid < 64)
        invs[tid] = 1.f / (wsum[tid] + wsum[64 + tid] + wsum[128 + tid] + wsum[192 + tid]);
#pragma unroll
    for (int j = 0; j < 4; j++) {
        int f = tid + j*512;
        cpa16(kbA + (unsigned)((4352 + f*4)*4), &Wf1[f*4]);
    }
    CP_COMMIT();                                          // grp7: w1

    CP_WAIT2(); __syncthreads();                           // Va2 ready (+invs visible)
    pv_half(Sb, VAf, 0, wc, q, g, r0, r1, accpv);          // keys 256-383
    CP_WAIT1(); __syncthreads();                           // Vb2 ready
    pv_half(Sb, VBf, 1, wc, q, g, r0, r1, accpv);          // keys 384-511
    CP_WAIT0();
    __syncthreads();                                       // w1 ready, all PV done

    {
        float iv0 = invs[r0], iv1 = invs[r1];
#pragma unroll
        for (int cb = 0; cb < 2; cb++) {
            int dc = wc*16 + cb*8 + 2*q;
            KB[dc*68 + r0]       = accpv[cb][0] * iv0;
            KB[(dc + 1)*68 + r0] = accpv[cb][1] * iv0;
            KB[dc*68 + r1]       = accpv[cb][2] * iv1;
            KB[(dc + 1)*68 + r1] = accpv[cb][3] * iv1;
        }
    }
    __syncthreads();

    // ---- FFN1: h1 = relu(ao@Wf1+bf1) (64x128), FFMA2 ----
    {
        const float* w1 = KB + 4352;
        const int ty4 = tid >> 5, tx4 = tid & 31;
        ull acc2[2][4];
#pragma unroll
        for (int p = 0; p < 2; p++)
#pragma unroll
            for (int c = 0; c < 4; c++) acc2[p][c] = 0ULL;
#pragma unroll 4
        for (int kk = 0; kk < 64; kk++) {
            ulonglong2 a = *(const ulonglong2*)&KB[kk*68 + ty4*4];
            float4 bw = *(const float4*)&w1[kk*128 + tx4*4];
            ull b0 = dup2(bw.x), b1 = dup2(bw.y), b2 = dup2(bw.z), b3 = dup2(bw.w);
            fma2(acc2[0][0], a.x, b0); fma2(acc2[0][1], a.x, b1);
            fma2(acc2[0][2], a.x, b2); fma2(acc2[0][3], a.x, b3);
            fma2(acc2[1][0], a.y, b0); fma2(acc2[1][1], a.y, b1);
            fma2(acc2[1][2], a.y, b2); fma2(acc2[1][3], a.y, b3);
        }
        __syncthreads();
#pragma unroll
        for (int c = 0; c < 4; c++) {
            float bias = bf1[tx4*4 + c];
            float2 u0 = unpk(acc2[0][c]), u1 = unpk(acc2[1][c]);
            float4 v4 = {fmaxf(u0.x + bias, 0.f), fmaxf(u0.y + bias, 0.f),
                         fmaxf(u1.x + bias, 0.f), fmaxf(u1.y + bias, 0.f)};
            *(float4*)&S[(tx4*4 + c)*68 + ty4*4] = v4;   // h1T
        }
#pragma unroll
        for (int j = 0; j < 4; j++) {
            int f = tid + j*512;
            *(float4*)&KB[f*4] = *(const float4*)&Wf2[f*4];   // w2
        }
        *(float4*)&S[8960 + tid*4] = *(const float4*)&Ws1[tid*4];   // ws1
        if (tid < 8) *(float4*)&S[11008 + tid*4] = *(const float4*)&Ws2[tid*4];
    }
    __syncthreads();

    // ---- FFN2 + LayerNorm -> hnT ----
    {
        const int ty4 = tid >> 5, tx4 = tid & 31;
        ull acc2[2][2];
        acc2[0][0] = acc2[0][1] = acc2[1][0] = acc2[1][1] = 0ULL;
#pragma unroll 4
        for (int kk = 0; kk < 128; kk++) {
            ulonglong2 a = *(const ulonglong2*)&S[kk*68 + ty4*4];
            float2 bw = *(const float2*)&KB[kk*64 + tx4*2];
            ull b0 = dup2(bw.x), b1 = dup2(bw.y);
            fma2(acc2[0][0], a.x, b0); fma2(acc2[0][1], a.x, b1);
            fma2(acc2[1][0], a.y, b0); fma2(acc2[1][1], a.y, b1);
        }
        float h2[4][2];
        {
            float2 u00 = unpk(acc2[0][0]), u01 = unpk(acc2[0][1]);
            float2 u10 = unpk(acc2[1][0]), u11 = unpk(acc2[1][1]);
            h2[0][0] = u00.x; h2[0][1] = u01.x;
            h2[1][0] = u00.y; h2[1][1] = u01.y;
            h2[2][0] = u10.x; h2[2][1] = u11.x;
            h2[3][0] = u10.y; h2[3][1] = u11.y;
        }
        float b0 = bf2[tx4*2], b1 = bf2[tx4*2 + 1];
        float g0v = ln_g[tx4*2], g1v = ln_g[tx4*2 + 1];
        float be0 = ln_b[tx4*2], be1 = ln_b[tx4*2 + 1];
#pragma unroll
        for (int r = 0; r < 4; r++) {
            float e0 = h2[r][0] + b0, e1 = h2[r][1] + b1;
            float s  = e0 + e1;
            float s2 = e0*e0 + e1*e1;
#pragma unroll
            for (int o = 16; o >= 1; o >>= 1) {
                s  += __shfl_xor_sync(0xffffffffu, s,  o);
                s2 += __shfl_xor_sync(0xffffffffu, s2, o);
            }
            float mu = s * (1.f/64.f);
            float var = s2 * (1.f/64.f) - mu*mu;
            float inv = rsqrtf(var + 1e-5f);
            qTf[(tx4*2 + 0)*68 + ty4*4 + r] = (e0 - mu)*inv*g0v + be0;   // hnT
            qTf[(tx4*2 + 1)*68 + ty4*4 + r] = (e1 - mu)*inv*g1v + be1;
        }
    }
    __syncthreads();

    // ---- head (threads 0..255) ----
    if (tid < 256) {
        const int ty4 = tid >> 4, tx4 = tid & 15;
        float s1[4][2];
#pragma unroll
        for (int r = 0; r < 4; r++) { s1[r][0] = 0.f; s1[r][1] = 0.f; }
#pragma unroll 4
        for (int kk = 0; kk < 64; kk++) {
            float4 a = *(const float4*)&qTf[kk*68 + ty4*4];
            float w0 = S[8960 + kk*32 + tx4*2], w1b = S[8960 + kk*32 + tx4*2 + 1];
            s1[0][0] = fmaf(a.x, w0, s1[0][0]); s1[0][1] = fmaf(a.x, w1b, s1[0][1]);
            s1[1][0] = fmaf(a.y, w0, s1[1][0]); s1[1][1] = fmaf(a.y, w1b, s1[1][1]);
            s1[2][0] = fmaf(a.z, w0, s1[2][0]); s1[2][1] = fmaf(a.z, w1b, s1[2][1]);
            s1[3][0] = fmaf(a.w, w0, s1[3][0]); s1[3][1] = fmaf(a.w, w1b, s1[3][1]);
        }
        float w2a = S[11008 + tx4*2], w2b = S[11008 + tx4*2 + 1];
        float ba = bs1[tx4*2], bb = bs1[tx4*2 + 1];
        float bs2v = bs2[0];
#pragma unroll
        for (int r = 0; r < 4; r++) {
            float pa = fmaxf(s1[r][0] + ba, 0.f);
            float pb = fmaxf(s1[r][1] + bb, 0.f);
            float p = pa*w2a + pb*w2b;
#pragma unroll
            for (int o = 8; o >= 1; o >>= 1) p += __shfl_xor_sync(0xffffffffu, p, o, 16);
            if (tx4 == 0) {
                float z = p + bs2v;
                out[base + q0 + ty4*4 + r] = 1.f / (1.f + __expf(-z));
            }
        }
    }
}

// ============================================================
extern "C" void kernel_launch(void* const* d_in, const int* in_sizes, int n_in,
                              void* d_out, int out_size) {
    const float* x     = (const float*)d_in[0];
    const int*   ranks = (const int*)  d_in[1];
    const float* Wp    = (const float*)d_in[2];
    const float* bp    = (const float*)d_in[3];
    const float* Wq    = (const float*)d_in[4];
    const float* bq    = (const float*)d_in[5];
    const float* Wk    = (const float*)d_in[6];
    const float* bk    = (const float*)d_in[7];
    const float* Wv    = (const float*)d_in[8];
    const float* bv    = (const float*)d_in[9];
    const float* Eemb  = (const float*)d_in[10];
    const float* Wr1   = (const float*)d_in[11];
    const float* br1   = (const float*)d_in[12];
    const float* Wr2   = (const float*)d_in[13];
    const float* Wf1   = (const float*)d_in[14];
    const float* bf1   = (const float*)d_in[15];
    const float* Wf2   = (const float*)d_in[16];
    const float* bf2   = (const float*)d_in[17];
    const float* ln_g  = (const float*)d_in[18];
    const float* ln_b  = (const float*)d_in[19];
    const float* Ws1   = (const float*)d_in[20];
    const float* bs1   = (const float*)d_in[21];
    const float* Ws2   = (const float*)d_in[22];
    const float* bs2   = (const float*)d_in[23];
    float* out = (float*)d_out;

    cudaFuncSetAttribute(qkv_kernel, cudaFuncAttributeMaxDynamicSharedMemorySize, K1_BYTES);
    cudaFuncSetAttribute(attn_kernel, cudaFuncAttributeMaxDynamicSharedMemorySize, SMEM_BYTES);

    qkv_kernel<<<BB*NN/64, 512, K1_BYTES>>>(x, Wp, bp, Wq, bq, Wk, bk, Wv, bv,
                                            Eemb, Wr1, br1, Wr2);
    dim3 grid(NN/64, BB);
    attn_kernel<<<grid, 512, SMEM_BYTES>>>(ranks, Wf1, bf1, Wf2, bf2,
                                           ln_g, ln_b, Ws1, bs1, Ws2, bs2, out);
}

// round 12
// speedup vs baseline: 2.0484x; 1.0608x over previous
#include <cuda_runtime.h>

#define BB   16
#define NN   512
#define DIN  256
#define DD   64
#define EE   32
#define MAXDIST 50

typedef unsigned long long ull;

__device__ __forceinline__ float ex2(float x) {
    float r;
    asm("ex2.approx.f32 %0, %1;" : "=f"(r) : "f"(x));
    return r;
}
__device__ __forceinline__ unsigned cvt_tf32(float x) {
    unsigned r;
    asm("cvt.rna.tf32.f32 %0, %1;" : "=r"(r) : "f"(x));
    return r;
}
__device__ __forceinline__ void mma_tf32(float& c0, float& c1, float& c2, float& c3,
                                         unsigned a0, unsigned a1, unsigned a2, unsigned a3,
                                         unsigned b0, unsigned b1) {
    asm("mma.sync.aligned.m16n8k8.row.col.f32.tf32.tf32.f32 "
        "{%0,%1,%2,%3}, {%4,%5,%6,%7}, {%8,%9}, {%0,%1,%2,%3};"
        : "+f"(c0), "+f"(c1), "+f"(c2), "+f"(c3)
        : "r"(a0), "r"(a1), "r"(a2), "r"(a3), "r"(b0), "r"(b1));
}
__device__ __forceinline__ void cpa16(unsigned dst, const float* src) {
    asm volatile("cp.async.cg.shared.global [%0], [%1], 16;" :: "r"(dst), "l"(src));
}
#define CP_COMMIT() asm volatile("cp.async.commit_group;" ::: "memory")
#define CP_WAIT2()  asm volatile("cp.async.wait_group 2;" ::: "memory")
#define CP_WAIT1()  asm volatile("cp.async.wait_group 1;" ::: "memory")
#define CP_WAIT0()  asm volatile("cp.async.wait_group 0;" ::: "memory")

__device__ float g_qT[BB*DD*NN];   // per batch: [d][n], tf32-rounded
__device__ float g_kT[BB*DD*NN];   // per batch: [d][n], tf32-rounded
__device__ float g_v [BB*NN*DD];   // row-major [n][d], tf32-rounded
__device__ float g_rel[MAXDIST+1]; // 0.125 * log2(e) * sigmoid(...)

// ============================================================
// Kernel 1: xp = x@Wp+bp ; q,k,v = xp@W{q,k,v}+b  (tf32 mma)
// Outputs pre-rounded to tf32 (consumed only by tf32 mma).
// ============================================================
#define XS_OFF  0        /* 64x260  = 16640 */
#define WP_OFF  16640    /* 256x72  = 18432 */
#define WT_OFF  35072    /* 3x64x72 = 13824 */
#define XP_OFF  48896    /* 64x68   = 4352  */
#define K1_FLOATS 53248
#define K1_BYTES  (K1_FLOATS*4)

__global__ __launch_bounds__(512) void qkv_kernel(
    const float* __restrict__ x,
    const float* __restrict__ Wp, const float* __restrict__ bp,
    const float* __restrict__ Wq, const float* __restrict__ bq,
    const float* __restrict__ Wk, const float* __restrict__ bk,
    const float* __restrict__ Wv, const float* __restrict__ bv,
    const float* __restrict__ Eemb, const float* __restrict__ Wr1,
    const float* __restrict__ br1,  const float* __restrict__ Wr2) {
    extern __shared__ float sk[];
    float* XS = sk + XS_OFF;
    float* WP = sk + WP_OFF;
    float* WT = sk + WT_OFF;
    float* XP = sk + XP_OFF;

    const int tid = threadIdx.x;
    const int wp = tid >> 5, lane = tid & 31;
    const int g = lane >> 2, q = lane & 3;
    const int rb = wp >> 2, wc = wp & 3;
    const int r0 = rb*16 + g, r1 = r0 + 8;
    const int row0 = blockIdx.x * 64;
    const int b = row0 >> 9;
    const int n0 = row0 & 511;

    const unsigned sb = (unsigned)__cvta_generic_to_shared(sk);

#pragma unroll
    for (int j = 0; j < 8; j++) {
        int idx = tid + j*512;
        int row = idx >> 6, f = idx & 63;
        cpa16(sb + (unsigned)((XS_OFF + row*260 + f*4)*4), &x[(row0 + row)*DIN + f*4]);
    }
    CP_COMMIT();
#pragma unroll
    for (int j = 0; j < 8; j++) {
        int idx = tid + j*512;
        int row = idx >> 4, f = idx & 15;
        cpa16(sb + (unsigned)((WP_OFF + row*72 + f*4)*4), &Wp[row*DD + f*4]);
    }
    CP_COMMIT();
#pragma unroll
    for (int j = 0; j < 6; j++) {
        int idx = tid + j*512;
        int t = idx >> 10, rem = idx & 1023;
        int row = rem >> 4, f = rem & 15;
        const float* src = (t == 0) ? Wq : (t == 1) ? Wk : Wv;
        cpa16(sb + (unsigned)((WT_OFF + t*4608 + row*72 + f*4)*4), &src[row*DD + f*4]);
    }
    CP_COMMIT();

    if (blockIdx.x == 0 && tid <= MAXDIST) {
        float e[EE];
#pragma unroll
        for (int c = 0; c < EE; c++) e[c] = Eemb[tid*EE + c];
        float w = 0.f;
#pragma unroll
        for (int j = 0; j < 16; j++) {
            float h = br1[j];
#pragma unroll
            for (int c = 0; c < EE; c++) h = fmaf(e[c], Wr1[c*16 + j], h);
            h = fmaxf(h, 0.f);
            w = fmaf(h, Wr2[j], w);
        }
        g_rel[tid] = 0.18033688011112042f / (1.f + __expf(-w));
    }

    CP_WAIT1(); __syncthreads();          // x + Wp ready

    // ---- Phase A: xp = x @ Wp  (M=64, N=64, K=256) ----
    float acc[2][4];
#pragma unroll
    for (int cb = 0; cb < 2; cb++) {
        acc[cb][0] = 0.f; acc[cb][1] = 0.f; acc[cb][2] = 0.f; acc[cb][3] = 0.f;
    }
#pragma unroll 4
    for (int ks = 0; ks < 32; ks++) {
        unsigned a0 = cvt_tf32(XS[r0*260 + ks*8 + q]);
        unsigned a1 = cvt_tf32(XS[r1*260 + ks*8 + q]);
        unsigned a2 = cvt_tf32(XS[r0*260 + ks*8 + q + 4]);
        unsigned a3 = cvt_tf32(XS[r1*260 + ks*8 + q + 4]);
#pragma unroll
        for (int cb = 0; cb < 2; cb++) {
            int nc = wc*16 + cb*8;
            unsigned b0 = cvt_tf32(WP[(ks*8 + q)*72 + nc + g]);
            unsigned b1 = cvt_tf32(WP[(ks*8 + q + 4)*72 + nc + g]);
            mma_tf32(acc[cb][0], acc[cb][1], acc[cb][2], acc[cb][3],
                     a0, a1, a2, a3, b0, b1);
        }
    }
    CP_WAIT0();
#pragma unroll
    for (int cb = 0; cb < 2; cb++) {
        int c = wc*16 + cb*8 + 2*q;
        float bp0 = bp[c], bp1 = bp[c + 1];
        XP[r0*68 + c]     = acc[cb][0] + bp0;
        XP[r0*68 + c + 1] = acc[cb][1] + bp1;
        XP[r1*68 + c]     = acc[cb][2] + bp0;
        XP[r1*68 + c + 1] = acc[cb][3] + bp1;
    }
    __syncthreads();

    // ---- Phase B: q,k,v = xp @ W{q,k,v} + b  (K=64), tf32-rounded out ----
    const float* bias_t[3] = {bq, bk, bv};
#pragma unroll
    for (int t = 0; t < 3; t++) {
        const float* W = WT + t*4608;
        float o[2][4];
#pragma unroll
        for (int cb = 0; cb < 2; cb++) {
            o[cb][0] = 0.f; o[cb][1] = 0.f; o[cb][2] = 0.f; o[cb][3] = 0.f;
        }
#pragma unroll
        for (int ks = 0; ks < 8; ks++) {
            unsigned a0 = cvt_tf32(XP[r0*68 + ks*8 + q]);
            unsigned a1 = cvt_tf32(XP[r1*68 + ks*8 + q]);
            unsigned a2 = cvt_tf32(XP[r0*68 + ks*8 + q + 4]);
            unsigned a3 = cvt_tf32(XP[r1*68 + ks*8 + q + 4]);
#pragma unroll
            for (int cb = 0; cb < 2; cb++) {
                int nc = wc*16 + cb*8;
                unsigned b0 = cvt_tf32(W[(ks*8 + q)*72 + nc + g]);
                unsigned b1 = cvt_tf32(W[(ks*8 + q + 4)*72 + nc + g]);
                mma_tf32(o[cb][0], o[cb][1], o[cb][2], o[cb][3],
                         a0, a1, a2, a3, b0, b1);
            }
        }
        const float* bs = bias_t[t];
        if (t == 2) {
#pragma unroll
            for (int cb = 0; cb < 2; cb++) {
                int c = wc*16 + cb*8 + 2*q;
                float v0 = __uint_as_float(cvt_tf32(o[cb][0] + bs[c]));
                float v1 = __uint_as_float(cvt_tf32(o[cb][1] + bs[c + 1]));
                float v2 = __uint_as_float(cvt_tf32(o[cb][2] + bs[c]));
                float v3 = __uint_as_float(cvt_tf32(o[cb][3] + bs[c + 1]));
                *(float2*)&g_v[(row0 + r0)*DD + c] = make_float2(v0, v1);
                *(float2*)&g_v[(row0 + r1)*DD + c] = make_float2(v2, v3);
            }
        } else {
            float* dst = (t == 0) ? g_qT : g_kT;
#pragma unroll
            for (int cb = 0; cb < 2; cb++) {
                int c = wc*16 + cb*8 + 2*q;
                dst[b*DD*NN + c*NN + n0 + r0]       = __uint_as_float(cvt_tf32(o[cb][0] + bs[c]));
                dst[b*DD*NN + (c + 1)*NN + n0 + r0] = __uint_as_float(cvt_tf32(o[cb][1] + bs[c + 1]));
                dst[b*DD*NN + c*NN + n0 + r1]       = __uint_as_float(cvt_tf32(o[cb][2] + bs[c]));
                dst[b*DD*NN + (c + 1)*NN + n0 + r1] = __uint_as_float(cvt_tf32(o[cb][3] + bs[c + 1]));
            }
        }
    }
}

// ============================================================
// Kernel 2: full tf32 mma (QK, PV, FFN1, FFN2), cp.async pipeline.
// ============================================================
#define S_OFF    0       /* 16640 : exp scores / h1T(stride68)+ws1+ws2+LN partials */
#define KB_OFF   16640   /* 16896 : kT chunk [64][264] / w1 [128][132] / w2 [128][68] */
#define VA_OFF   33536   /* 128x72 = 9216 */
#define VB2_OFF  42752   /* 128x72 = 9216 */
#define QT_OFF   51968   /* 4608 : qT(tf32, s72) / aoT(tf32, s68) / hnT(f32, s68) */
#define REL_OFF  56576
#define RK_OFF   56640
#define WS_OFF   57152   /* 256 */
#define INV_OFF  57408   /* 64 */
#define SMEM_FLOATS 57472
#define SMEM_BYTES  (SMEM_FLOATS*4)

__device__ __forceinline__ void qk_chunk(
    float* S, const unsigned* qTb, const unsigned* KBu, const float* rel, const int* rk,
    int k0, int wc, int q, int g, int r0, int r1, int ri0, int ri1,
    float& rs0, float& rs1) {
    float acc[8][4];
#pragma unroll
    for (int cb = 0; cb < 8; cb++) {
        acc[cb][0] = 0.f; acc[cb][1] = 0.f; acc[cb][2] = 0.f; acc[cb][3] = 0.f;
    }
#pragma unroll
    for (int ks = 0; ks < 8; ks++) {
        unsigned a0 = qTb[(ks*8 + q)*72 + r0];
        unsigned a1 = qTb[(ks*8 + q)*72 + r1];
        unsigned a2 = qTb[(ks*8 + q + 4)*72 + r0];
        unsigned a3 = qTb[(ks*8 + q + 4)*72 + r1];
#pragma unroll
        for (int cb = 0; cb < 8; cb++) {
            int key0 = wc*64 + cb*8;
            unsigned b0 = KBu[(ks*8 + q)*264 + key0 + g];
            unsigned b1 = KBu[(ks*8 + q + 4)*264 + key0 + g];
            mma_tf32(acc[cb][0], acc[cb][1], acc[cb][2], acc[cb][3],
                     a0, a1, a2, a3, b0, b1);
        }
    }
#pragma unroll
    for (int cb = 0; cb < 8; cb++) {
        int kloc = wc*64 + cb*8 + 2*q;
        int ka = rk[k0 + kloc], kb = rk[k0 + kloc + 1];
        int d00 = ri0 - ka; d00 = d00 < 0 ? -d00 : d00; if (d00 > MAXDIST) d00 = MAXDIST;
        int d01 = ri0 - kb; d01 = d01 < 0 ? -d01 : d01; if (d01 > MAXDIST) d01 = MAXDIST;
        int d10 = ri1 - ka; d10 = d10 < 0 ? -d10 : d10; if (d10 > MAXDIST) d10 = MAXDIST;
        int d11 = ri1 - kb; d11 = d11 < 0 ? -d11 : d11; if (d11 > MAXDIST) d11 = MAXDIST;
        float f00 = __uint_as_float(cvt_tf32(ex2(acc[cb][0] * rel[d00])));
        float f01 = __uint_as_float(cvt_tf32(ex2(acc[cb][1] * rel[d01])));
        float f10 = __uint_as_float(cvt_tf32(ex2(acc[cb][2] * rel[d10])));
        float f11 = __uint_as_float(cvt_tf32(ex2(acc[cb][3] * rel[d11])));
        *(float2*)&S[r0*260 + kloc] = make_float2(f00, f01);
        *(float2*)&S[r1*260 + kloc] = make_float2(f10, f11);
        rs0 += f00 + f01;
        rs1 += f10 + f11;
    }
}

__device__ __forceinline__ void pv_half(
    const unsigned* Sb, const unsigned* VBu,
    int h, int wc, int q, int g, int r0, int r1, float (&accpv)[2][4]) {
#pragma unroll
    for (int ks = 0; ks < 16; ks++) {
        int kk = h*128 + ks*8;
        unsigned a0 = Sb[r0*260 + kk + q];
        unsigned a1 = Sb[r1*260 + kk + q];
        unsigned a2 = Sb[r0*260 + kk + q + 4];
        unsigned a3 = Sb[r1*260 + kk + q + 4];
#pragma unroll
        for (int cb = 0; cb < 2; cb++) {
            int d0 = wc*16 + cb*8;
            unsigned b0 = VBu[(ks*8 + q)*72 + d0 + g];
            unsigned b1 = VBu[(ks*8 + q + 4)*72 + d0 + g];
            mma_tf32(accpv[cb][0], accpv[cb][1], accpv[cb][2], accpv[cb][3],
                     a0, a1, a2, a3, b0, b1);
        }
    }
}

__global__ __launch_bounds__(512) void attn_kernel(
    const int* __restrict__ ranks,
    const float* __restrict__ Wf1, const float* __restrict__ bf1,
    const float* __restrict__ Wf2, const float* __restrict__ bf2,
    const float* __restrict__ ln_g, const float* __restrict__ ln_b,
    const float* __restrict__ Ws1, const float* __restrict__ bs1,
    const float* __restrict__ Ws2, const float* __restrict__ bs2,
    float* __restrict__ out) {
    extern __shared__ float sm[];
    float* S    = sm + S_OFF;
    float* KB   = sm + KB_OFF;
    float* qTf  = sm + QT_OFF;
    float* rel  = sm + REL_OFF;
    int*   rk   = (int*)(sm + RK_OFF);
    float* wsum = sm + WS_OFF;
    float* invs = sm + INV_OFF;
    float* wsq  = sm + 11264;            // LN sumsq partials (S region, after ws2)
    const unsigned* qTb = (const unsigned*)qTf;
    const unsigned* Sb  = (const unsigned*)S;
    const unsigned* KBu = (const unsigned*)KB;
    const unsigned* VAu = (const unsigned*)(sm + VA_OFF);
    const unsigned* VBu = (const unsigned*)(sm + VB2_OFF);

    const int tid = threadIdx.x;
    const int b = blockIdx.y;
    const int q0 = blockIdx.x * 64;
    const int base = b * NN;
    const int bT = b * DD * NN;
    const int wp = tid >> 5, lane = tid & 31;
    const int g = lane >> 2, q = lane & 3;
    const int rb = wp >> 2, wc = wp & 3;
    const int r0 = rb*16 + g, r1 = r0 + 8;

    const unsigned sb = (unsigned)__cvta_generic_to_shared(sm);
    const unsigned kbA = sb + KB_OFF*4;
    const unsigned vaA = sb + VA_OFF*4;
    const unsigned vbA = sb + VB2_OFF*4;

#pragma unroll
    for (int j = 0; j < 8; j++) {
        int idx = tid + j*512;
        int d = idx >> 6, f = idx & 63;
        cpa16(kbA + (unsigned)((d*264 + f*4)*4), &g_kT[bT + d*NN + f*4]);
    }
    CP_COMMIT();                                          // grp1: K0
#pragma unroll
    for (int j = 0; j < 4; j++) {
        int idx = tid + j*512;
        int key = idx >> 4, f = idx & 15;
        cpa16(vaA + (unsigned)((key*72 + f*4)*4), &g_v[(base + key)*DD + f*4]);
    }
    CP_COMMIT();                                          // grp2: Va
#pragma unroll
    for (int j = 0; j < 4; j++) {
        int idx = tid + j*512;
        int key = idx >> 4, f = idx & 15;
        cpa16(vbA + (unsigned)((key*72 + f*4)*4), &g_v[(base + 128 + key)*DD + f*4]);
    }
    CP_COMMIT();                                          // grp3: Vb

    if (tid <= MAXDIST) rel[tid] = g_rel[tid];
    for (int m = tid; m < NN; m += 512) rk[m] = ranks[base + m];
#pragma unroll
    for (int j = 0; j < 2; j++) {
        int idx = tid + j*512;
        int d = idx >> 4, f = idx & 15;
        *(float4*)&qTf[d*72 + f*4] = *(const float4*)&g_qT[bT + d*NN + q0 + f*4];
    }

    float rs0 = 0.f, rs1 = 0.f;
    float accpv[2][4];
#pragma unroll
    for (int c = 0; c < 2; c++) {
        accpv[c][0] = 0.f; accpv[c][1] = 0.f; accpv[c][2] = 0.f; accpv[c][3] = 0.f;
    }

    CP_WAIT2(); __syncthreads();                           // K0 ready
    const int ri0 = rk[q0 + r0], ri1 = rk[q0 + r1];

    qk_chunk(S, qTb, KBu, rel, rk, 0, wc, q, g, r0, r1, ri0, ri1, rs0, rs1);
    __syncthreads();                                       // S0 ready, KB free

#pragma unroll
    for (int j = 0; j < 8; j++) {
        int idx = tid + j*512;
        int d = idx >> 6, f = idx & 63;
        cpa16(kbA + (unsigned)((d*264 + f*4)*4), &g_kT[bT + d*NN + 256 + f*4]);
    }
    CP_COMMIT();                                          // grp4: K1

    CP_WAIT2(); __syncthreads();                           // Va ready
    pv_half(Sb, VAu, 0, wc, q, g, r0, r1, accpv);          // keys 0-127
    CP_WAIT1(); __syncthreads();                           // Vb ready, VA free
#pragma unroll
    for (int j = 0; j < 4; j++) {
        int idx = tid + j*512;
        int key = idx >> 4, f = idx & 15;
        cpa16(vaA + (unsigned)((key*72 + f*4)*4), &g_v[(base + 256 + key)*DD + f*4]);
    }
    CP_COMMIT();                                          // grp5: Va2
    pv_half(Sb, VBu, 1, wc, q, g, r0, r1, accpv);          // keys 128-255
    __syncthreads();                                       // VB free, S free
#pragma unroll
    for (int j = 0; j < 4; j++) {
        int idx = tid + j*512;
        int key = idx >> 4, f = idx & 15;
        cpa16(vbA + (unsigned)((key*72 + f*4)*4), &g_v[(base + 384 + key)*DD + f*4]);
    }
    CP_COMMIT();                                          // grp6: Vb2
    CP_WAIT2(); __syncthreads();                           // K1 ready

    qk_chunk(S, qTb, KBu, rel, rk, 256, wc, q, g, r0, r1, ri0, ri1, rs0, rs1);
    {
        rs0 += __shfl_xor_sync(0xffffffffu, rs0, 1);
        rs0 += __shfl_xor_sync(0xffffffffu, rs0, 2);
        rs1 += __shfl_xor_sync(0xffffffffu, rs1, 1);
        rs1 += __shfl_xor_sync(0xffffffffu, rs1, 2);
        if (q == 0) {
            wsum[wc*64 + r0] = rs0;
            wsum[wc*64 + r1] = rs1;
        }
    }
    __syncthreads();                                       // S1 + wsum ready
    if (tid < 64)
        invs[tid] = 1.f / (wsum[tid] + wsum[64 + tid] + wsum[128 + tid] + wsum[192 + tid]);
    // issue w1 -> KB [128][132] (overlaps PV1)
#pragma unroll
    for (int j = 0; j < 8; j++) {
        int idx = tid + j*512;
        int k = idx >> 5, f = idx & 31;
        cpa16(kbA + (unsigned)((k*132 + f*4)*4), &Wf1[k*128 + f*4]);
    }
    CP_COMMIT();                                          // grp7: w1

    CP_WAIT2(); __syncthreads();                           // Va2 ready (+invs visible)
    pv_half(Sb, VAu, 0, wc, q, g, r0, r1, accpv);          // keys 256-383
    CP_WAIT1(); __syncthreads();                           // Vb2 ready
    pv_half(Sb, VBu, 1, wc, q, g, r0, r1, accpv);          // keys 384-511
    CP_WAIT0();
    __syncthreads();                                       // w1 ready, all PV done

    // ---- PV epilogue: 1/sum, aoT(tf32) [d][row] s68 -> qTf (qT dead) ----
    {
        unsigned* aoT = (unsigned*)qTf;
        float iv0 = invs[r0], iv1 = invs[r1];
#pragma unroll
        for (int cb = 0; cb < 2; cb++) {
            int dc = wc*16 + cb*8 + 2*q;
            aoT[dc*68 + r0]       = cvt_tf32(accpv[cb][0] * iv0);
            aoT[(dc + 1)*68 + r0] = cvt_tf32(accpv[cb][1] * iv0);
            aoT[dc*68 + r1]       = cvt_tf32(accpv[cb][2] * iv1);
            aoT[(dc + 1)*68 + r1] = cvt_tf32(accpv[cb][3] * iv1);
        }
    }
    __syncthreads();

    // ---- FFN1: h1 = relu(ao@Wf1+bf1), M64 N128 K64, tf32 mma ----
    {
        const unsigned* aoT = (const unsigned*)qTf;
        float f1[4][4];
#pragma unroll
        for (int cb = 0; cb < 4; cb++) {
            f1[cb][0] = 0.f; f1[cb][1] = 0.f; f1[cb][2] = 0.f; f1[cb][3] = 0.f;
        }
#pragma unroll
        for (int ks = 0; ks < 8; ks++) {
            unsigned a0 = aoT[(ks*8 + q)*68 + r0];
            unsigned a1 = aoT[(ks*8 + q)*68 + r1];
            unsigned a2 = aoT[(ks*8 + q + 4)*68 + r0];
            unsigned a3 = aoT[(ks*8 + q + 4)*68 + r1];
#pragma unroll
            for (int cb = 0; cb < 4; cb++) {
                int nc = wc*32 + cb*8;
                unsigned b0 = cvt_tf32(KB[(ks*8 + q)*132 + nc + g]);
                unsigned b1 = cvt_tf32(KB[(ks*8 + q + 4)*132 + nc + g]);
                mma_tf32(f1[cb][0], f1[cb][1], f1[cb][2], f1[cb][3],
                         a0, a1, a2, a3, b0, b1);
            }
        }
        // h1T (tf32) -> S stride 68; ws1/ws2 staged alongside
        unsigned* h1T = (unsigned*)S;
#pragma unroll
        for (int cb = 0; cb < 4; cb++) {
            int c = wc*32 + cb*8 + 2*q;
            float bc0 = bf1[c], bc1 = bf1[c + 1];
            h1T[c*68 + r0]       = cvt_tf32(fmaxf(f1[cb][0] + bc0, 0.f));
            h1T[(c + 1)*68 + r0] = cvt_tf32(fmaxf(f1[cb][1] + bc1, 0.f));
            h1T[c*68 + r1]       = cvt_tf32(fmaxf(f1[cb][2] + bc0, 0.f));
            h1T[(c + 1)*68 + r1] = cvt_tf32(fmaxf(f1[cb][3] + bc1, 0.f));
        }
        *(float4*)&S[8960 + tid*4] = *(const float4*)&Ws1[tid*4];
        if (tid < 8) *(float4*)&S[11008 + tid*4] = *(const float4*)&Ws2[tid*4];
    }
    __syncthreads();                                       // w1 reads + h1T done

    // stage w2 -> KB [128][68]
    for (int idx = tid; idx < 2176; idx += 512) {
        int k = idx >> 4, f = idx & 15;
        if (f < 16) *(float4*)&KB[k*68 + f*4] = *(const float4*)&Wf2[k*64 + f*4];
    }
    __syncthreads();

    // ---- FFN2 + LayerNorm, M64 N64 K128, tf32 mma ----
    {
        const unsigned* h1T = (const unsigned*)S;
        float f2[2][4];
        f2[0][0] = f2[0][1] = f2[0][2] = f2[0][3] = 0.f;
        f2[1][0] = f2[1][1] = f2[1][2] = f2[1][3] = 0.f;
#pragma unroll
        for (int ks = 0; ks < 16; ks++) {
            unsigned a0 = h1T[(ks*8 + q)*68 + r0];
            unsigned a1 = h1T[(ks*8 + q)*68 + r1];
            unsigned a2 = h1T[(ks*8 + q + 4)*68 + r0];
            unsigned a3 = h1T[(ks*8 + q + 4)*68 + r1];
#pragma unroll
            for (int cb = 0; cb < 2; cb++) {
                int nc = wc*16 + cb*8;
                unsigned b0 = cvt_tf32(KB[(ks*8 + q)*68 + nc + g]);
                unsigned b1 = cvt_tf32(KB[(ks*8 + q + 4)*68 + nc + g]);
                mma_tf32(f2[cb][0], f2[cb][1], f2[cb][2], f2[cb][3],
                         a0, a1, a2, a3, b0, b1);
            }
        }
        // bias + LN partials
        float e[2][4];
        float s0 = 0.f, q0s = 0.f, s1v = 0.f, q1s = 0.f;
#pragma unroll
        for (int cb = 0; cb < 2; cb++) {
            int c = wc*16 + cb*8 + 2*q;
            e[cb][0] = f2[cb][0] + bf2[c];
            e[cb][1] = f2[cb][1] + bf2[c + 1];
            e[cb][2] = f2[cb][2] + bf2[c];
            e[cb][3] = f2[cb][3] + bf2[c + 1];
            s0  += e[cb][0] + e[cb][1];
            q0s += e[cb][0]*e[cb][0] + e[cb][1]*e[cb][1];
            s1v += e[cb][2] + e[cb][3];
            q1s += e[cb][2]*e[cb][2] + e[cb][3]*e[cb][3];
        }
#pragma unroll
        for (int o = 1; o <= 2; o <<= 1) {
            s0  += __shfl_xor_sync(0xffffffffu, s0,  o);
            q0s += __shfl_xor_sync(0xffffffffu, q0s, o);
            s1v += __shfl_xor_sync(0xffffffffu, s1v, o);
            q1s += __shfl_xor_sync(0xffffffffu, q1s, o);
        }
        if (q == 0) {
            wsum[wc*64 + r0] = s0;  wsq[wc*64 + r0] = q0s;
            wsum[wc*64 + r1] = s1v; wsq[wc*64 + r1] = q1s;
        }
        __syncthreads();
        float S0 = wsum[r0] + wsum[64 + r0] + wsum[128 + r0] + wsum[192 + r0];
        float Q0 = wsq[r0]  + wsq[64 + r0]  + wsq[128 + r0]  + wsq[192 + r0];
        float S1 = wsum[r1] + wsum[64 + r1] + wsum[128 + r1] + wsum[192 + r1];
        float Q1 = wsq[r1]  + wsq[64 + r1]  + wsq[128 + r1]  + wsq[192 + r1];
        float mu0 = S0 * (1.f/64.f), mu1 = S1 * (1.f/64.f);
        float in0 = rsqrtf(Q0 * (1.f/64.f) - mu0*mu0 + 1e-5f);
        float in1 = rsqrtf(Q1 * (1.f/64.f) - mu1*mu1 + 1e-5f);
        // hnT (fp32) -> qTf stride 68 (aoT dead)
#pragma unroll
        for (int cb = 0; cb < 2; cb++) {
            int c = wc*16 + cb*8 + 2*q;
            float g0v = ln_g[c], g1v = ln_g[c + 1];
            float be0 = ln_b[c], be1 = ln_b[c + 1];
            qTf[c*68 + r0]       = (e[cb][0] - mu0)*in0*g0v + be0;
            qTf[(c + 1)*68 + r0] = (e[cb][1] - mu0)*in0*g1v + be1;
            qTf[c*68 + r1]       = (e[cb][2] - mu1)*in1*g0v + be0;
            qTf[(c + 1)*68 + r1] = (e[cb][3] - mu1)*in1*g1v + be1;
        }
    }
    __syncthreads();

    // ---- head (threads 0..255) ----
    if (tid < 256) {
        const int ty4 = tid >> 4, tx4 = tid & 15;
        float s1[4][2];
#pragma unroll
        for (int r = 0; r < 4; r++) { s1[r][0] = 0.f; s1[r][1] = 0.f; }
#pragma unroll 4
        for (int kk = 0; kk < 64; kk++) {
            float4 a = *(const float4*)&qTf[kk*68 + ty4*4];
            float w0 = S[8960 + kk*32 + tx4*2], w1b = S[8960 + kk*32 + tx4*2 + 1];
            s1[0][0] = fmaf(a.x, w0, s1[0][0]); s1[0][1] = fmaf(a.x, w1b, s1[0][1]);
            s1[1][0] = fmaf(a.y, w0, s1[1][0]); s1[1][1] = fmaf(a.y, w1b, s1[1][1]);
            s1[2][0] = fmaf(a.z, w0, s1[2][0]); s1[2][1] = fmaf(a.z, w1b, s1[2][1]);
            s1[3][0] = fmaf(a.w, w0, s1[3][0]); s1[3][1] = fmaf(a.w, w1b, s1[3][1]);
        }
        float w2a = S[11008 + tx4*2], w2b = S[11008 + tx4*2 + 1];
        float ba = bs1[tx4*2], bb = bs1[tx4*2 + 1];
        float bs2v = bs2[0];
#pragma unroll
        for (int r = 0; r < 4; r++) {
            float pa = fmaxf(s1[r][0] + ba, 0.f);
            float pb = fmaxf(s1[r][1] + bb, 0.f);
            float p = pa*w2a + pb*w2b;
#pragma unroll
            for (int o = 8; o >= 1; o >>= 1) p += __shfl_xor_sync(0xffffffffu, p, o, 16);
            if (tx4 == 0) {
                float z = p + bs2v;
                out[base + q0 + ty4*4 + r] = 1.f / (1.f + __expf(-z));
            }
        }
    }
}

// ============================================================
extern "C" void kernel_launch(void* const* d_in, const int* in_sizes, int n_in,
                              void* d_out, int out_size) {
    const float* x     = (const float*)d_in[0];
    const int*   ranks = (const int*)  d_in[1];
    const float* Wp    = (const float*)d_in[2];
    const float* bp    = (const float*)d_in[3];
    const float* Wq    = (const float*)d_in[4];
    const float* bq    = (const float*)d_in[5];
    const float* Wk    = (const float*)d_in[6];
    const float* bk    = (const float*)d_in[7];
    const float* Wv    = (const float*)d_in[8];
    const float* bv    = (const float*)d_in[9];
    const float* Eemb  = (const float*)d_in[10];
    const float* Wr1   = (const float*)d_in[11];
    const float* br1   = (const float*)d_in[12];
    const float* Wr2   = (const float*)d_in[13];
    const float* Wf1   = (const float*)d_in[14];
    const float* bf1   = (const float*)d_in[15];
    const float* Wf2   = (const float*)d_in[16];
    const float* bf2   = (const float*)d_in[17];
    const float* ln_g  = (const float*)d_in[18];
    const float* ln_b  = (const float*)d_in[19];
    const float* Ws1   = (const float*)d_in[20];
    const float* bs1   = (const float*)d_in[21];
    const float* Ws2   = (const float*)d_in[22];
    const float* bs2   = (const float*)d_in[23];
    float* out = (float*)d_out;

    cudaFuncSetAttribute(qkv_kernel, cudaFuncAttributeMaxDynamicSharedMemorySize, K1_BYTES);
    cudaFuncSetAttribute(attn_kernel, cudaFuncAttributeMaxDynamicSharedMemorySize, SMEM_BYTES);

    qkv_kernel<<<BB*NN/64, 512, K1_BYTES>>>(x, Wp, bp, Wq, bq, Wk, bk, Wv, bv,
                                            Eemb, Wr1, br1, Wr2);
    dim3 grid(NN/64, BB);
    attn_kernel<<<grid, 512, SMEM_BYTES>>>(ranks, Wf1, bf1, Wf2, bf2,
                                           ln_g, ln_b, Ws1, bs1, Ws2, bs2, out);
}

// round 13
// speedup vs baseline: 2.2179x; 1.0828x over previous
#include <cuda_runtime.h>

#define BB   16
#define NN   512
#define DIN  256
#define DD   64
#define EE   32
#define MAXDIST 50

typedef unsigned long long ull;

__device__ __forceinline__ float ex2(float x) {
    float r;
    asm("ex2.approx.f32 %0, %1;" : "=f"(r) : "f"(x));
    return r;
}
__device__ __forceinline__ unsigned cvt_tf32(float x) {
    unsigned r;
    asm("cvt.rna.tf32.f32 %0, %1;" : "=r"(r) : "f"(x));
    return r;
}
__device__ __forceinline__ void mma_tf32(float& c0, float& c1, float& c2, float& c3,
                                         unsigned a0, unsigned a1, unsigned a2, unsigned a3,
                                         unsigned b0, unsigned b1) {
    asm("mma.sync.aligned.m16n8k8.row.col.f32.tf32.tf32.f32 "
        "{%0,%1,%2,%3}, {%4,%5,%6,%7}, {%8,%9}, {%0,%1,%2,%3};"
        : "+f"(c0), "+f"(c1), "+f"(c2), "+f"(c3)
        : "r"(a0), "r"(a1), "r"(a2), "r"(a3), "r"(b0), "r"(b1));
}
__device__ __forceinline__ void cpa16(unsigned dst, const float* src) {
    asm volatile("cp.async.cg.shared.global [%0], [%1], 16;" :: "r"(dst), "l"(src));
}
#define CP_COMMIT() asm volatile("cp.async.commit_group;" ::: "memory")
#define CP_WAIT2()  asm volatile("cp.async.wait_group 2;" ::: "memory")
#define CP_WAIT1()  asm volatile("cp.async.wait_group 1;" ::: "memory")
#define CP_WAIT0()  asm volatile("cp.async.wait_group 0;" ::: "memory")

__device__ float g_kT[BB*DD*NN];   // per batch: [d][n], tf32-rounded
__device__ float g_v [BB*NN*DD];   // row-major [n][d], tf32-rounded
__device__ int   g_ctr[BB];        // producer doorbell (self-resetting)
__device__ int   g_done[BB];       // consumer done count (self-resetting)

// ---- smem layout (floats) ----
// qkv phase: XS 0..16640, WP 16640..35072, WT 35072..48896, XP 48896..53248
// attn phase: S 0..16640, KB 16640..33536, VA 33536..42752, VB 42752..51968
// shared tail: QT 51968..56576 (q written by qkv phase B epilogue, after sync)
//              rel 56576, rk 56640, wsum 57152, invs 57408; wsq inside S @11264
#define XS_OFF  0
#define WP_OFF  16640
#define WT_OFF  35072
#define XP_OFF  48896
#define S_OFF    0
#define KB_OFF   16640
#define VA_OFF   33536
#define VB2_OFF  42752
#define QT_OFF   51968
#define REL_OFF  56576
#define RK_OFF   56640
#define WS_OFF   57152
#define INV_OFF  57408
#define SMEM_FLOATS 57472
#define SMEM_BYTES  (SMEM_FLOATS*4)

__device__ __forceinline__ void qk_chunk(
    float* S, const unsigned* qTb, const unsigned* KBu, const float* rel, const int* rk,
    int k0, int wc, int q, int g, int r0, int r1, int ri0, int ri1,
    float& rs0, float& rs1) {
    float acc[8][4];
#pragma unroll
    for (int cb = 0; cb < 8; cb++) {
        acc[cb][0] = 0.f; acc[cb][1] = 0.f; acc[cb][2] = 0.f; acc[cb][3] = 0.f;
    }
#pragma unroll
    for (int ks = 0; ks < 8; ks++) {
        unsigned a0 = qTb[(ks*8 + q)*72 + r0];
        unsigned a1 = qTb[(ks*8 + q)*72 + r1];
        unsigned a2 = qTb[(ks*8 + q + 4)*72 + r0];
        unsigned a3 = qTb[(ks*8 + q + 4)*72 + r1];
#pragma unroll
        for (int cb = 0; cb < 8; cb++) {
            int key0 = wc*64 + cb*8;
            unsigned b0 = KBu[(ks*8 + q)*264 + key0 + g];
            unsigned b1 = KBu[(ks*8 + q + 4)*264 + key0 + g];
            mma_tf32(acc[cb][0], acc[cb][1], acc[cb][2], acc[cb][3],
                     a0, a1, a2, a3, b0, b1);
        }
    }
#pragma unroll
    for (int cb = 0; cb < 8; cb++) {
        int kloc = wc*64 + cb*8 + 2*q;
        int ka = rk[k0 + kloc], kb = rk[k0 + kloc + 1];
        int d00 = ri0 - ka; d00 = d00 < 0 ? -d00 : d00; if (d00 > MAXDIST) d00 = MAXDIST;
        int d01 = ri0 - kb; d01 = d01 < 0 ? -d01 : d01; if (d01 > MAXDIST) d01 = MAXDIST;
        int d10 = ri1 - ka; d10 = d10 < 0 ? -d10 : d10; if (d10 > MAXDIST) d10 = MAXDIST;
        int d11 = ri1 - kb; d11 = d11 < 0 ? -d11 : d11; if (d11 > MAXDIST) d11 = MAXDIST;
        float f00 = __uint_as_float(cvt_tf32(ex2(acc[cb][0] * rel[d00])));
        float f01 = __uint_as_float(cvt_tf32(ex2(acc[cb][1] * rel[d01])));
        float f10 = __uint_as_float(cvt_tf32(ex2(acc[cb][2] * rel[d10])));
        float f11 = __uint_as_float(cvt_tf32(ex2(acc[cb][3] * rel[d11])));
        *(float2*)&S[r0*260 + kloc] = make_float2(f00, f01);
        *(float2*)&S[r1*260 + kloc] = make_float2(f10, f11);
        rs0 += f00 + f01;
        rs1 += f10 + f11;
    }
}

__device__ __forceinline__ void pv_half(
    const unsigned* Sb, const unsigned* VBu,
    int h, int wc, int q, int g, int r0, int r1, float (&accpv)[2][4]) {
#pragma unroll
    for (int ks = 0; ks < 16; ks++) {
        int kk = h*128 + ks*8;
        unsigned a0 = Sb[r0*260 + kk + q];
        unsigned a1 = Sb[r1*260 + kk + q];
        unsigned a2 = Sb[r0*260 + kk + q + 4];
        unsigned a3 = Sb[r1*260 + kk + q + 4];
#pragma unroll
        for (int cb = 0; cb < 2; cb++) {
            int d0 = wc*16 + cb*8;
            unsigned b0 = VBu[(ks*8 + q)*72 + d0 + g];
            unsigned b1 = VBu[(ks*8 + q + 4)*72 + d0 + g];
            mma_tf32(accpv[cb][0], accpv[cb][1], accpv[cb][2], accpv[cb][3],
                     a0, a1, a2, a3, b0, b1);
        }
    }
}

__global__ __launch_bounds__(512) void fused_kernel(
    const float* __restrict__ x, const int* __restrict__ ranks,
    const float* __restrict__ Wp, const float* __restrict__ bp,
    const float* __restrict__ Wq, const float* __restrict__ bq,
    const float* __restrict__ Wk, const float* __restrict__ bk,
    const float* __restrict__ Wv, const float* __restrict__ bv,
    const float* __restrict__ Eemb, const float* __restrict__ Wr1,
    const float* __restrict__ br1,  const float* __restrict__ Wr2,
    const float* __restrict__ Wf1, const float* __restrict__ bf1,
    const float* __restrict__ Wf2, const float* __restrict__ bf2,
    const float* __restrict__ ln_g, const float* __restrict__ ln_b,
    const float* __restrict__ Ws1, const float* __restrict__ bs1,
    const float* __restrict__ Ws2, const float* __restrict__ bs2,
    float* __restrict__ out) {
    extern __shared__ float sm[];
    const int tid = threadIdx.x;
    const int wp = tid >> 5, lane = tid & 31;
    const int g = lane >> 2, q = lane & 3;
    const int rb = wp >> 2, wc = wp & 3;
    const int r0 = rb*16 + g, r1 = r0 + 8;
    const int blk = blockIdx.x;
    const int b = blk >> 3;
    const int row0 = blk * 64;
    const int n0 = row0 & 511;
    const int q0 = n0;
    const int base = b * NN;
    const int bT = b * DD * NN;

    const unsigned sb = (unsigned)__cvta_generic_to_shared(sm);

    // ================= QKV PHASE =================
    {
        float* XS = sm + XS_OFF;
        float* WP = sm + WP_OFF;
        float* WT = sm + WT_OFF;
        float* XP = sm + XP_OFF;
        float* rel = sm + REL_OFF;
        int*   rk  = (int*)(sm + RK_OFF);

#pragma unroll
        for (int j = 0; j < 8; j++) {
            int idx = tid + j*512;
            int row = idx >> 6, f = idx & 63;
            cpa16(sb + (unsigned)((XS_OFF + row*260 + f*4)*4), &x[(row0 + row)*DIN + f*4]);
        }
        CP_COMMIT();
#pragma unroll
        for (int j = 0; j < 8; j++) {
            int idx = tid + j*512;
            int row = idx >> 4, f = idx & 15;
            cpa16(sb + (unsigned)((WP_OFF + row*72 + f*4)*4), &Wp[row*DD + f*4]);
        }
        CP_COMMIT();
#pragma unroll
        for (int j = 0; j < 6; j++) {
            int idx = tid + j*512;
            int t = idx >> 10, rem = idx & 1023;
            int row = rem >> 4, f = rem & 15;
            const float* src = (t == 0) ? Wk : (t == 1) ? Wv : Wq;
            cpa16(sb + (unsigned)((WT_OFF + t*4608 + row*72 + f*4)*4), &src[row*DD + f*4]);
        }
        CP_COMMIT();

        // rel (every CTA, local) + rk staging — regions above qkv smem
        if (tid <= MAXDIST) {
            float e[EE];
#pragma unroll
            for (int c = 0; c < EE; c++) e[c] = Eemb[tid*EE + c];
            float w = 0.f;
#pragma unroll
            for (int j = 0; j < 16; j++) {
                float h = br1[j];
#pragma unroll
                for (int c = 0; c < EE; c++) h = fmaf(e[c], Wr1[c*16 + j], h);
                h = fmaxf(h, 0.f);
                w = fmaf(h, Wr2[j], w);
            }
            rel[tid] = 0.18033688011112042f / (1.f + __expf(-w));
        }
        if (tid < NN) rk[tid] = ranks[base + tid];

        CP_WAIT1(); __syncthreads();          // x + Wp ready

        // Phase A: xp = x @ Wp
        float acc[2][4];
#pragma unroll
        for (int cb = 0; cb < 2; cb++) {
            acc[cb][0] = 0.f; acc[cb][1] = 0.f; acc[cb][2] = 0.f; acc[cb][3] = 0.f;
        }
#pragma unroll 4
        for (int ks = 0; ks < 32; ks++) {
            unsigned a0 = cvt_tf32(XS[r0*260 + ks*8 + q]);
            unsigned a1 = cvt_tf32(XS[r1*260 + ks*8 + q]);
            unsigned a2 = cvt_tf32(XS[r0*260 + ks*8 + q + 4]);
            unsigned a3 = cvt_tf32(XS[r1*260 + ks*8 + q + 4]);
#pragma unroll
            for (int cb = 0; cb < 2; cb++) {
                int nc = wc*16 + cb*8;
                unsigned b0 = cvt_tf32(WP[(ks*8 + q)*72 + nc + g]);
                unsigned b1 = cvt_tf32(WP[(ks*8 + q + 4)*72 + nc + g]);
                mma_tf32(acc[cb][0], acc[cb][1], acc[cb][2], acc[cb][3],
                         a0, a1, a2, a3, b0, b1);
            }
        }
        CP_WAIT0();
#pragma unroll
        for (int cb = 0; cb < 2; cb++) {
            int c = wc*16 + cb*8 + 2*q;
            float bp0 = bp[c], bp1 = bp[c + 1];
            XP[r0*68 + c]     = acc[cb][0] + bp0;
            XP[r0*68 + c + 1] = acc[cb][1] + bp1;
            XP[r1*68 + c]     = acc[cb][2] + bp0;
            XP[r1*68 + c + 1] = acc[cb][3] + bp1;
        }
        __syncthreads();

        // Phase B: k then v (to global), signal, then q (to local smem)
#pragma unroll
        for (int t = 0; t < 2; t++) {
            const float* W = WT + t*4608;
            const float* bs = (t == 0) ? bk : bv;
            float o[2][4];
#pragma unroll
            for (int cb = 0; cb < 2; cb++) {
                o[cb][0] = 0.f; o[cb][1] = 0.f; o[cb][2] = 0.f; o[cb][3] = 0.f;
            }
#pragma unroll
            for (int ks = 0; ks < 8; ks++) {
                unsigned a0 = cvt_tf32(XP[r0*68 + ks*8 + q]);
                unsigned a1 = cvt_tf32(XP[r1*68 + ks*8 + q]);
                unsigned a2 = cvt_tf32(XP[r0*68 + ks*8 + q + 4]);
                unsigned a3 = cvt_tf32(XP[r1*68 + ks*8 + q + 4]);
#pragma unroll
                for (int cb = 0; cb < 2; cb++) {
                    int nc = wc*16 + cb*8;
                    unsigned b0 = cvt_tf32(W[(ks*8 + q)*72 + nc + g]);
                    unsigned b1 = cvt_tf32(W[(ks*8 + q + 4)*72 + nc + g]);
                    mma_tf32(o[cb][0], o[cb][1], o[cb][2], o[cb][3],
                             a0, a1, a2, a3, b0, b1);
                }
            }
            if (t == 1) {
#pragma unroll
                for (int cb = 0; cb < 2; cb++) {
                    int c = wc*16 + cb*8 + 2*q;
                    float v0 = __uint_as_float(cvt_tf32(o[cb][0] + bs[c]));
                    float v1 = __uint_as_float(cvt_tf32(o[cb][1] + bs[c + 1]));
                    float v2 = __uint_as_float(cvt_tf32(o[cb][2] + bs[c]));
                    float v3 = __uint_as_float(cvt_tf32(o[cb][3] + bs[c + 1]));
                    *(float2*)&g_v[(row0 + r0)*DD + c] = make_float2(v0, v1);
                    *(float2*)&g_v[(row0 + r1)*DD + c] = make_float2(v2, v3);
                }
            } else {
#pragma unroll
                for (int cb = 0; cb < 2; cb++) {
                    int c = wc*16 + cb*8 + 2*q;
                    g_kT[bT + c*NN + n0 + r0]       = __uint_as_float(cvt_tf32(o[cb][0] + bs[c]));
                    g_kT[bT + (c + 1)*NN + n0 + r0] = __uint_as_float(cvt_tf32(o[cb][1] + bs[c + 1]));
                    g_kT[bT + c*NN + n0 + r1]       = __uint_as_float(cvt_tf32(o[cb][2] + bs[c]));
                    g_kT[bT + (c + 1)*NN + n0 + r1] = __uint_as_float(cvt_tf32(o[cb][3] + bs[c + 1]));
                }
            }
        }
        __syncthreads();                      // all k/v stores issued
        if (tid == 0) {
            __threadfence();
            atomicAdd(&g_ctr[b], 1);          // doorbell: this tile's k/v ready
        }

        // q (local): mma over XP, then write qT region (overlaps XP tail -> sync first)
        {
            const float* W = WT + 2*4608;
            float o[2][4];
#pragma unroll
            for (int cb = 0; cb < 2; cb++) {
                o[cb][0] = 0.f; o[cb][1] = 0.f; o[cb][2] = 0.f; o[cb][3] = 0.f;
            }
#pragma unroll
            for (int ks = 0; ks < 8; ks++) {
                unsigned a0 = cvt_tf32(XP[r0*68 + ks*8 + q]);
                unsigned a1 = cvt_tf32(XP[r1*68 + ks*8 + q]);
                unsigned a2 = cvt_tf32(XP[r0*68 + ks*8 + q + 4]);
                unsigned a3 = cvt_tf32(XP[r1*68 + ks*8 + q + 4]);
#pragma unroll
                for (int cb = 0; cb < 2; cb++) {
                    int nc = wc*16 + cb*8;
                    unsigned b0 = cvt_tf32(W[(ks*8 + q)*72 + nc + g]);
                    unsigned b1 = cvt_tf32(W[(ks*8 + q + 4)*72 + nc + g]);
                    mma_tf32(o[cb][0], o[cb][1], o[cb][2], o[cb][3],
                             a0, a1, a2, a3, b0, b1);
                }
            }
            __syncthreads();                  // XP reads done before qT overwrite
            unsigned* qTu = (unsigned*)(sm + QT_OFF);
#pragma unroll
            for (int cb = 0; cb < 2; cb++) {
                int c = wc*16 + cb*8 + 2*q;
                qTu[c*72 + r0]       = cvt_tf32(o[cb][0] + bq[c]);
                qTu[(c + 1)*72 + r0] = cvt_tf32(o[cb][1] + bq[c + 1]);
                qTu[c*72 + r1]       = cvt_tf32(o[cb][2] + bq[c]);
                qTu[(c + 1)*72 + r1] = cvt_tf32(o[cb][3] + bq[c + 1]);
            }
        }
    }

    // ---- wait for all 8 producer tiles of this batch ----
    if (tid == 0) {
        volatile int* c = &g_ctr[b];
        while (*c < 8) {}
        __threadfence();
    }
    __syncthreads();

    // ================= ATTN PHASE =================
    {
        float* S    = sm + S_OFF;
        float* KB   = sm + KB_OFF;
        float* qTf  = sm + QT_OFF;
        float* rel  = sm + REL_OFF;
        int*   rk   = (int*)(sm + RK_OFF);
        float* wsum = sm + WS_OFF;
        float* invs = sm + INV_OFF;
        float* wsq  = sm + 11264;
        const unsigned* qTb = (const unsigned*)qTf;
        const unsigned* Sb  = (const unsigned*)S;
        const unsigned* KBu = (const unsigned*)KB;
        const unsigned* VAu = (const unsigned*)(sm + VA_OFF);
        const unsigned* VBu = (const unsigned*)(sm + VB2_OFF);
        const unsigned kbA = sb + KB_OFF*4;
        const unsigned vaA = sb + VA_OFF*4;
        const unsigned vbA = sb + VB2_OFF*4;

#pragma unroll
        for (int j = 0; j < 8; j++) {
            int idx = tid + j*512;
            int d = idx >> 6, f = idx & 63;
            cpa16(kbA + (unsigned)((d*264 + f*4)*4), &g_kT[bT + d*NN + f*4]);
        }
        CP_COMMIT();                                          // grp1: K0
#pragma unroll
        for (int j = 0; j < 4; j++) {
            int idx = tid + j*512;
            int key = idx >> 4, f = idx & 15;
            cpa16(vaA + (unsigned)((key*72 + f*4)*4), &g_v[(base + key)*DD + f*4]);
        }
        CP_COMMIT();                                          // grp2: Va
#pragma unroll
        for (int j = 0; j < 4; j++) {
            int idx = tid + j*512;
            int key = idx >> 4, f = idx & 15;
            cpa16(vbA + (unsigned)((key*72 + f*4)*4), &g_v[(base + 128 + key)*DD + f*4]);
        }
        CP_COMMIT();                                          // grp3: Vb

        float rs0 = 0.f, rs1 = 0.f;
        float accpv[2][4];
#pragma unroll
        for (int c = 0; c < 2; c++) {
            accpv[c][0] = 0.f; accpv[c][1] = 0.f; accpv[c][2] = 0.f; accpv[c][3] = 0.f;
        }

        CP_WAIT2(); __syncthreads();                           // K0 ready
        const int ri0 = rk[q0 + r0], ri1 = rk[q0 + r1];

        qk_chunk(S, qTb, KBu, rel, rk, 0, wc, q, g, r0, r1, ri0, ri1, rs0, rs1);
        __syncthreads();                                       // S0 ready, KB free

#pragma unroll
        for (int j = 0; j < 8; j++) {
            int idx = tid + j*512;
            int d = idx >> 6, f = idx & 63;
            cpa16(kbA + (unsigned)((d*264 + f*4)*4), &g_kT[bT + d*NN + 256 + f*4]);
        }
        CP_COMMIT();                                          // grp4: K1

        CP_WAIT2(); __syncthreads();                           // Va ready
        pv_half(Sb, VAu, 0, wc, q, g, r0, r1, accpv);
        CP_WAIT1(); __syncthreads();                           // Vb ready, VA free
#pragma unroll
        for (int j = 0; j < 4; j++) {
            int idx = tid + j*512;
            int key = idx >> 4, f = idx & 15;
            cpa16(vaA + (unsigned)((key*72 + f*4)*4), &g_v[(base + 256 + key)*DD + f*4]);
        }
        CP_COMMIT();                                          // grp5: Va2
        pv_half(Sb, VBu, 1, wc, q, g, r0, r1, accpv);
        __syncthreads();                                       // VB free, S free
#pragma unroll
        for (int j = 0; j < 4; j++) {
            int idx = tid + j*512;
            int key = idx >> 4, f = idx & 15;
            cpa16(vbA + (unsigned)((key*72 + f*4)*4), &g_v[(base + 384 + key)*DD + f*4]);
        }
        CP_COMMIT();                                          // grp6: Vb2
        CP_WAIT2(); __syncthreads();                           // K1 ready

        qk_chunk(S, qTb, KBu, rel, rk, 256, wc, q, g, r0, r1, ri0, ri1, rs0, rs1);
        {
            rs0 += __shfl_xor_sync(0xffffffffu, rs0, 1);
            rs0 += __shfl_xor_sync(0xffffffffu, rs0, 2);
            rs1 += __shfl_xor_sync(0xffffffffu, rs1, 1);
            rs1 += __shfl_xor_sync(0xffffffffu, rs1, 2);
            if (q == 0) {
                wsum[wc*64 + r0] = rs0;
                wsum[wc*64 + r1] = rs1;
            }
        }
        __syncthreads();                                       // S1 + wsum ready
        if (tid < 64)
            invs[tid] = 1.f / (wsum[tid] + wsum[64 + tid] + wsum[128 + tid] + wsum[192 + tid]);
#pragma unroll
        for (int j = 0; j < 8; j++) {
            int idx = tid + j*512;
            int k = idx >> 5, f = idx & 31;
            cpa16(kbA + (unsigned)((k*132 + f*4)*4), &Wf1[k*128 + f*4]);
        }
        CP_COMMIT();                                          // grp7: w1

        CP_WAIT2(); __syncthreads();                           // Va2 ready (+invs)
        pv_half(Sb, VAu, 0, wc, q, g, r0, r1, accpv);
        CP_WAIT1(); __syncthreads();                           // Vb2 ready
        pv_half(Sb, VBu, 1, wc, q, g, r0, r1, accpv);
        CP_WAIT0();
        __syncthreads();                                       // w1 ready, PV done

        // PV epilogue: 1/sum, aoT(tf32) -> qTf (qT dead)
        {
            unsigned* aoT = (unsigned*)qTf;
            float iv0 = invs[r0], iv1 = invs[r1];
#pragma unroll
            for (int cb = 0; cb < 2; cb++) {
                int dc = wc*16 + cb*8 + 2*q;
                aoT[dc*68 + r0]       = cvt_tf32(accpv[cb][0] * iv0);
                aoT[(dc + 1)*68 + r0] = cvt_tf32(accpv[cb][1] * iv0);
                aoT[dc*68 + r1]       = cvt_tf32(accpv[cb][2] * iv1);
                aoT[(dc + 1)*68 + r1] = cvt_tf32(accpv[cb][3] * iv1);
            }
        }
        __syncthreads();

        // FFN1: tf32 mma, M64 N128 K64
        {
            const unsigned* aoT = (const unsigned*)qTf;
            float f1[4][4];
#pragma unroll
            for (int cb = 0; cb < 4; cb++) {
                f1[cb][0] = 0.f; f1[cb][1] = 0.f; f1[cb][2] = 0.f; f1[cb][3] = 0.f;
            }
#pragma unroll
            for (int ks = 0; ks < 8; ks++) {
                unsigned a0 = aoT[(ks*8 + q)*68 + r0];
                unsigned a1 = aoT[(ks*8 + q)*68 + r1];
                unsigned a2 = aoT[(ks*8 + q + 4)*68 + r0];
                unsigned a3 = aoT[(ks*8 + q + 4)*68 + r1];
#pragma unroll
                for (int cb = 0; cb < 4; cb++) {
                    int nc = wc*32 + cb*8;
                    unsigned b0 = cvt_tf32(KB[(ks*8 + q)*132 + nc + g]);
                    unsigned b1 = cvt_tf32(KB[(ks*8 + q + 4)*132 + nc + g]);
                    mma_tf32(f1[cb][0], f1[cb][1], f1[cb][2], f1[cb][3],
                             a0, a1, a2, a3, b0, b1);
                }
            }
            unsigned* h1T = (unsigned*)S;
#pragma unroll
            for (int cb = 0; cb < 4; cb++) {
                int c = wc*32 + cb*8 + 2*q;
                float bc0 = bf1[c], bc1 = bf1[c + 1];
                h1T[c*68 + r0]       = cvt_tf32(fmaxf(f1[cb][0] + bc0, 0.f));
                h1T[(c + 1)*68 + r0] = cvt_tf32(fmaxf(f1[cb][1] + bc1, 0.f));
                h1T[c*68 + r1]       = cvt_tf32(fmaxf(f1[cb][2] + bc0, 0.f));
                h1T[(c + 1)*68 + r1] = cvt_tf32(fmaxf(f1[cb][3] + bc1, 0.f));
            }
            *(float4*)&S[8960 + tid*4] = *(const float4*)&Ws1[tid*4];
            if (tid < 8) *(float4*)&S[11008 + tid*4] = *(const float4*)&Ws2[tid*4];
        }
        __syncthreads();

        for (int idx = tid; idx < 2048; idx += 512) {
            int k = idx >> 4, f = idx & 15;
            *(float4*)&KB[k*68 + f*4] = *(const float4*)&Wf2[k*64 + f*4];
        }
        __syncthreads();

        // FFN2 + LayerNorm, M64 N64 K128
        {
            const unsigned* h1T = (const unsigned*)S;
            float f2[2][4];
            f2[0][0] = f2[0][1] = f2[0][2] = f2[0][3] = 0.f;
            f2[1][0] = f2[1][1] = f2[1][2] = f2[1][3] = 0.f;
#pragma unroll
            for (int ks = 0; ks < 16; ks++) {
                unsigned a0 = h1T[(ks*8 + q)*68 + r0];
                unsigned a1 = h1T[(ks*8 + q)*68 + r1];
                unsigned a2 = h1T[(ks*8 + q + 4)*68 + r0];
                unsigned a3 = h1T[(ks*8 + q + 4)*68 + r1];
#pragma unroll
                for (int cb = 0; cb < 2; cb++) {
                    int nc = wc*16 + cb*8;
                    unsigned b0 = cvt_tf32(KB[(ks*8 + q)*68 + nc + g]);
                    unsigned b1 = cvt_tf32(KB[(ks*8 + q + 4)*68 + nc + g]);
                    mma_tf32(f2[cb][0], f2[cb][1], f2[cb][2], f2[cb][3],
                             a0, a1, a2, a3, b0, b1);
                }
            }
            float e[2][4];
            float s0 = 0.f, q0s = 0.f, s1v = 0.f, q1s = 0.f;
#pragma unroll
            for (int cb = 0; cb < 2; cb++) {
                int c = wc*16 + cb*8 + 2*q;
                e[cb][0] = f2[cb][0] + bf2[c];
                e[cb][1] = f2[cb][1] + bf2[c + 1];
                e[cb][2] = f2[cb][2] + bf2[c];
                e[cb][3] = f2[cb][3] + bf2[c + 1];
                s0  += e[cb][0] + e[cb][1];
                q0s += e[cb][0]*e[cb][0] + e[cb][1]*e[cb][1];
                s1v += e[cb][2] + e[cb][3];
                q1s += e[cb][2]*e[cb][2] + e[cb][3]*e[cb][3];
            }
#pragma unroll
            for (int o = 1; o <= 2; o <<= 1) {
                s0  += __shfl_xor_sync(0xffffffffu, s0,  o);
                q0s += __shfl_xor_sync(0xffffffffu, q0s, o);
                s1v += __shfl_xor_sync(0xffffffffu, s1v, o);
                q1s += __shfl_xor_sync(0xffffffffu, q1s, o);
            }
            if (q == 0) {
                wsum[wc*64 + r0] = s0;  wsq[wc*64 + r0] = q0s;
                wsum[wc*64 + r1] = s1v; wsq[wc*64 + r1] = q1s;
            }
            __syncthreads();
            float S0 = wsum[r0] + wsum[64 + r0] + wsum[128 + r0] + wsum[192 + r0];
            float Q0 = wsq[r0]  + wsq[64 + r0]  + wsq[128 + r0]  + wsq[192 + r0];
            float S1 = wsum[r1] + wsum[64 + r1] + wsum[128 + r1] + wsum[192 + r1];
            float Q1 = wsq[r1]  + wsq[64 + r1]  + wsq[128 + r1]  + wsq[192 + r1];
            float mu0 = S0 * (1.f/64.f), mu1 = S1 * (1.f/64.f);
            float in0 = rsqrtf(Q0 * (1.f/64.f) - mu0*mu0 + 1e-5f);
            float in1 = rsqrtf(Q1 * (1.f/64.f) - mu1*mu1 + 1e-5f);
#pragma unroll
            for (int cb = 0; cb < 2; cb++) {
                int c = wc*16 + cb*8 + 2*q;
                float g0v = ln_g[c], g1v = ln_g[c + 1];
                float be0 = ln_b[c], be1 = ln_b[c + 1];
                qTf[c*68 + r0]       = (e[cb][0] - mu0)*in0*g0v + be0;
                qTf[(c + 1)*68 + r0] = (e[cb][1] - mu0)*in0*g1v + be1;
                qTf[c*68 + r1]       = (e[cb][2] - mu1)*in1*g0v + be0;
                qTf[(c + 1)*68 + r1] = (e[cb][3] - mu1)*in1*g1v + be1;
            }
        }
        __syncthreads();

        // head (threads 0..255)
        if (tid < 256) {
            const int ty4 = tid >> 4, tx4 = tid & 15;
            float s1[4][2];
#pragma unroll
            for (int r = 0; r < 4; r++) { s1[r][0] = 0.f; s1[r][1] = 0.f; }
#pragma unroll 4
            for (int kk = 0; kk < 64; kk++) {
                float4 a = *(const float4*)&qTf[kk*68 + ty4*4];
                float w0 = S[8960 + kk*32 + tx4*2], w1b = S[8960 + kk*32 + tx4*2 + 1];
                s1[0][0] = fmaf(a.x, w0, s1[0][0]); s1[0][1] = fmaf(a.x, w1b, s1[0][1]);
                s1[1][0] = fmaf(a.y, w0, s1[1][0]); s1[1][1] = fmaf(a.y, w1b, s1[1][1]);
                s1[2][0] = fmaf(a.z, w0, s1[2][0]); s1[2][1] = fmaf(a.z, w1b, s1[2][1]);
                s1[3][0] = fmaf(a.w, w0, s1[3][0]); s1[3][1] = fmaf(a.w, w1b, s1[3][1]);
            }
            float w2a = S[11008 + tx4*2], w2b = S[11008 + tx4*2 + 1];
            float ba = bs1[tx4*2], bb = bs1[tx4*2 + 1];
            float bs2v = bs2[0];
#pragma unroll
            for (int r = 0; r < 4; r++) {
                float pa = fmaxf(s1[r][0] + ba, 0.f);
                float pb = fmaxf(s1[r][1] + bb, 0.f);
                float p = pa*w2a + pb*w2b;
#pragma unroll
                for (int o = 8; o >= 1; o >>= 1) p += __shfl_xor_sync(0xffffffffu, p, o, 16);
                if (tx4 == 0) {
                    float z = p + bs2v;
                    out[base + q0 + ty4*4 + r] = 1.f / (1.f + __expf(-z));
                }
            }
        }
    }

    // ---- self-resetting counters for graph replay ----
    __syncthreads();
    if (tid == 0) {
        int d = atomicAdd(&g_done[b], 1);
        if (d == 7) {
            g_ctr[b] = 0;
            g_done[b] = 0;
            __threadfence();
        }
    }
}

// ============================================================
extern "C" void kernel_launch(void* const* d_in, const int* in_sizes, int n_in,
                              void* d_out, int out_size) {
    const float* x     = (const float*)d_in[0];
    const int*   ranks = (const int*)  d_in[1];
    const float* Wp    = (const float*)d_in[2];
    const float* bp    = (const float*)d_in[3];
    const float* Wq    = (const float*)d_in[4];
    const float* bq    = (const float*)d_in[5];
    const float* Wk    = (const float*)d_in[6];
    const float* bk    = (const float*)d_in[7];
    const float* Wv    = (const float*)d_in[8];
    const float* bv    = (const float*)d_in[9];
    const float* Eemb  = (const float*)d_in[10];
    const float* Wr1   = (const float*)d_in[11];
    const float* br1   = (const float*)d_in[12];
    const float* Wr2   = (const float*)d_in[13];
    const float* Wf1   = (const float*)d_in[14];
    const float* bf1   = (const float*)d_in[15];
    const float* Wf2   = (const float*)d_in[16];
    const float* bf2   = (const float*)d_in[17];
    const float* ln_g  = (const float*)d_in[18];
    const float* ln_b  = (const float*)d_in[19];
    const float* Ws1   = (const float*)d_in[20];
    const float* bs1   = (const float*)d_in[21];
    const float* Ws2   = (const float*)d_in[22];
    const float* bs2   = (const float*)d_in[23];
    float* out = (float*)d_out;

    cudaFuncSetAttribute(fused_kernel, cudaFuncAttributeMaxDynamicSharedMemorySize, SMEM_BYTES);

    fused_kernel<<<BB*NN/64, 512, SMEM_BYTES>>>(
        x, ranks, Wp, bp, Wq, bq, Wk, bk, Wv, bv,
        Eemb, Wr1, br1, Wr2, Wf1, bf1, Wf2, bf2,
        ln_g, ln_b, Ws1, bs1, Ws2, bs2, out);
}

// round 14
// speedup vs baseline: 2.2349x; 1.0077x over previous
#include <cuda_runtime.h>

#define BB   16
#define NN   512
#define DIN  256
#define DD   64
#define EE   32
#define MAXDIST 50

typedef unsigned long long ull;

__device__ __forceinline__ float ex2(float x) {
    float r;
    asm("ex2.approx.f32 %0, %1;" : "=f"(r) : "f"(x));
    return r;
}
__device__ __forceinline__ unsigned cvt_tf32(float x) {
    unsigned r;
    asm("cvt.rna.tf32.f32 %0, %1;" : "=r"(r) : "f"(x));
    return r;
}
__device__ __forceinline__ void mma_tf32(float& c0, float& c1, float& c2, float& c3,
                                         unsigned a0, unsigned a1, unsigned a2, unsigned a3,
                                         unsigned b0, unsigned b1) {
    asm("mma.sync.aligned.m16n8k8.row.col.f32.tf32.tf32.f32 "
        "{%0,%1,%2,%3}, {%4,%5,%6,%7}, {%8,%9}, {%0,%1,%2,%3};"
        : "+f"(c0), "+f"(c1), "+f"(c2), "+f"(c3)
        : "r"(a0), "r"(a1), "r"(a2), "r"(a3), "r"(b0), "r"(b1));
}
__device__ __forceinline__ void cpa16(unsigned dst, const float* src) {
    asm volatile("cp.async.cg.shared.global [%0], [%1], 16;" :: "r"(dst), "l"(src));
}
#define CP_COMMIT() asm volatile("cp.async.commit_group;" ::: "memory")
#define CP_WAIT2()  asm volatile("cp.async.wait_group 2;" ::: "memory")
#define CP_WAIT1()  asm volatile("cp.async.wait_group 1;" ::: "memory")
#define CP_WAIT0()  asm volatile("cp.async.wait_group 0;" ::: "memory")

__device__ float g_kT[BB*DD*NN];   // per batch: [d][n], tf32-rounded
__device__ float g_v [BB*NN*DD];   // row-major [n][d], tf32-rounded
__device__ int   g_ctr[BB];        // producer doorbell (self-resetting)
__device__ int   g_done[BB];       // consumer done count (self-resetting)

#define XS_OFF  0
#define WP_OFF  16640
#define WT_OFF  35072
#define XP_OFF  48896
#define S_OFF    0
#define KB_OFF   16640
#define VA_OFF   33536
#define VB2_OFF  42752
#define QT_OFF   51968
#define REL_OFF  56576
#define RK_OFF   56640
#define WS_OFF   57152
#define INV_OFF  57408
#define SMEM_FLOATS 57472
#define SMEM_BYTES  (SMEM_FLOATS*4)

__device__ __forceinline__ void qk_chunk(
    float* S, const unsigned* qTb, const unsigned* KBu, const float* rel, const int* rk,
    int k0, int wc, int q, int g, int r0, int r1, int ri0, int ri1,
    float& rs0, float& rs1) {
    float acc[8][4];
#pragma unroll
    for (int cb = 0; cb < 8; cb++) {
        acc[cb][0] = 0.f; acc[cb][1] = 0.f; acc[cb][2] = 0.f; acc[cb][3] = 0.f;
    }
#pragma unroll
    for (int ks = 0; ks < 8; ks++) {
        unsigned a0 = qTb[(ks*8 + q)*72 + r0];
        unsigned a1 = qTb[(ks*8 + q)*72 + r1];
        unsigned a2 = qTb[(ks*8 + q + 4)*72 + r0];
        unsigned a3 = qTb[(ks*8 + q + 4)*72 + r1];
#pragma unroll
        for (int cb = 0; cb < 8; cb++) {
            int key0 = wc*64 + cb*8;
            unsigned b0 = KBu[(ks*8 + q)*264 + key0 + g];
            unsigned b1 = KBu[(ks*8 + q + 4)*264 + key0 + g];
            mma_tf32(acc[cb][0], acc[cb][1], acc[cb][2], acc[cb][3],
                     a0, a1, a2, a3, b0, b1);
        }
    }
#pragma unroll
    for (int cb = 0; cb < 8; cb++) {
        int kloc = wc*64 + cb*8 + 2*q;
        int ka = rk[k0 + kloc], kb = rk[k0 + kloc + 1];
        int d00 = ri0 - ka; d00 = d00 < 0 ? -d00 : d00; if (d00 > MAXDIST) d00 = MAXDIST;
        int d01 = ri0 - kb; d01 = d01 < 0 ? -d01 : d01; if (d01 > MAXDIST) d01 = MAXDIST;
        int d10 = ri1 - ka; d10 = d10 < 0 ? -d10 : d10; if (d10 > MAXDIST) d10 = MAXDIST;
        int d11 = ri1 - kb; d11 = d11 < 0 ? -d11 : d11; if (d11 > MAXDIST) d11 = MAXDIST;
        float f00 = __uint_as_float(cvt_tf32(ex2(acc[cb][0] * rel[d00])));
        float f01 = __uint_as_float(cvt_tf32(ex2(acc[cb][1] * rel[d01])));
        float f10 = __uint_as_float(cvt_tf32(ex2(acc[cb][2] * rel[d10])));
        float f11 = __uint_as_float(cvt_tf32(ex2(acc[cb][3] * rel[d11])));
        *(float2*)&S[r0*260 + kloc] = make_float2(f00, f01);
        *(float2*)&S[r1*260 + kloc] = make_float2(f10, f11);
        rs0 += f00 + f01;
        rs1 += f10 + f11;
    }
}

__device__ __forceinline__ void pv_half(
    const unsigned* Sb, const unsigned* VBu,
    int h, int wc, int q, int g, int r0, int r1, float (&accpv)[2][4]) {
#pragma unroll
    for (int ks = 0; ks < 16; ks++) {
        int kk = h*128 + ks*8;
        unsigned a0 = Sb[r0*260 + kk + q];
        unsigned a1 = Sb[r1*260 + kk + q];
        unsigned a2 = Sb[r0*260 + kk + q + 4];
        unsigned a3 = Sb[r1*260 + kk + q + 4];
#pragma unroll
        for (int cb = 0; cb < 2; cb++) {
            int d0 = wc*16 + cb*8;
            unsigned b0 = VBu[(ks*8 + q)*72 + d0 + g];
            unsigned b1 = VBu[(ks*8 + q + 4)*72 + d0 + g];
            mma_tf32(accpv[cb][0], accpv[cb][1], accpv[cb][2], accpv[cb][3],
                     a0, a1, a2, a3, b0, b1);
        }
    }
}

__global__ __launch_bounds__(512) void fused_kernel(
    const float* __restrict__ x, const int* __restrict__ ranks,
    const float* __restrict__ Wp, const float* __restrict__ bp,
    const float* __restrict__ Wq, const float* __restrict__ bq,
    const float* __restrict__ Wk, const float* __restrict__ bk,
    const float* __restrict__ Wv, const float* __restrict__ bv,
    const float* __restrict__ Eemb, const float* __restrict__ Wr1,
    const float* __restrict__ br1,  const float* __restrict__ Wr2,
    const float* __restrict__ Wf1, const float* __restrict__ bf1,
    const float* __restrict__ Wf2, const float* __restrict__ bf2,
    const float* __restrict__ ln_g, const float* __restrict__ ln_b,
    const float* __restrict__ Ws1, const float* __restrict__ bs1,
    const float* __restrict__ Ws2, const float* __restrict__ bs2,
    float* __restrict__ out) {
    extern __shared__ float sm[];
    const int tid = threadIdx.x;
    const int wp = tid >> 5, lane = tid & 31;
    const int g = lane >> 2, q = lane & 3;
    const int rb = wp >> 2, wc = wp & 3;
    const int r0 = rb*16 + g, r1 = r0 + 8;
    const int blk = blockIdx.x;
    const int b = blk >> 3;
    const int row0 = blk * 64;
    const int n0 = row0 & 511;
    const int q0 = n0;
    const int base = b * NN;
    const int bT = b * DD * NN;

    const unsigned sb = (unsigned)__cvta_generic_to_shared(sm);

    // ================= QKV PHASE =================
    {
        float* XS = sm + XS_OFF;
        float* WP = sm + WP_OFF;
        float* WT = sm + WT_OFF;
        float* XP = sm + XP_OFF;
        float* rel = sm + REL_OFF;
        int*   rk  = (int*)(sm + RK_OFF);

#pragma unroll
        for (int j = 0; j < 8; j++) {
            int idx = tid + j*512;
            int row = idx >> 6, f = idx & 63;
            cpa16(sb + (unsigned)((XS_OFF + row*260 + f*4)*4), &x[(row0 + row)*DIN + f*4]);
        }
        CP_COMMIT();
#pragma unroll
        for (int j = 0; j < 8; j++) {
            int idx = tid + j*512;
            int row = idx >> 4, f = idx & 15;
            cpa16(sb + (unsigned)((WP_OFF + row*72 + f*4)*4), &Wp[row*DD + f*4]);
        }
        CP_COMMIT();
#pragma unroll
        for (int j = 0; j < 6; j++) {
            int idx = tid + j*512;
            int t = idx >> 10, rem = idx & 1023;
            int row = rem >> 4, f = rem & 15;
            const float* src = (t == 0) ? Wk : (t == 1) ? Wv : Wq;
            cpa16(sb + (unsigned)((WT_OFF + t*4608 + row*72 + f*4)*4), &src[row*DD + f*4]);
        }
        CP_COMMIT();

        if (tid <= MAXDIST) {
            float e[EE];
#pragma unroll
            for (int c = 0; c < EE; c++) e[c] = Eemb[tid*EE + c];
            float w = 0.f;
#pragma unroll
            for (int j = 0; j < 16; j++) {
                float h = br1[j];
#pragma unroll
                for (int c = 0; c < EE; c++) h = fmaf(e[c], Wr1[c*16 + j], h);
                h = fmaxf(h, 0.f);
                w = fmaf(h, Wr2[j], w);
            }
            rel[tid] = 0.18033688011112042f / (1.f + __expf(-w));
        }
        if (tid < NN) rk[tid] = ranks[base + tid];

        CP_WAIT1(); __syncthreads();          // x + Wp ready

        float acc[2][4];
#pragma unroll
        for (int cb = 0; cb < 2; cb++) {
            acc[cb][0] = 0.f; acc[cb][1] = 0.f; acc[cb][2] = 0.f; acc[cb][3] = 0.f;
        }
#pragma unroll 4
        for (int ks = 0; ks < 32; ks++) {
            unsigned a0 = cvt_tf32(XS[r0*260 + ks*8 + q]);
            unsigned a1 = cvt_tf32(XS[r1*260 + ks*8 + q]);
            unsigned a2 = cvt_tf32(XS[r0*260 + ks*8 + q + 4]);
            unsigned a3 = cvt_tf32(XS[r1*260 + ks*8 + q + 4]);
#pragma unroll
            for (int cb = 0; cb < 2; cb++) {
                int nc = wc*16 + cb*8;
                unsigned b0 = cvt_tf32(WP[(ks*8 + q)*72 + nc + g]);
                unsigned b1 = cvt_tf32(WP[(ks*8 + q + 4)*72 + nc + g]);
                mma_tf32(acc[cb][0], acc[cb][1], acc[cb][2], acc[cb][3],
                         a0, a1, a2, a3, b0, b1);
            }
        }
        CP_WAIT0();
#pragma unroll
        for (int cb = 0; cb < 2; cb++) {
            int c = wc*16 + cb*8 + 2*q;
            float bp0 = bp[c], bp1 = bp[c + 1];
            XP[r0*68 + c]     = acc[cb][0] + bp0;
            XP[r0*68 + c + 1] = acc[cb][1] + bp1;
            XP[r1*68 + c]     = acc[cb][2] + bp0;
            XP[r1*68 + c + 1] = acc[cb][3] + bp1;
        }
        __syncthreads();

        // Phase B: k then v (to global), signal, then q (to local smem)
#pragma unroll
        for (int t = 0; t < 2; t++) {
            const float* W = WT + t*4608;
            const float* bs = (t == 0) ? bk : bv;
            float o[2][4];
#pragma unroll
            for (int cb = 0; cb < 2; cb++) {
                o[cb][0] = 0.f; o[cb][1] = 0.f; o[cb][2] = 0.f; o[cb][3] = 0.f;
            }
#pragma unroll
            for (int ks = 0; ks < 8; ks++) {
                unsigned a0 = cvt_tf32(XP[r0*68 + ks*8 + q]);
                unsigned a1 = cvt_tf32(XP[r1*68 + ks*8 + q]);
                unsigned a2 = cvt_tf32(XP[r0*68 + ks*8 + q + 4]);
                unsigned a3 = cvt_tf32(XP[r1*68 + ks*8 + q + 4]);
#pragma unroll
                for (int cb = 0; cb < 2; cb++) {
                    int nc = wc*16 + cb*8;
                    unsigned b0 = cvt_tf32(W[(ks*8 + q)*72 + nc + g]);
                    unsigned b1 = cvt_tf32(W[(ks*8 + q + 4)*72 + nc + g]);
                    mma_tf32(o[cb][0], o[cb][1], o[cb][2], o[cb][3],
                             a0, a1, a2, a3, b0, b1);
                }
            }
            if (t == 1) {
#pragma unroll
                for (int cb = 0; cb < 2; cb++) {
                    int c = wc*16 + cb*8 + 2*q;
                    float v0 = __uint_as_float(cvt_tf32(o[cb][0] + bs[c]));
                    float v1 = __uint_as_float(cvt_tf32(o[cb][1] + bs[c + 1]));
                    float v2 = __uint_as_float(cvt_tf32(o[cb][2] + bs[c]));
                    float v3 = __uint_as_float(cvt_tf32(o[cb][3] + bs[c + 1]));
                    *(float2*)&g_v[(row0 + r0)*DD + c] = make_float2(v0, v1);
                    *(float2*)&g_v[(row0 + r1)*DD + c] = make_float2(v2, v3);
                }
            } else {
#pragma unroll
                for (int cb = 0; cb < 2; cb++) {
                    int c = wc*16 + cb*8 + 2*q;
                    g_kT[bT + c*NN + n0 + r0]       = __uint_as_float(cvt_tf32(o[cb][0] + bs[c]));
                    g_kT[bT + (c + 1)*NN + n0 + r0] = __uint_as_float(cvt_tf32(o[cb][1] + bs[c + 1]));
                    g_kT[bT + c*NN + n0 + r1]       = __uint_as_float(cvt_tf32(o[cb][2] + bs[c]));
                    g_kT[bT + (c + 1)*NN + n0 + r1] = __uint_as_float(cvt_tf32(o[cb][3] + bs[c + 1]));
                }
            }
        }
        __syncthreads();
        if (tid == 0) {
            __threadfence();
            atomicAdd(&g_ctr[b], 1);
        }

        // q (local)
        {
            const float* W = WT + 2*4608;
            float o[2][4];
#pragma unroll
            for (int cb = 0; cb < 2; cb++) {
                o[cb][0] = 0.f; o[cb][1] = 0.f; o[cb][2] = 0.f; o[cb][3] = 0.f;
            }
#pragma unroll
            for (int ks = 0; ks < 8; ks++) {
                unsigned a0 = cvt_tf32(XP[r0*68 + ks*8 + q]);
                unsigned a1 = cvt_tf32(XP[r1*68 + ks*8 + q]);
                unsigned a2 = cvt_tf32(XP[r0*68 + ks*8 + q + 4]);
                unsigned a3 = cvt_tf32(XP[r1*68 + ks*8 + q + 4]);
#pragma unroll
                for (int cb = 0; cb < 2; cb++) {
                    int nc = wc*16 + cb*8;
                    unsigned b0 = cvt_tf32(W[(ks*8 + q)*72 + nc + g]);
                    unsigned b1 = cvt_tf32(W[(ks*8 + q + 4)*72 + nc + g]);
                    mma_tf32(o[cb][0], o[cb][1], o[cb][2], o[cb][3],
                             a0, a1, a2, a3, b0, b1);
                }
            }
            __syncthreads();
            unsigned* qTu = (unsigned*)(sm + QT_OFF);
#pragma unroll
            for (int cb = 0; cb < 2; cb++) {
                int c = wc*16 + cb*8 + 2*q;
                qTu[c*72 + r0]       = cvt_tf32(o[cb][0] + bq[c]);
                qTu[(c + 1)*72 + r0] = cvt_tf32(o[cb][1] + bq[c + 1]);
                qTu[c*72 + r1]       = cvt_tf32(o[cb][2] + bq[c]);
                qTu[(c + 1)*72 + r1] = cvt_tf32(o[cb][3] + bq[c + 1]);
            }
        }
    }

    // ---- wait for all 8 producer tiles of this batch ----
    if (tid == 0) {
        volatile int* c = &g_ctr[b];
        while (*c < 8) {}
        __threadfence();
    }
    __syncthreads();

    // ================= ATTN PHASE =================
    {
        float* S    = sm + S_OFF;
        float* KB   = sm + KB_OFF;
        float* VAf  = sm + VA_OFF;
        float* VBf  = sm + VB2_OFF;
        float* qTf  = sm + QT_OFF;
        float* rel  = sm + REL_OFF;
        int*   rk   = (int*)(sm + RK_OFF);
        float* wsum = sm + WS_OFF;
        float* invs = sm + INV_OFF;
        float* wsq  = sm + 11264;
        const unsigned* qTb = (const unsigned*)qTf;
        const unsigned* Sb  = (const unsigned*)S;
        const unsigned* KBu = (const unsigned*)KB;
        const unsigned* VAu = (const unsigned*)VAf;
        const unsigned* VBu = (const unsigned*)VBf;
        const unsigned kbA = sb + KB_OFF*4;
        const unsigned vaA = sb + VA_OFF*4;
        const unsigned vbA = sb + VB2_OFF*4;

#pragma unroll
        for (int j = 0; j < 8; j++) {
            int idx = tid + j*512;
            int d = idx >> 6, f = idx & 63;
            cpa16(kbA + (unsigned)((d*264 + f*4)*4), &g_kT[bT + d*NN + f*4]);
        }
        CP_COMMIT();                                          // grp1: K0
#pragma unroll
        for (int j = 0; j < 4; j++) {
            int idx = tid + j*512;
            int key = idx >> 4, f = idx & 15;
            cpa16(vaA + (unsigned)((key*72 + f*4)*4), &g_v[(base + key)*DD + f*4]);
        }
        CP_COMMIT();                                          // grp2: Va
#pragma unroll
        for (int j = 0; j < 4; j++) {
            int idx = tid + j*512;
            int key = idx >> 4, f = idx & 15;
            cpa16(vbA + (unsigned)((key*72 + f*4)*4), &g_v[(base + 128 + key)*DD + f*4]);
        }
        CP_COMMIT();                                          // grp3: Vb

        float rs0 = 0.f, rs1 = 0.f;
        float accpv[2][4];
#pragma unroll
        for (int c = 0; c < 2; c++) {
            accpv[c][0] = 0.f; accpv[c][1] = 0.f; accpv[c][2] = 0.f; accpv[c][3] = 0.f;
        }

        CP_WAIT2(); __syncthreads();                           // K0 ready
        const int ri0 = rk[q0 + r0], ri1 = rk[q0 + r1];

        qk_chunk(S, qTb, KBu, rel, rk, 0, wc, q, g, r0, r1, ri0, ri1, rs0, rs1);
        __syncthreads();                                       // S0 ready, KB free

#pragma unroll
        for (int j = 0; j < 8; j++) {
            int idx = tid + j*512;
            int d = idx >> 6, f = idx & 63;
            cpa16(kbA + (unsigned)((d*264 + f*4)*4), &g_kT[bT + d*NN + 256 + f*4]);
        }
        CP_COMMIT();                                          // grp4: K1

        CP_WAIT2(); __syncthreads();                           // Va ready
        pv_half(Sb, VAu, 0, wc, q, g, r0, r1, accpv);
        CP_WAIT1(); __syncthreads();                           // Vb ready, VA free
#pragma unroll
        for (int j = 0; j < 4; j++) {
            int idx = tid + j*512;
            int key = idx >> 4, f = idx & 15;
            cpa16(vaA + (unsigned)((key*72 + f*4)*4), &g_v[(base + 256 + key)*DD + f*4]);
        }
        CP_COMMIT();                                          // grp5: Va2
        pv_half(Sb, VBu, 1, wc, q, g, r0, r1, accpv);
        __syncthreads();                                       // VB free, S free
#pragma unroll
        for (int j = 0; j < 4; j++) {
            int idx = tid + j*512;
            int key = idx >> 4, f = idx & 15;
            cpa16(vbA + (unsigned)((key*72 + f*4)*4), &g_v[(base + 384 + key)*DD + f*4]);
        }
        CP_COMMIT();                                          // grp6: Vb2
        CP_WAIT2(); __syncthreads();                           // K1 ready

        qk_chunk(S, qTb, KBu, rel, rk, 256, wc, q, g, r0, r1, ri0, ri1, rs0, rs1);
        {
            rs0 += __shfl_xor_sync(0xffffffffu, rs0, 1);
            rs0 += __shfl_xor_sync(0xffffffffu, rs0, 2);
            rs1 += __shfl_xor_sync(0xffffffffu, rs1, 1);
            rs1 += __shfl_xor_sync(0xffffffffu, rs1, 2);
            if (q == 0) {
                wsum[wc*64 + r0] = rs0;
                wsum[wc*64 + r1] = rs1;
            }
        }
        __syncthreads();
        if (tid < 64)
            invs[tid] = 1.f / (wsum[tid] + wsum[64 + tid] + wsum[128 + tid] + wsum[192 + tid]);
#pragma unroll
        for (int j = 0; j < 8; j++) {
            int idx = tid + j*512;
            int k = idx >> 5, f = idx & 31;
            cpa16(kbA + (unsigned)((k*132 + f*4)*4), &Wf1[k*128 + f*4]);
        }
        CP_COMMIT();                                          // grp7: w1

        CP_WAIT2(); __syncthreads();                           // Va2 ready (+invs)
        pv_half(Sb, VAu, 0, wc, q, g, r0, r1, accpv);
        CP_WAIT1(); __syncthreads();                           // Vb2 ready
        pv_half(Sb, VBu, 1, wc, q, g, r0, r1, accpv);
        CP_WAIT0();
        __syncthreads();                                       // w1 ready, PV done

        // issue Wf2 -> VA [128][72], ws1/ws2 -> VB (overlap PV epi + FFN1)
#pragma unroll
        for (int j = 0; j < 4; j++) {
            int idx = tid + j*512;
            int k = idx >> 4, f = idx & 15;
            cpa16(vaA + (unsigned)((k*72 + f*4)*4), &Wf2[k*64 + f*4]);
        }
        cpa16(vbA + (unsigned)(tid*16), &Ws1[tid*4]);
        if (tid < 8) cpa16(vbA + (unsigned)((2048 + tid*4)*4), &Ws2[tid*4]);
        CP_COMMIT();                                          // grp8

        // PV epilogue: 1/sum, aoT(tf32) -> qTf
        {
            unsigned* aoT = (unsigned*)qTf;
            float iv0 = invs[r0], iv1 = invs[r1];
#pragma unroll
            for (int cb = 0; cb < 2; cb++) {
                int dc = wc*16 + cb*8 + 2*q;
                aoT[dc*68 + r0]       = cvt_tf32(accpv[cb][0] * iv0);
                aoT[(dc + 1)*68 + r0] = cvt_tf32(accpv[cb][1] * iv0);
                aoT[dc*68 + r1]       = cvt_tf32(accpv[cb][2] * iv1);
                aoT[(dc + 1)*68 + r1] = cvt_tf32(accpv[cb][3] * iv1);
            }
        }
        __syncthreads();

        // FFN1: tf32 mma, M64 N128 K64
        {
            const unsigned* aoT = (const unsigned*)qTf;
            float f1[4][4];
#pragma unroll
            for (int cb = 0; cb < 4; cb++) {
                f1[cb][0] = 0.f; f1[cb][1] = 0.f; f1[cb][2] = 0.f; f1[cb][3] = 0.f;
            }
#pragma unroll
            for (int ks = 0; ks < 8; ks++) {
                unsigned a0 = aoT[(ks*8 + q)*68 + r0];
                unsigned a1 = aoT[(ks*8 + q)*68 + r1];
                unsigned a2 = aoT[(ks*8 + q + 4)*68 + r0];
                unsigned a3 = aoT[(ks*8 + q + 4)*68 + r1];
#pragma unroll
                for (int cb = 0; cb < 4; cb++) {
                    int nc = wc*32 + cb*8;
                    unsigned b0 = cvt_tf32(KB[(ks*8 + q)*132 + nc + g]);
                    unsigned b1 = cvt_tf32(KB[(ks*8 + q + 4)*132 + nc + g]);
                    mma_tf32(f1[cb][0], f1[cb][1], f1[cb][2], f1[cb][3],
                             a0, a1, a2, a3, b0, b1);
                }
            }
            unsigned* h1T = (unsigned*)S;
#pragma unroll
            for (int cb = 0; cb < 4; cb++) {
                int c = wc*32 + cb*8 + 2*q;
                float bc0 = bf1[c], bc1 = bf1[c + 1];
                h1T[c*68 + r0]       = cvt_tf32(fmaxf(f1[cb][0] + bc0, 0.f));
                h1T[(c + 1)*68 + r0] = cvt_tf32(fmaxf(f1[cb][1] + bc1, 0.f));
                h1T[c*68 + r1]       = cvt_tf32(fmaxf(f1[cb][2] + bc0, 0.f));
                h1T[(c + 1)*68 + r1] = cvt_tf32(fmaxf(f1[cb][3] + bc1, 0.f));
            }
        }
        CP_WAIT0();                                            // Wf2 + ws arrived
        __syncthreads();                                       // h1T + VA/VB visible

        // FFN2 + LayerNorm, M64 N64 K128 (B from VA stride 72, conflict-free)
        {
            const unsigned* h1T = (const unsigned*)S;
            float f2[2][4];
            f2[0][0] = f2[0][1] = f2[0][2] = f2[0][3] = 0.f;
            f2[1][0] = f2[1][1] = f2[1][2] = f2[1][3] = 0.f;
#pragma unroll
            for (int ks = 0; ks < 16; ks++) {
                unsigned a0 = h1T[(ks*8 + q)*68 + r0];
                unsigned a1 = h1T[(ks*8 + q)*68 + r1];
                unsigned a2 = h1T[(ks*8 + q + 4)*68 + r0];
                unsigned a3 = h1T[(ks*8 + q + 4)*68 + r1];
#pragma unroll
                for (int cb = 0; cb < 2; cb++) {
                    int nc = wc*16 + cb*8;
                    unsigned b0 = cvt_tf32(VAf[(ks*8 + q)*72 + nc + g]);
                    unsigned b1 = cvt_tf32(VAf[(ks*8 + q + 4)*72 + nc + g]);
                    mma_tf32(f2[cb][0], f2[cb][1], f2[cb][2], f2[cb][3],
                             a0, a1, a2, a3, b0, b1);
                }
            }
            float e[2][4];
            float s0 = 0.f, q0s = 0.f, s1v = 0.f, q1s = 0.f;
#pragma unroll
            for (int cb = 0; cb < 2; cb++) {
                int c = wc*16 + cb*8 + 2*q;
                e[cb][0] = f2[cb][0] + bf2[c];
                e[cb][1] = f2[cb][1] + bf2[c + 1];
                e[cb][2] = f2[cb][2] + bf2[c];
                e[cb][3] = f2[cb][3] + bf2[c + 1];
                s0  += e[cb][0] + e[cb][1];
                q0s += e[cb][0]*e[cb][0] + e[cb][1]*e[cb][1];
                s1v += e[cb][2] + e[cb][3];
                q1s += e[cb][2]*e[cb][2] + e[cb][3]*e[cb][3];
            }
#pragma unroll
            for (int o = 1; o <= 2; o <<= 1) {
                s0  += __shfl_xor_sync(0xffffffffu, s0,  o);
                q0s += __shfl_xor_sync(0xffffffffu, q0s, o);
                s1v += __shfl_xor_sync(0xffffffffu, s1v, o);
                q1s += __shfl_xor_sync(0xffffffffu, q1s, o);
            }
            if (q == 0) {
                wsum[wc*64 + r0] = s0;  wsq[wc*64 + r0] = q0s;
                wsum[wc*64 + r1] = s1v; wsq[wc*64 + r1] = q1s;
            }
            __syncthreads();
            float S0 = wsum[r0] + wsum[64 + r0] + wsum[128 + r0] + wsum[192 + r0];
            float Q0 = wsq[r0]  + wsq[64 + r0]  + wsq[128 + r0]  + wsq[192 + r0];
            float S1 = wsum[r1] + wsum[64 + r1] + wsum[128 + r1] + wsum[192 + r1];
            float Q1 = wsq[r1]  + wsq[64 + r1]  + wsq[128 + r1]  + wsq[192 + r1];
            float mu0 = S0 * (1.f/64.f), mu1 = S1 * (1.f/64.f);
            float in0 = rsqrtf(Q0 * (1.f/64.f) - mu0*mu0 + 1e-5f);
            float in1 = rsqrtf(Q1 * (1.f/64.f) - mu1*mu1 + 1e-5f);
#pragma unroll
            for (int cb = 0; cb < 2; cb++) {
                int c = wc*16 + cb*8 + 2*q;
                float g0v = ln_g[c], g1v = ln_g[c + 1];
                float be0 = ln_b[c], be1 = ln_b[c + 1];
                qTf[c*68 + r0]       = (e[cb][0] - mu0)*in0*g0v + be0;
                qTf[(c + 1)*68 + r0] = (e[cb][1] - mu0)*in0*g1v + be1;
                qTf[c*68 + r1]       = (e[cb][2] - mu1)*in1*g0v + be0;
                qTf[(c + 1)*68 + r1] = (e[cb][3] - mu1)*in1*g1v + be1;
            }
        }
        __syncthreads();

        // head: all 512 threads, 2 rows per 16-lane slot
        {
            const int slot = tid >> 4;          // 0..31 -> rows slot*2, slot*2+1
            const int tx4 = tid & 15;
            float s1[2][2];
            s1[0][0] = s1[0][1] = s1[1][0] = s1[1][1] = 0.f;
#pragma unroll 4
            for (int kk = 0; kk < 64; kk++) {
                float2 a = *(const float2*)&qTf[kk*68 + slot*2];
                float w0 = VBf[kk*32 + tx4*2], w1b = VBf[kk*32 + tx4*2 + 1];
                s1[0][0] = fmaf(a.x, w0, s1[0][0]); s1[0][1] = fmaf(a.x, w1b, s1[0][1]);
                s1[1][0] = fmaf(a.y, w0, s1[1][0]); s1[1][1] = fmaf(a.y, w1b, s1[1][1]);
            }
            float w2a = VBf[2048 + tx4*2], w2b = VBf[2048 + tx4*2 + 1];
            float ba = bs1[tx4*2], bb = bs1[tx4*2 + 1];
            float bs2v = bs2[0];
#pragma unroll
            for (int r = 0; r < 2; r++) {
                float pa = fmaxf(s1[r][0] + ba, 0.f);
                float pb = fmaxf(s1[r][1] + bb, 0.f);
                float p = pa*w2a + pb*w2b;
#pragma unroll
                for (int o = 8; o >= 1; o >>= 1) p += __shfl_xor_sync(0xffffffffu, p, o, 16);
                if (tx4 == 0) {
                    float z = p + bs2v;
                    out[base + q0 + slot*2 + r] = 1.f / (1.f + __expf(-z));
                }
            }
        }
    }

    // ---- self-resetting counters for graph replay ----
    __syncthreads();
    if (tid == 0) {
        int d = atomicAdd(&g_done[b], 1);
        if (d == 7) {
            g_ctr[b] = 0;
            g_done[b] = 0;
            __threadfence();
        }
    }
}

// ============================================================
extern "C" void kernel_launch(void* const* d_in, const int* in_sizes, int n_in,
                              void* d_out, int out_size) {
    const float* x     = (const float*)d_in[0];
    const int*   ranks = (const int*)  d_in[1];
    const float* Wp    = (const float*)d_in[2];
    const float* bp    = (const float*)d_in[3];
    const float* Wq    = (const float*)d_in[4];
    const float* bq    = (const float*)d_in[5];
    const float* Wk    = (const float*)d_in[6];
    const float* bk    = (const float*)d_in[7];
    const float* Wv    = (const float*)d_in[8];
    const float* bv    = (const float*)d_in[9];
    const float* Eemb  = (const float*)d_in[10];
    const float* Wr1   = (const float*)d_in[11];
    const float* br1   = (const float*)d_in[12];
    const float* Wr2   = (const float*)d_in[13];
    const float* Wf1   = (const float*)d_in[14];
    const float* bf1   = (const float*)d_in[15];
    const float* Wf2   = (const float*)d_in[16];
    const float* bf2   = (const float*)d_in[17];
    const float* ln_g  = (const float*)d_in[18];
    const float* ln_b  = (const float*)d_in[19];
    const float* Ws1   = (const float*)d_in[20];
    const float* bs1   = (const float*)d_in[21];
    const float* Ws2   = (const float*)d_in[22];
    const float* bs2   = (const float*)d_in[23];
    float* out = (float*)d_out;

    cudaFuncSetAttribute(fused_kernel, cudaFuncAttributeMaxDynamicSharedMemorySize, SMEM_BYTES);

    fused_kernel<<<BB*NN/64, 512, SMEM_BYTES>>>(
        x, ranks, Wp, bp, Wq, bq, Wk, bk, Wv, bv,
        Eemb, Wr1, br1, Wr2, Wf1, bf1, Wf2, bf2,
        ln_g, ln_b, Ws1, bs1, Ws2, bs2, out);
}

// round 15
// speedup vs baseline: 2.2483x; 1.0060x over previous
#include <cuda_runtime.h>

#define BB   16
#define NN   512
#define DIN  256
#define DD   64
#define EE   32
#define MAXDIST 50

typedef unsigned long long ull;

__device__ __forceinline__ float ex2(float x) {
    float r;
    asm("ex2.approx.f32 %0, %1;" : "=f"(r) : "f"(x));
    return r;
}
__device__ __forceinline__ unsigned cvt_tf32(float x) {
    unsigned r;
    asm("cvt.rna.tf32.f32 %0, %1;" : "=r"(r) : "f"(x));
    return r;
}
__device__ __forceinline__ void mma_tf32(float& c0, float& c1, float& c2, float& c3,
                                         unsigned a0, unsigned a1, unsigned a2, unsigned a3,
                                         unsigned b0, unsigned b1) {
    asm("mma.sync.aligned.m16n8k8.row.col.f32.tf32.tf32.f32 "
        "{%0,%1,%2,%3}, {%4,%5,%6,%7}, {%8,%9}, {%0,%1,%2,%3};"
        : "+f"(c0), "+f"(c1), "+f"(c2), "+f"(c3)
        : "r"(a0), "r"(a1), "r"(a2), "r"(a3), "r"(b0), "r"(b1));
}
__device__ __forceinline__ void cpa16(unsigned dst, const float* src) {
    asm volatile("cp.async.cg.shared.global [%0], [%1], 16;" :: "r"(dst), "l"(src));
}
#define CP_COMMIT() asm volatile("cp.async.commit_group;" ::: "memory")
#define CP_WAIT2()  asm volatile("cp.async.wait_group 2;" ::: "memory")
#define CP_WAIT1()  asm volatile("cp.async.wait_group 1;" ::: "memory")
#define CP_WAIT0()  asm volatile("cp.async.wait_group 0;" ::: "memory")

__device__ float g_kT[BB*DD*NN];   // per batch: [d][n], tf32-rounded
__device__ float g_v [BB*NN*DD];   // row-major [n][d], tf32-rounded
__device__ int   g_ctr[BB];        // producer doorbell (self-resetting)
__device__ int   g_done[BB];       // consumer done count (self-resetting)

#define XS_OFF  0
#define WP_OFF  16640
#define WT_OFF  35072
#define XP_OFF  48896
#define S_OFF    0
#define KB_OFF   16640
#define VA_OFF   33536
#define VB2_OFF  42752
#define QT_OFF   51968
#define REL_OFF  56576
#define RK_OFF   56640
#define WS_OFF   57152
#define INV_OFF  57408
#define SMEM_FLOATS 57472
#define SMEM_BYTES  (SMEM_FLOATS*4)

__device__ __forceinline__ void qk_chunk(
    float* S, const unsigned* qTb, const unsigned* KBu, const float* rel, const int* rk,
    int k0, int wc, int q, int g, int r0, int r1, int ri0, int ri1,
    float& rs0, float& rs1) {
    float acc[8][4];
#pragma unroll
    for (int cb = 0; cb < 8; cb++) {
        acc[cb][0] = 0.f; acc[cb][1] = 0.f; acc[cb][2] = 0.f; acc[cb][3] = 0.f;
    }
#pragma unroll
    for (int ks = 0; ks < 8; ks++) {
        unsigned a0 = qTb[(ks*8 + q)*72 + r0];
        unsigned a1 = qTb[(ks*8 + q)*72 + r1];
        unsigned a2 = qTb[(ks*8 + q + 4)*72 + r0];
        unsigned a3 = qTb[(ks*8 + q + 4)*72 + r1];
#pragma unroll
        for (int cb = 0; cb < 8; cb++) {
            int key0 = wc*64 + cb*8;
            unsigned b0 = KBu[(ks*8 + q)*264 + key0 + g];
            unsigned b1 = KBu[(ks*8 + q + 4)*264 + key0 + g];
            mma_tf32(acc[cb][0], acc[cb][1], acc[cb][2], acc[cb][3],
                     a0, a1, a2, a3, b0, b1);
        }
    }
#pragma unroll
    for (int cb = 0; cb < 8; cb++) {
        int kloc = wc*64 + cb*8 + 2*q;
        int ka = rk[k0 + kloc], kb = rk[k0 + kloc + 1];
        int d00 = ri0 - ka; d00 = d00 < 0 ? -d00 : d00; if (d00 > MAXDIST) d00 = MAXDIST;
        int d01 = ri0 - kb; d01 = d01 < 0 ? -d01 : d01; if (d01 > MAXDIST) d01 = MAXDIST;
        int d10 = ri1 - ka; d10 = d10 < 0 ? -d10 : d10; if (d10 > MAXDIST) d10 = MAXDIST;
        int d11 = ri1 - kb; d11 = d11 < 0 ? -d11 : d11; if (d11 > MAXDIST) d11 = MAXDIST;
        float f00 = __uint_as_float(cvt_tf32(ex2(acc[cb][0] * rel[d00])));
        float f01 = __uint_as_float(cvt_tf32(ex2(acc[cb][1] * rel[d01])));
        float f10 = __uint_as_float(cvt_tf32(ex2(acc[cb][2] * rel[d10])));
        float f11 = __uint_as_float(cvt_tf32(ex2(acc[cb][3] * rel[d11])));
        *(float2*)&S[r0*260 + kloc] = make_float2(f00, f01);
        *(float2*)&S[r1*260 + kloc] = make_float2(f10, f11);
        rs0 += f00 + f01;
        rs1 += f10 + f11;
    }
}

__device__ __forceinline__ void pv_half(
    const unsigned* Sb, const unsigned* VBu,
    int h, int wc, int q, int g, int r0, int r1, float (&accpv)[2][4]) {
#pragma unroll
    for (int ks = 0; ks < 16; ks++) {
        int kk = h*128 + ks*8;
        unsigned a0 = Sb[r0*260 + kk + q];
        unsigned a1 = Sb[r1*260 + kk + q];
        unsigned a2 = Sb[r0*260 + kk + q + 4];
        unsigned a3 = Sb[r1*260 + kk + q + 4];
#pragma unroll
        for (int cb = 0; cb < 2; cb++) {
            int d0 = wc*16 + cb*8;
            unsigned b0 = VBu[(ks*8 + q)*72 + d0 + g];
            unsigned b1 = VBu[(ks*8 + q + 4)*72 + d0 + g];
            mma_tf32(accpv[cb][0], accpv[cb][1], accpv[cb][2], accpv[cb][3],
                     a0, a1, a2, a3, b0, b1);
        }
    }
}

__global__ __launch_bounds__(512) void fused_kernel(
    const float* __restrict__ x, const int* __restrict__ ranks,
    const float* __restrict__ Wp, const float* __restrict__ bp,
    const float* __restrict__ Wq, const float* __restrict__ bq,
    const float* __restrict__ Wk, const float* __restrict__ bk,
    const float* __restrict__ Wv, const float* __restrict__ bv,
    const float* __restrict__ Eemb, const float* __restrict__ Wr1,
    const float* __restrict__ br1,  const float* __restrict__ Wr2,
    const float* __restrict__ Wf1, const float* __restrict__ bf1,
    const float* __restrict__ Wf2, const float* __restrict__ bf2,
    const float* __restrict__ ln_g, const float* __restrict__ ln_b,
    const float* __restrict__ Ws1, const float* __restrict__ bs1,
    const float* __restrict__ Ws2, const float* __restrict__ bs2,
    float* __restrict__ out) {
    extern __shared__ float sm[];
    const int tid = threadIdx.x;
    const int wp = tid >> 5, lane = tid & 31;
    const int g = lane >> 2, q = lane & 3;
    const int rb = wp >> 2, wc = wp & 3;
    const int r0 = rb*16 + g, r1 = r0 + 8;
    const int blk = blockIdx.x;
    const int b = blk >> 3;
    const int row0 = blk * 64;
    const int n0 = row0 & 511;
    const int q0 = n0;
    const int base = b * NN;
    const int bT = b * DD * NN;

    const unsigned sb = (unsigned)__cvta_generic_to_shared(sm);
    const unsigned kbA = sb + KB_OFF*4;
    const unsigned vaA = sb + VA_OFF*4;
    const unsigned vbA = sb + VB2_OFF*4;

    // ================= QKV PHASE =================
    {
        float* XS = sm + XS_OFF;
        float* WP = sm + WP_OFF;
        float* WT = sm + WT_OFF;
        unsigned* XSu = (unsigned*)XS;
        unsigned* WPu = (unsigned*)WP;
        unsigned* WTu = (unsigned*)WT;
        unsigned* XPu = (unsigned*)(sm + XP_OFF);
        float* rel = sm + REL_OFF;
        int*   rk  = (int*)(sm + RK_OFF);

#pragma unroll
        for (int j = 0; j < 8; j++) {
            int idx = tid + j*512;
            int row = idx >> 6, f = idx & 63;
            cpa16(sb + (unsigned)((XS_OFF + row*260 + f*4)*4), &x[(row0 + row)*DIN + f*4]);
        }
        CP_COMMIT();
#pragma unroll
        for (int j = 0; j < 8; j++) {
            int idx = tid + j*512;
            int row = idx >> 4, f = idx & 15;
            cpa16(sb + (unsigned)((WP_OFF + row*72 + f*4)*4), &Wp[row*DD + f*4]);
        }
        CP_COMMIT();
#pragma unroll
        for (int j = 0; j < 6; j++) {
            int idx = tid + j*512;
            int t = idx >> 10, rem = idx & 1023;
            int row = rem >> 4, f = rem & 15;
            const float* src = (t == 0) ? Wk : (t == 1) ? Wv : Wq;
            cpa16(sb + (unsigned)((WT_OFF + t*4608 + row*72 + f*4)*4), &src[row*DD + f*4]);
        }
        CP_COMMIT();

        if (tid <= MAXDIST) {
            float e[EE];
#pragma unroll
            for (int c = 0; c < EE; c++) e[c] = Eemb[tid*EE + c];
            float w = 0.f;
#pragma unroll
            for (int j = 0; j < 16; j++) {
                float h = br1[j];
#pragma unroll
                for (int c = 0; c < EE; c++) h = fmaf(e[c], Wr1[c*16 + j], h);
                h = fmaxf(h, 0.f);
                w = fmaf(h, Wr2[j], w);
            }
            rel[tid] = 0.18033688011112042f / (1.f + __expf(-w));
        }
        if (tid < NN) rk[tid] = ranks[base + tid];

        CP_WAIT1(); __syncthreads();          // x + Wp ready

        // pre-convert XS + WP to tf32 in place (bit-identical to per-read cvt)
        for (int idx = tid; idx < 16640; idx += 512) XSu[idx] = cvt_tf32(XS[idx]);
        for (int idx = tid; idx < 18432; idx += 512) WPu[idx] = cvt_tf32(WP[idx]);
        __syncthreads();

        // Phase A: xp = x @ Wp
        float acc[2][4];
#pragma unroll
        for (int cb = 0; cb < 2; cb++) {
            acc[cb][0] = 0.f; acc[cb][1] = 0.f; acc[cb][2] = 0.f; acc[cb][3] = 0.f;
        }
#pragma unroll 4
        for (int ks = 0; ks < 32; ks++) {
            unsigned a0 = XSu[r0*260 + ks*8 + q];
            unsigned a1 = XSu[r1*260 + ks*8 + q];
            unsigned a2 = XSu[r0*260 + ks*8 + q + 4];
            unsigned a3 = XSu[r1*260 + ks*8 + q + 4];
#pragma unroll
            for (int cb = 0; cb < 2; cb++) {
                int nc = wc*16 + cb*8;
                unsigned b0 = WPu[(ks*8 + q)*72 + nc + g];
                unsigned b1 = WPu[(ks*8 + q + 4)*72 + nc + g];
                mma_tf32(acc[cb][0], acc[cb][1], acc[cb][2], acc[cb][3],
                         a0, a1, a2, a3, b0, b1);
            }
        }
        CP_WAIT0();
        // XP written pre-converted to tf32
#pragma unroll
        for (int cb = 0; cb < 2; cb++) {
            int c = wc*16 + cb*8 + 2*q;
            float bp0 = bp[c], bp1 = bp[c + 1];
            XPu[r0*68 + c]     = cvt_tf32(acc[cb][0] + bp0);
            XPu[r0*68 + c + 1] = cvt_tf32(acc[cb][1] + bp1);
            XPu[r1*68 + c]     = cvt_tf32(acc[cb][2] + bp0);
            XPu[r1*68 + c + 1] = cvt_tf32(acc[cb][3] + bp1);
        }
        __syncthreads();                      // WT visible + XP visible
        // pre-convert WT
        for (int idx = tid; idx < 13824; idx += 512) WTu[idx] = cvt_tf32(WT[idx]);
        __syncthreads();

        // Phase B: k then v (to global), signal
#pragma unroll
        for (int t = 0; t < 2; t++) {
            const unsigned* W = WTu + t*4608;
            const float* bs = (t == 0) ? bk : bv;
            float o[2][4];
#pragma unroll
            for (int cb = 0; cb < 2; cb++) {
                o[cb][0] = 0.f; o[cb][1] = 0.f; o[cb][2] = 0.f; o[cb][3] = 0.f;
            }
#pragma unroll
            for (int ks = 0; ks < 8; ks++) {
                unsigned a0 = XPu[r0*68 + ks*8 + q];
                unsigned a1 = XPu[r1*68 + ks*8 + q];
                unsigned a2 = XPu[r0*68 + ks*8 + q + 4];
                unsigned a3 = XPu[r1*68 + ks*8 + q + 4];
#pragma unroll
                for (int cb = 0; cb < 2; cb++) {
                    int nc = wc*16 + cb*8;
                    unsigned b0 = W[(ks*8 + q)*72 + nc + g];
                    unsigned b1 = W[(ks*8 + q + 4)*72 + nc + g];
                    mma_tf32(o[cb][0], o[cb][1], o[cb][2], o[cb][3],
                             a0, a1, a2, a3, b0, b1);
                }
            }
            if (t == 1) {
#pragma unroll
                for (int cb = 0; cb < 2; cb++) {
                    int c = wc*16 + cb*8 + 2*q;
                    float v0 = __uint_as_float(cvt_tf32(o[cb][0] + bs[c]));
                    float v1 = __uint_as_float(cvt_tf32(o[cb][1] + bs[c + 1]));
                    float v2 = __uint_as_float(cvt_tf32(o[cb][2] + bs[c]));
                    float v3 = __uint_as_float(cvt_tf32(o[cb][3] + bs[c + 1]));
                    *(float2*)&g_v[(row0 + r0)*DD + c] = make_float2(v0, v1);
                    *(float2*)&g_v[(row0 + r1)*DD + c] = make_float2(v2, v3);
                }
            } else {
#pragma unroll
                for (int cb = 0; cb < 2; cb++) {
                    int c = wc*16 + cb*8 + 2*q;
                    g_kT[bT + c*NN + n0 + r0]       = __uint_as_float(cvt_tf32(o[cb][0] + bs[c]));
                    g_kT[bT + (c + 1)*NN + n0 + r0] = __uint_as_float(cvt_tf32(o[cb][1] + bs[c + 1]));
                    g_kT[bT + c*NN + n0 + r1]       = __uint_as_float(cvt_tf32(o[cb][2] + bs[c]));
                    g_kT[bT + (c + 1)*NN + n0 + r1] = __uint_as_float(cvt_tf32(o[cb][3] + bs[c + 1]));
                }
            }
        }
        __syncthreads();
        if (tid == 0) {
            __threadfence();
            atomicAdd(&g_ctr[b], 1);
        }

        // ---- doorbell wait (all 8 producers of this batch) ----
        if (tid == 0) {
            volatile int* c = &g_ctr[b];
            while (*c < 8) {}
            __threadfence();
        }
        __syncthreads();

        // issue K0 (grp1) — hidden behind local q GEMM (disjoint from WT/XP)
#pragma unroll
        for (int j = 0; j < 8; j++) {
            int idx = tid + j*512;
            int d = idx >> 6, f = idx & 63;
            cpa16(kbA + (unsigned)((d*264 + f*4)*4), &g_kT[bT + d*NN + f*4]);
        }
        CP_COMMIT();                          // grp1: K0

        // q (local)
        {
            const unsigned* W = WTu + 2*4608;
            float o[2][4];
#pragma unroll
            for (int cb = 0; cb < 2; cb++) {
                o[cb][0] = 0.f; o[cb][1] = 0.f; o[cb][2] = 0.f; o[cb][3] = 0.f;
            }
#pragma unroll
            for (int ks = 0; ks < 8; ks++) {
                unsigned a0 = XPu[r0*68 + ks*8 + q];
                unsigned a1 = XPu[r1*68 + ks*8 + q];
                unsigned a2 = XPu[r0*68 + ks*8 + q + 4];
                unsigned a3 = XPu[r1*68 + ks*8 + q + 4];
#pragma unroll
                for (int cb = 0; cb < 2; cb++) {
                    int nc = wc*16 + cb*8;
                    unsigned b0 = W[(ks*8 + q)*72 + nc + g];
                    unsigned b1 = W[(ks*8 + q + 4)*72 + nc + g];
                    mma_tf32(o[cb][0], o[cb][1], o[cb][2], o[cb][3],
                             a0, a1, a2, a3, b0, b1);
                }
            }
            __syncthreads();                  // XP/WT reads done
            unsigned* qTu = (unsigned*)(sm + QT_OFF);
#pragma unroll
            for (int cb = 0; cb < 2; cb++) {
                int c = wc*16 + cb*8 + 2*q;
                qTu[c*72 + r0]       = cvt_tf32(o[cb][0] + bq[c]);
                qTu[(c + 1)*72 + r0] = cvt_tf32(o[cb][1] + bq[c + 1]);
                qTu[c*72 + r1]       = cvt_tf32(o[cb][2] + bq[c]);
                qTu[(c + 1)*72 + r1] = cvt_tf32(o[cb][3] + bq[c + 1]);
            }
        }
        // issue Va (grp2), Vb (grp3) — XP dead now
#pragma unroll
        for (int j = 0; j < 4; j++) {
            int idx = tid + j*512;
            int key = idx >> 4, f = idx & 15;
            cpa16(vaA + (unsigned)((key*72 + f*4)*4), &g_v[(base + key)*DD + f*4]);
        }
        CP_COMMIT();                          // grp2: Va
#pragma unroll
        for (int j = 0; j < 4; j++) {
            int idx = tid + j*512;
            int key = idx >> 4, f = idx & 15;
            cpa16(vbA + (unsigned)((key*72 + f*4)*4), &g_v[(base + 128 + key)*DD + f*4]);
        }
        CP_COMMIT();                          // grp3: Vb
    }

    // ================= ATTN PHASE =================
    {
        float* S    = sm + S_OFF;
        float* KB   = sm + KB_OFF;
        float* VAf  = sm + VA_OFF;
        float* VBf  = sm + VB2_OFF;
        float* qTf  = sm + QT_OFF;
        float* rel  = sm + REL_OFF;
        int*   rk   = (int*)(sm + RK_OFF);
        float* wsum = sm + WS_OFF;
        float* invs = sm + INV_OFF;
        float* wsq  = sm + 11264;
        const unsigned* qTb = (const unsigned*)qTf;
        const unsigned* Sb  = (const unsigned*)S;
        const unsigned* KBu = (const unsigned*)KB;
        const unsigned* VAu = (const unsigned*)VAf;
        const unsigned* VBu = (const unsigned*)VBf;

        float rs0 = 0.f, rs1 = 0.f;
        float accpv[2][4];
#pragma unroll
        for (int c = 0; c < 2; c++) {
            accpv[c][0] = 0.f; accpv[c][1] = 0.f; accpv[c][2] = 0.f; accpv[c][3] = 0.f;
        }

        CP_WAIT2(); __syncthreads();                           // K0 ready, qT visible
        const int ri0 = rk[q0 + r0], ri1 = rk[q0 + r1];

        qk_chunk(S, qTb, KBu, rel, rk, 0, wc, q, g, r0, r1, ri0, ri1, rs0, rs1);
        __syncthreads();                                       // S0 ready, KB free

#pragma unroll
        for (int j = 0; j < 8; j++) {
            int idx = tid + j*512;
            int d = idx >> 6, f = idx & 63;
            cpa16(kbA + (unsigned)((d*264 + f*4)*4), &g_kT[bT + d*NN + 256 + f*4]);
        }
        CP_COMMIT();                                          // grp4: K1

        CP_WAIT2(); __syncthreads();                           // Va ready
        pv_half(Sb, VAu, 0, wc, q, g, r0, r1, accpv);
        CP_WAIT1(); __syncthreads();                           // Vb ready, VA free
#pragma unroll
        for (int j = 0; j < 4; j++) {
            int idx = tid + j*512;
            int key = idx >> 4, f = idx & 15;
            cpa16(vaA + (unsigned)((key*72 + f*4)*4), &g_v[(base + 256 + key)*DD + f*4]);
        }
        CP_COMMIT();                                          // grp5: Va2
        pv_half(Sb, VBu, 1, wc, q, g, r0, r1, accpv);
        __syncthreads();                                       // VB free, S free
#pragma unroll
        for (int j = 0; j < 4; j++) {
            int idx = tid + j*512;
            int key = idx >> 4, f = idx & 15;
            cpa16(vbA + (unsigned)((key*72 + f*4)*4), &g_v[(base + 384 + key)*DD + f*4]);
        }
        CP_COMMIT();                                          // grp6: Vb2
        CP_WAIT2(); __syncthreads();                           // K1 ready

        qk_chunk(S, qTb, KBu, rel, rk, 256, wc, q, g, r0, r1, ri0, ri1, rs0, rs1);
        {
            rs0 += __shfl_xor_sync(0xffffffffu, rs0, 1);
            rs0 += __shfl_xor_sync(0xffffffffu, rs0, 2);
            rs1 += __shfl_xor_sync(0xffffffffu, rs1, 1);
            rs1 += __shfl_xor_sync(0xffffffffu, rs1, 2);
            if (q == 0) {
                wsum[wc*64 + r0] = rs0;
                wsum[wc*64 + r1] = rs1;
            }
        }
        __syncthreads();
        if (tid < 64)
            invs[tid] = 1.f / (wsum[tid] + wsum[64 + tid] + wsum[128 + tid] + wsum[192 + tid]);
#pragma unroll
        for (int j = 0; j < 8; j++) {
            int idx = tid + j*512;
            int k = idx >> 5, f = idx & 31;
            cpa16(kbA + (unsigned)((k*132 + f*4)*4), &Wf1[k*128 + f*4]);
        }
        CP_COMMIT();                                          // grp7: w1

        CP_WAIT2(); __syncthreads();                           // Va2 ready (+invs)
        pv_half(Sb, VAu, 0, wc, q, g, r0, r1, accpv);
        CP_WAIT1(); __syncthreads();                           // Vb2 ready
        pv_half(Sb, VBu, 1, wc, q, g, r0, r1, accpv);
        CP_WAIT0();
        __syncthreads();                                       // w1 ready, PV done

        // issue Wf2 -> VA [128][72], ws1/ws2 -> VB (overlap PV epi + FFN1)
#pragma unroll
        for (int j = 0; j < 4; j++) {
            int idx = tid + j*512;
            int k = idx >> 4, f = idx & 15;
            cpa16(vaA + (unsigned)((k*72 + f*4)*4), &Wf2[k*64 + f*4]);
        }
        cpa16(vbA + (unsigned)(tid*16), &Ws1[tid*4]);
        if (tid < 8) cpa16(vbA + (unsigned)((2048 + tid*4)*4), &Ws2[tid*4]);
        CP_COMMIT();                                          // grp8

        // PV epilogue: 1/sum, aoT(tf32) -> qTf
        {
            unsigned* aoT = (unsigned*)qTf;
            float iv0 = invs[r0], iv1 = invs[r1];
#pragma unroll
            for (int cb = 0; cb < 2; cb++) {
                int dc = wc*16 + cb*8 + 2*q;
                aoT[dc*68 + r0]       = cvt_tf32(accpv[cb][0] * iv0);
                aoT[(dc + 1)*68 + r0] = cvt_tf32(accpv[cb][1] * iv0);
                aoT[dc*68 + r1]       = cvt_tf32(accpv[cb][2] * iv1);
                aoT[(dc + 1)*68 + r1] = cvt_tf32(accpv[cb][3] * iv1);
            }
        }
        __syncthreads();

        // FFN1: tf32 mma, M64 N128 K64
        {
            const unsigned* aoT = (const unsigned*)qTf;
            float f1[4][4];
#pragma unroll
            for (int cb = 0; cb < 4; cb++) {
                f1[cb][0] = 0.f; f1[cb][1] = 0.f; f1[cb][2] = 0.f; f1[cb][3] = 0.f;
            }
#pragma unroll
            for (int ks = 0; ks < 8; ks++) {
                unsigned a0 = aoT[(ks*8 + q)*68 + r0];
                unsigned a1 = aoT[(ks*8 + q)*68 + r1];
                unsigned a2 = aoT[(ks*8 + q + 4)*68 + r0];
                unsigned a3 = aoT[(ks*8 + q + 4)*68 + r1];
#pragma unroll
                for (int cb = 0; cb < 4; cb++) {
                    int nc = wc*32 + cb*8;
                    unsigned b0 = cvt_tf32(KB[(ks*8 + q)*132 + nc + g]);
                    unsigned b1 = cvt_tf32(KB[(ks*8 + q + 4)*132 + nc + g]);
                    mma_tf32(f1[cb][0], f1[cb][1], f1[cb][2], f1[cb][3],
                             a0, a1, a2, a3, b0, b1);
                }
            }
            unsigned* h1T = (unsigned*)S;
#pragma unroll
            for (int cb = 0; cb < 4; cb++) {
                int c = wc*32 + cb*8 + 2*q;
                float bc0 = bf1[c], bc1 = bf1[c + 1];
                h1T[c*68 + r0]       = cvt_tf32(fmaxf(f1[cb][0] + bc0, 0.f));
                h1T[(c + 1)*68 + r0] = cvt_tf32(fmaxf(f1[cb][1] + bc1, 0.f));
                h1T[c*68 + r1]       = cvt_tf32(fmaxf(f1[cb][2] + bc0, 0.f));
                h1T[(c + 1)*68 + r1] = cvt_tf32(fmaxf(f1[cb][3] + bc1, 0.f));
            }
        }
        CP_WAIT0();                                            // Wf2 + ws arrived
        __syncthreads();                                       // h1T + VA/VB visible

        // FFN2 + LayerNorm, M64 N64 K128 (B from VA stride 72)
        {
            const unsigned* h1T = (const unsigned*)S;
            float f2[2][4];
            f2[0][0] = f2[0][1] = f2[0][2] = f2[0][3] = 0.f;
            f2[1][0] = f2[1][1] = f2[1][2] = f2[1][3] = 0.f;
#pragma unroll
            for (int ks = 0; ks < 16; ks++) {
                unsigned a0 = h1T[(ks*8 + q)*68 + r0];
                unsigned a1 = h1T[(ks*8 + q)*68 + r1];
                unsigned a2 = h1T[(ks*8 + q + 4)*68 + r0];
                unsigned a3 = h1T[(ks*8 + q + 4)*68 + r1];
#pragma unroll
                for (int cb = 0; cb < 2; cb++) {
                    int nc = wc*16 + cb*8;
                    unsigned b0 = cvt_tf32(VAf[(ks*8 + q)*72 + nc + g]);
                    unsigned b1 = cvt_tf32(VAf[(ks*8 + q + 4)*72 + nc + g]);
                    mma_tf32(f2[cb][0], f2[cb][1], f2[cb][2], f2[cb][3],
                             a0, a1, a2, a3, b0, b1);
                }
            }
            float e[2][4];
            float s0 = 0.f, q0s = 0.f, s1v = 0.f, q1s = 0.f;
#pragma unroll
            for (int cb = 0; cb < 2; cb++) {
                int c = wc*16 + cb*8 + 2*q;
                e[cb][0] = f2[cb][0] + bf2[c];
                e[cb][1] = f2[cb][1] + bf2[c + 1];
                e[cb][2] = f2[cb][2] + bf2[c];
                e[cb][3] = f2[cb][3] + bf2[c + 1];
                s0  += e[cb][0] + e[cb][1];
                q0s += e[cb][0]*e[cb][0] + e[cb][1]*e[cb][1];
                s1v += e[cb][2] + e[cb][3];
                q1s += e[cb][2]*e[cb][2] + e[cb][3]*e[cb][3];
            }
#pragma unroll
            for (int o = 1; o <= 2; o <<= 1) {
                s0  += __shfl_xor_sync(0xffffffffu, s0,  o);
                q0s += __shfl_xor_sync(0xffffffffu, q0s, o);
                s1v += __shfl_xor_sync(0xffffffffu, s1v, o);
                q1s += __shfl_xor_sync(0xffffffffu, q1s, o);
            }
            if (q == 0) {
                wsum[wc*64 + r0] = s0;  wsq[wc*64 + r0] = q0s;
                wsum[wc*64 + r1] = s1v; wsq[wc*64 + r1] = q1s;
            }
            __syncthreads();
            float S0 = wsum[r0] + wsum[64 + r0] + wsum[128 + r0] + wsum[192 + r0];
            float Q0 = wsq[r0]  + wsq[64 + r0]  + wsq[128 + r0]  + wsq[192 + r0];
            float S1 = wsum[r1] + wsum[64 + r1] + wsum[128 + r1] + wsum[192 + r1];
            float Q1 = wsq[r1]  + wsq[64 + r1]  + wsq[128 + r1]  + wsq[192 + r1];
            float mu0 = S0 * (1.f/64.f), mu1 = S1 * (1.f/64.f);
            float in0 = rsqrtf(Q0 * (1.f/64.f) - mu0*mu0 + 1e-5f);
            float in1 = rsqrtf(Q1 * (1.f/64.f) - mu1*mu1 + 1e-5f);
#pragma unroll
            for (int cb = 0; cb < 2; cb++) {
                int c = wc*16 + cb*8 + 2*q;
                float g0v = ln_g[c], g1v = ln_g[c + 1];
                float be0 = ln_b[c], be1 = ln_b[c + 1];
                qTf[c*68 + r0]       = (e[cb][0] - mu0)*in0*g0v + be0;
                qTf[(c + 1)*68 + r0] = (e[cb][1] - mu0)*in0*g1v + be1;
                qTf[c*68 + r1]       = (e[cb][2] - mu1)*in1*g0v + be0;
                qTf[(c + 1)*68 + r1] = (e[cb][3] - mu1)*in1*g1v + be1;
            }
        }
        __syncthreads();

        // head: all 512 threads, 2 rows per 16-lane slot
        {
            const int slot = tid >> 4;
            const int tx4 = tid & 15;
            float s1[2][2];
            s1[0][0] = s1[0][1] = s1[1][0] = s1[1][1] = 0.f;
#pragma unroll 4
            for (int kk = 0; kk < 64; kk++) {
                float2 a = *(const float2*)&qTf[kk*68 + slot*2];
                float w0 = VBf[kk*32 + tx4*2], w1b = VBf[kk*32 + tx4*2 + 1];
                s1[0][0] = fmaf(a.x, w0, s1[0][0]); s1[0][1] = fmaf(a.x, w1b, s1[0][1]);
                s1[1][0] = fmaf(a.y, w0, s1[1][0]); s1[1][1] = fmaf(a.y, w1b, s1[1][1]);
            }
            float w2a = VBf[2048 + tx4*2], w2b = VBf[2048 + tx4*2 + 1];
            float ba = bs1[tx4*2], bb = bs1[tx4*2 + 1];
            float bs2v = bs2[0];
#pragma unroll
            for (int r = 0; r < 2; r++) {
                float pa = fmaxf(s1[r][0] + ba, 0.f);
                float pb = fmaxf(s1[r][1] + bb, 0.f);
                float p = pa*w2a + pb*w2b;
#pragma unroll
                for (int o = 8; o >= 1; o >>= 1) p += __shfl_xor_sync(0xffffffffu, p, o, 16);
                if (tx4 == 0) {
                    float z = p + bs2v;
                    out[base + q0 + slot*2 + r] = 1.f / (1.f + __expf(-z));
                }
            }
        }
    }

    // ---- self-resetting counters for graph replay ----
    __syncthreads();
    if (tid == 0) {
        int d = atomicAdd(&g_done[b], 1);
        if (d == 7) {
            g_ctr[b] = 0;
            g_done[b] = 0;
            __threadfence();
        }
    }
}

// ============================================================
extern "C" void kernel_launch(void* const* d_in, const int* in_sizes, int n_in,
                              void* d_out, int out_size) {
    const float* x     = (const float*)d_in[0];
    const int*   ranks = (const int*)  d_in[1];
    const float* Wp    = (const float*)d_in[2];
    const float* bp    = (const float*)d_in[3];
    const float* Wq    = (const float*)d_in[4];
    const float* bq    = (const float*)d_in[5];
    const float* Wk    = (const float*)d_in[6];
    const float* bk    = (const float*)d_in[7];
    const float* Wv    = (const float*)d_in[8];
    const float* bv    = (const float*)d_in[9];
    const float* Eemb  = (const float*)d_in[10];
    const float* Wr1   = (const float*)d_in[11];
    const float* br1   = (const float*)d_in[12];
    const float* Wr2   = (const float*)d_in[13];
    const float* Wf1   = (const float*)d_in[14];
    const float* bf1   = (const float*)d_in[15];
    const float* Wf2   = (const float*)d_in[16];
    const float* bf2   = (const float*)d_in[17];
    const float* ln_g  = (const float*)d_in[18];
    const float* ln_b  = (const float*)d_in[19];
    const float* Ws1   = (const float*)d_in[20];
    const float* bs1   = (const float*)d_in[21];
    const float* Ws2   = (const float*)d_in[22];
    const float* bs2   = (const float*)d_in[23];
    float* out = (float*)d_out;

    cudaFuncSetAttribute(fused_kernel, cudaFuncAttributeMaxDynamicSharedMemorySize, SMEM_BYTES);

    fused_kernel<<<BB*NN/64, 512, SMEM_BYTES>>>(
        x, ranks, Wp, bp, Wq, bq, Wk, bk, Wv, bv,
        Eemb, Wr1, br1, Wr2, Wf1, bf1, Wf2, bf2,
        ln_g, ln_b, Ws1, bs1, Ws2, bs2, out);
}